// round 9
// baseline (speedup 1.0000x reference)
#include <cuda_runtime.h>
#include <math.h>

#define Bb 2
#define Nn 4096
#define NT (Bb*Nn)
#define Kk 32
#define D0 64
#define E2C 322

typedef unsigned long long ull;

__device__ float PI_g[(size_t)NT * E2C + 384];
__device__ float PJ_g[(size_t)NT * E2C + 384];
__device__ float Wn1T_g[128 * 96];
__device__ float Wn2T_g[64 * 128];
__device__ float WgT_g[32 * 64];

__device__ __forceinline__ float siluf(float x) { return x / (1.f + __expf(-x)); }
__device__ __forceinline__ float sigmf(float x) { return 1.f / (1.f + __expf(-x)); }
__device__ __forceinline__ unsigned bf2(float lo, float hi) {
    unsigned r; asm("cvt.rn.bf16x2.f32 %0, %1, %2;" : "=r"(r) : "f"(hi), "f"(lo)); return r;
}
__device__ __forceinline__ unsigned bfsplat(float x) {
    unsigned r; asm("cvt.rn.bf16x2.f32 %0, %1, %1;" : "=r"(r) : "f"(x)); return r;
}
__device__ __forceinline__ unsigned hfma2(unsigned a, unsigned b, unsigned c) {
    unsigned d; asm("fma.rn.bf16x2 %0, %1, %2, %3;" : "=r"(d) : "r"(a), "r"(b), "r"(c)); return d;
}
__device__ __forceinline__ float blo(unsigned u) { return __uint_as_float(u << 16); }
__device__ __forceinline__ float bhi(unsigned u) { return __uint_as_float(u & 0xffff0000u); }
__device__ __forceinline__ ull pk2(float lo, float hi) {
    ull r; asm("mov.b64 %0, {%1, %2};" : "=l"(r) : "f"(lo), "f"(hi)); return r;
}
__device__ __forceinline__ void up2(ull v, float& lo, float& hi) {
    asm("mov.b64 {%0, %1}, %2;" : "=f"(lo), "=f"(hi) : "l"(v));
}
__device__ __forceinline__ ull ffma2(ull a, ull b, ull c) {
    ull d; asm("fma.rn.f32x2 %0, %1, %2, %3;" : "=l"(d) : "l"(a), "l"(b), "l"(c)); return d;
}

// ---------------- per-node projections: 8 nodes/block, register-reuse GEMM
__global__ void __launch_bounds__(192)
proj_kernel(const float* __restrict__ f0, const float* __restrict__ We1,
            const float* __restrict__ be1)
{
    __shared__ ull ndu[8][64];
    const int nb = blockIdx.x * 8;
    const int tid = threadIdx.x;
    for (int idx = tid; idx < 512; idx += 192) {
        const float v = f0[(size_t)nb * 64 + idx];
        ndu[idx >> 6][idx & 63] = pk2(v, v);
    }
    __syncthreads();
    const int p = tid;
    if (p < 161) {
        ull si[8], sj[8];
        #pragma unroll
        for (int n = 0; n < 8; n++) { si[n] = 0ull; sj[n] = 0ull; }
        for (int d = 0; d < 64; d++) {
            const float2 wi = __ldg((const float2*)&We1[(size_t)d * E2C + 2 * p]);
            const float2 wj = __ldg((const float2*)&We1[(size_t)(64 + d) * E2C + 2 * p]);
            const ull wiu = pk2(wi.x, wi.y);
            const ull wju = pk2(wj.x, wj.y);
            #pragma unroll
            for (int n = 0; n < 8; n++) {
                const ull v = ndu[n][d];
                si[n] = ffma2(v, wiu, si[n]);
                sj[n] = ffma2(v, wju, sj[n]);
            }
        }
        const float2 b = *(const float2*)&be1[2 * p];
        #pragma unroll
        for (int n = 0; n < 8; n++) {
            float a0, a1, c0, c1;
            up2(si[n], a0, a1); up2(sj[n], c0, c1);
            *(float2*)&PI_g[(size_t)(nb + n) * E2C + 2 * p] = make_float2(a0 + b.x, a1 + b.y);
            *(float2*)&PJ_g[(size_t)(nb + n) * E2C + 2 * p] = make_float2(c0, c1);
        }
    }
}

// ---------------- transpose small tail weights
__global__ void __launch_bounds__(256)
prep_kernel(const float* __restrict__ Wn1, const float* __restrict__ Wn2,
            const float* __restrict__ Wg)
{
    const int idx = blockIdx.x * 256 + threadIdx.x;
    if (idx < 128 * 96) {
        const int col = idx / 96, k = idx - col * 96;
        Wn1T_g[idx] = Wn1[k * 128 + col];
    } else if (idx < 128 * 96 + 64 * 128) {
        const int j = idx - 128 * 96;
        const int col = j / 128, k = j - col * 128;
        Wn2T_g[j] = Wn2[k * 64 + col];
    } else if (idx < 128 * 96 + 64 * 128 + 32 * 64) {
        const int j = idx - 128 * 96 - 64 * 128;
        const int col = j / 64, k = j - col * 64;
        WgT_g[j] = Wg[k * 32 + col];
    }
}

// ---------------- main fused kernel
__global__ void __launch_bounds__(256, 4)
egnn_main(const float* __restrict__ f0, const float* __restrict__ f1,
          const int* __restrict__ nbr, const unsigned char* __restrict__ msk,
          const float* __restrict__ rdist,
          const float* __restrict__ We1,
          const float* __restrict__ We2, const float* __restrict__ be2,
          const float* __restrict__ Wh1, const float* __restrict__ bh1,
          const float* __restrict__ Wh2, const float* __restrict__ bh2,
          const float* __restrict__ bn1, const float* __restrict__ bn2,
          const float* __restrict__ bg,
          const float* __restrict__ lng, const float* __restrict__ lnb,
          const float* __restrict__ hns, const float* __restrict__ hnb,
          float* __restrict__ out)
{
    extern __shared__ float sm[];
    unsigned* A    = (unsigned*)sm;            // 2688 u32
    unsigned* H1u  = A + 2688;                 // [32 e][164] u32; aliased by G1u
    float*    EIcT = (float*)(H1u + 5248);     // [32 d][36]
    unsigned* EIbT = (unsigned*)(EIcT + 1152); // [33 k][36]
    float*    PI   = (float*)(EIbT + 1188);    // [324]
    unsigned* MSbT = (unsigned*)(PI + 324);    // [32 r][36]
    float*    WST  = (float*)(MSbT + 1152);    // [32 d][36]
    float*    HT2  = WST + 1152;               // [192]
    float*    nodes_s = HT2 + 192;             // [64]
    float*    f1i_s   = nodes_s + 64;          // [96]
    float*    MI   = f1i_s + 96;               // [32]
    float*    NI   = MI + 32;                  // [96]
    float*    N1s  = NI + 96;                  // [128]
    float*    nouts= N1s + 128;                // [64]
    float*    gates= nouts + 64;               // [32]
    float*    maskv= gates + 32;               // [32]
    float*    stats= maskv + 32;               // [2]
    int*      nbr_s= (int*)(stats + 2);        // [32]
    float*    Ppart= (float*)(nbr_s + 32);     // [256]
    unsigned* G1u  = H1u;

    const int tid  = threadIdx.x;
    const int lane = tid & 31;
    const int wrow = tid >> 5;
    const int node = blockIdx.x;
    const int bbase = (node / Nn) * Nn;

    // ---- P0 ----
    if (tid < 64)           nodes_s[tid]    = f0[(size_t)node * 64 + tid];
    else if (tid < 160)     f1i_s[tid - 64] = f1[(size_t)node * 96 + (tid - 64)];
    if (tid < 32)           nbr_s[tid] = nbr[node * Kk + tid];
    else if (tid < 64)      maskv[tid - 32] = (float)msk[node * Kk + tid - 32];
    else if (tid < 96)      EIbT[32 * 36 + (tid - 64)] = bfsplat(rdist[node * Kk + tid - 64]);
    for (int c = tid; c < 324; c += 256)
        PI[c] = (c < E2C) ? PI_g[(size_t)node * E2C + c] : 0.f;
    for (int idx = tid; idx < 11 * 192; idx += 256) {
        const int kr = idx / 192, p = idx - kr * 192;
        unsigned v = 0u;
        if (p < 161) {
            const float2 w = __ldg((const float2*)&We1[(size_t)(128 + kr) * E2C + 2 * p]);
            v = bf2(w.x, w.y);
        }
        A[kr * 192 + 6 * (p & 31) + (p >> 5)] = v;   // thread-major pair layout
    }
    __syncthreads();

    // ---- P1: rel_norm gather + LN stats ----
    #pragma unroll
    for (int i = 0; i < 4; i++) {
        const int e = wrow + 8 * i;
        const float* f1j = f1 + (size_t)(bbase + nbr_s[e]) * 96;
        const float r0 = f1i_s[lane * 3 + 0] - f1j[lane * 3 + 0];
        const float r1 = f1i_s[lane * 3 + 1] - f1j[lane * 3 + 1];
        const float r2 = f1i_s[lane * 3 + 2] - f1j[lane * 3 + 2];
        const float nrm = sqrtf(r0 * r0 + r1 * r1 + r2 * r2);
        EIcT[lane * 36 + e] = nrm;
        EIbT[lane * 36 + e] = bfsplat(nrm);
    }
    if (wrow == 7) {
        float x0 = nodes_s[lane], x1 = nodes_s[lane + 32];
        float s = x0 + x1, ss = x0 * x0 + x1 * x1;
        #pragma unroll
        for (int o = 16; o > 0; o >>= 1) {
            s  += __shfl_down_sync(0xffffffffu, s,  o);
            ss += __shfl_down_sync(0xffffffffu, ss, o);
        }
        if (lane == 0) {
            const float mu  = s * (1.f / 64.f);
            const float var = ss * (1.f / 64.f) - mu * mu;
            stats[0] = mu;
            stats[1] = rsqrtf(var + 1e-5f);
        }
    }
    __syncthreads();

    // ---- GEMM1 (K=33, 3 staged chunks; LDS.64 weight pairs) ----
    unsigned acc2[4][6];
    #pragma unroll
    for (int i = 0; i < 4; i++)
        #pragma unroll
        for (int jj = 0; jj < 6; jj++) acc2[i][jj] = 0u;

    #pragma unroll
    for (int s = 0; s < 3; s++) {
        for (int kr = 0; kr < 11; kr++) {
            const int k = 11 * s + kr;
            const uint4 ev4 = *(const uint4*)&EIbT[k * 36 + 4 * wrow];
            const uint2 w01 = *(const uint2*)&A[kr * 192 + 6 * lane];
            const uint2 w23 = *(const uint2*)&A[kr * 192 + 6 * lane + 2];
            const uint2 w45 = *(const uint2*)&A[kr * 192 + 6 * lane + 4];
            acc2[0][0] = hfma2(ev4.x, w01.x, acc2[0][0]); acc2[0][1] = hfma2(ev4.x, w01.y, acc2[0][1]);
            acc2[0][2] = hfma2(ev4.x, w23.x, acc2[0][2]); acc2[0][3] = hfma2(ev4.x, w23.y, acc2[0][3]);
            acc2[0][4] = hfma2(ev4.x, w45.x, acc2[0][4]); acc2[0][5] = hfma2(ev4.x, w45.y, acc2[0][5]);
            acc2[1][0] = hfma2(ev4.y, w01.x, acc2[1][0]); acc2[1][1] = hfma2(ev4.y, w01.y, acc2[1][1]);
            acc2[1][2] = hfma2(ev4.y, w23.x, acc2[1][2]); acc2[1][3] = hfma2(ev4.y, w23.y, acc2[1][3]);
            acc2[1][4] = hfma2(ev4.y, w45.x, acc2[1][4]); acc2[1][5] = hfma2(ev4.y, w45.y, acc2[1][5]);
            acc2[2][0] = hfma2(ev4.z, w01.x, acc2[2][0]); acc2[2][1] = hfma2(ev4.z, w01.y, acc2[2][1]);
            acc2[2][2] = hfma2(ev4.z, w23.x, acc2[2][2]); acc2[2][3] = hfma2(ev4.z, w23.y, acc2[2][3]);
            acc2[2][4] = hfma2(ev4.z, w45.x, acc2[2][4]); acc2[2][5] = hfma2(ev4.z, w45.y, acc2[2][5]);
            acc2[3][0] = hfma2(ev4.w, w01.x, acc2[3][0]); acc2[3][1] = hfma2(ev4.w, w01.y, acc2[3][1]);
            acc2[3][2] = hfma2(ev4.w, w23.x, acc2[3][2]); acc2[3][3] = hfma2(ev4.w, w23.y, acc2[3][3]);
            acc2[3][4] = hfma2(ev4.w, w45.x, acc2[3][4]); acc2[3][5] = hfma2(ev4.w, w45.y, acc2[3][5]);
        }
        __syncthreads();
        if (s < 2) {
            for (int idx = tid; idx < 11 * 192; idx += 256) {
                const int kr = idx / 192, p = idx - kr * 192;
                unsigned v = 0u;
                if (p < 161) {
                    const float2 w = __ldg((const float2*)&We1[(size_t)(128 + 11 * (s + 1) + kr) * E2C + 2 * p]);
                    v = bf2(w.x, w.y);
                }
                A[kr * 192 + 6 * (p & 31) + (p >> 5)] = v;
            }
            __syncthreads();
        }
    }

    // ---- epilogue: H1 = bf16(silu(acc + PI + PJ)), overlap We2 chunk-0 staging ----
    #pragma unroll
    for (int i = 0; i < 4; i++) {
        const int e = 4 * wrow + i;
        const float* pj = PJ_g + (size_t)(bbase + nbr_s[e]) * E2C;
        #pragma unroll
        for (int jj = 0; jj < 6; jj++) {
            const int p = lane + 32 * jj;
            if (p < 161) {
                const float2 pi2 = *(const float2*)&PI[2 * p];
                const float2 pj2 = __ldg((const float2*)(pj + 2 * p));
                const float h0 = siluf(blo(acc2[i][jj]) + pi2.x + pj2.x);
                const float h1 = siluf(bhi(acc2[i][jj]) + pi2.y + pj2.y);
                H1u[e * 164 + p] = bf2(h0, h1);
            }
        }
    }
    if (tid < 96) H1u[(tid / 3) * 164 + 161 + (tid % 3)] = 0u;
    for (int idx = tid; idx < 21 * 32; idx += 256) {
        const int c8 = idx >> 5, r = idx & 31;
        const int m = r >> 3, q = r & 7;
        const int k = 8 * c8 + 2 * m;
        const float4 w0 = __ldg((const float4*)&We2[k * 32 + 4 * q]);
        const float4 w1 = __ldg((const float4*)&We2[(k + 1) * 32 + 4 * q]);
        A[c8 * 128 + (4 * q + 0) * 4 + m] = bf2(w0.x, w1.x);
        A[c8 * 128 + (4 * q + 1) * 4 + m] = bf2(w0.y, w1.y);
        A[c8 * 128 + (4 * q + 2) * 4 + m] = bf2(w0.z, w1.z);
        A[c8 * 128 + (4 * q + 3) * 4 + m] = bf2(w0.w, w1.w);
    }
    __syncthreads();

    // ---- GEMM2 (2 edges x 2 cols per thread; h broadcast across 16 lanes) ----
    {
        const int ep = tid >> 4;      // edge pair 0..15
        const int cp = tid & 15;      // col pair 0..15
        unsigned a2[2][2] = {{0u, 0u}, {0u, 0u}};
        const uint4* A4 = (const uint4*)A;
        const uint4* H4 = (const uint4*)H1u;   // row stride 41
        for (int c = 0; c < 21; c++) {
            const uint4 w0 = A4[c * 32 + 2 * cp];
            const uint4 w1 = A4[c * 32 + 2 * cp + 1];
            #pragma unroll
            for (int i = 0; i < 2; i++) {
                const uint4 h = H4[(2 * ep + i) * 41 + c];
                a2[i][0] = hfma2(h.x, w0.x, a2[i][0]); a2[i][1] = hfma2(h.x, w1.x, a2[i][1]);
                a2[i][0] = hfma2(h.y, w0.y, a2[i][0]); a2[i][1] = hfma2(h.y, w1.y, a2[i][1]);
                a2[i][0] = hfma2(h.z, w0.z, a2[i][0]); a2[i][1] = hfma2(h.z, w1.z, a2[i][1]);
                a2[i][0] = hfma2(h.w, w0.w, a2[i][0]); a2[i][1] = hfma2(h.w, w1.w, a2[i][1]);
            }
        }
        __syncthreads();
        for (int idx = tid; idx < 20 * 32; idx += 256) {
            const int c8 = idx >> 5, r = idx & 31;
            const int m = r >> 3, q = r & 7;
            const int k = 8 * (21 + c8) + 2 * m;
            float4 w0 = make_float4(0.f, 0.f, 0.f, 0.f), w1 = w0;
            if (k     < E2C) w0 = __ldg((const float4*)&We2[k * 32 + 4 * q]);
            if (k + 1 < E2C) w1 = __ldg((const float4*)&We2[(k + 1) * 32 + 4 * q]);
            A[c8 * 128 + (4 * q + 0) * 4 + m] = bf2(w0.x, w1.x);
            A[c8 * 128 + (4 * q + 1) * 4 + m] = bf2(w0.y, w1.y);
            A[c8 * 128 + (4 * q + 2) * 4 + m] = bf2(w0.z, w1.z);
            A[c8 * 128 + (4 * q + 3) * 4 + m] = bf2(w0.w, w1.w);
        }
        __syncthreads();
        for (int c = 0; c < 20; c++) {
            const uint4 w0 = A4[c * 32 + 2 * cp];
            const uint4 w1 = A4[c * 32 + 2 * cp + 1];
            #pragma unroll
            for (int i = 0; i < 2; i++) {
                const uint4 h = H4[(2 * ep + i) * 41 + 21 + c];
                a2[i][0] = hfma2(h.x, w0.x, a2[i][0]); a2[i][1] = hfma2(h.x, w1.x, a2[i][1]);
                a2[i][0] = hfma2(h.y, w0.y, a2[i][0]); a2[i][1] = hfma2(h.y, w1.y, a2[i][1]);
                a2[i][0] = hfma2(h.z, w0.z, a2[i][0]); a2[i][1] = hfma2(h.z, w1.z, a2[i][1]);
                a2[i][0] = hfma2(h.w, w0.w, a2[i][0]); a2[i][1] = hfma2(h.w, w1.w, a2[i][1]);
            }
        }
        #pragma unroll
        for (int i = 0; i < 2; i++)
            #pragma unroll
            for (int j = 0; j < 2; j++) {
                const int col = 2 * cp + j, e = 2 * ep + i;
                const float m = siluf(blo(a2[i][j]) + bhi(a2[i][j]) + be2[col]);
                MSbT[col * 36 + e] = bfsplat(m);
            }
    }
    __syncthreads();

    // ---- stage Wh1 (warps 0-6) + MI (warp 7) ----
    if (wrow < 7) {
        for (int idx = tid; idx < 1024; idx += 224) {
            const float4 w = __ldg((const float4*)&Wh1[(idx >> 5) * 128 + 4 * (idx & 31)]);
            A[2 * idx]     = bf2(w.x, w.y);
            A[2 * idx + 1] = bf2(w.z, w.w);
        }
    } else {
        float s = 0.f;
        #pragma unroll 8
        for (int e = 0; e < 32; e++)
            s += maskv[e] * blo(MSbT[lane * 36 + e]);
        MI[lane] = s;
    }
    __syncthreads();

    // ---- GEMM3: G1 = silu(MS @ Wh1 + bh1) ----
    unsigned a3[4][2];
    #pragma unroll
    for (int i = 0; i < 4; i++) { a3[i][0] = 0u; a3[i][1] = 0u; }
    #pragma unroll 4
    for (int r = 0; r < 32; r++) {
        const uint4 mv4 = *(const uint4*)&MSbT[r * 36 + 4 * wrow];
        const uint2 w = *(const uint2*)&A[r * 64 + lane * 2];
        a3[0][0] = hfma2(mv4.x, w.x, a3[0][0]); a3[0][1] = hfma2(mv4.x, w.y, a3[0][1]);
        a3[1][0] = hfma2(mv4.y, w.x, a3[1][0]); a3[1][1] = hfma2(mv4.y, w.y, a3[1][1]);
        a3[2][0] = hfma2(mv4.z, w.x, a3[2][0]); a3[2][1] = hfma2(mv4.z, w.y, a3[2][1]);
        a3[3][0] = hfma2(mv4.w, w.x, a3[3][0]); a3[3][1] = hfma2(mv4.w, w.y, a3[3][1]);
    }
    __syncthreads();

    // ---- G1 write + stage Wh2 ----
    #pragma unroll
    for (int i = 0; i < 4; i++) {
        const int e = 4 * wrow + i;
        #pragma unroll
        for (int jj = 0; jj < 2; jj++) {
            const int c0 = 4 * lane + 2 * jj;
            const float g0 = siluf(blo(a3[i][jj]) + bh1[c0]);
            const float g1 = siluf(bhi(a3[i][jj]) + bh1[c0 + 1]);
            G1u[e * 68 + lane * 2 + jj] = bf2(g0, g1);
        }
    }
    for (int idx = tid; idx < 512; idx += 256) {
        const int c8 = idx >> 5, r = idx & 31;
        const int m = r >> 3, q = r & 7;
        const int k = 8 * c8 + 2 * m;
        const float4 w0 = __ldg((const float4*)&Wh2[k * 32 + 4 * q]);
        const float4 w1 = __ldg((const float4*)&Wh2[(k + 1) * 32 + 4 * q]);
        A[c8 * 128 + (4 * q + 0) * 4 + m] = bf2(w0.x, w1.x);
        A[c8 * 128 + (4 * q + 1) * 4 + m] = bf2(w0.y, w1.y);
        A[c8 * 128 + (4 * q + 2) * 4 + m] = bf2(w0.z, w1.z);
        A[c8 * 128 + (4 * q + 3) * 4 + m] = bf2(w0.w, w1.w);
    }
    __syncthreads();

    // ---- GEMM4 (2 edges x 2 cols) ----
    {
        const int ep = tid >> 4;
        const int cp = tid & 15;
        unsigned a4[2][2] = {{0u, 0u}, {0u, 0u}};
        const uint4* A4 = (const uint4*)A;
        const uint4* G4 = (const uint4*)G1u;   // row stride 17
        for (int c = 0; c < 16; c++) {
            const uint4 w0 = A4[c * 32 + 2 * cp];
            const uint4 w1 = A4[c * 32 + 2 * cp + 1];
            #pragma unroll
            for (int i = 0; i < 2; i++) {
                const uint4 g = G4[(2 * ep + i) * 17 + c];
                a4[i][0] = hfma2(g.x, w0.x, a4[i][0]); a4[i][1] = hfma2(g.x, w1.x, a4[i][1]);
                a4[i][0] = hfma2(g.y, w0.y, a4[i][0]); a4[i][1] = hfma2(g.y, w1.y, a4[i][1]);
                a4[i][0] = hfma2(g.z, w0.z, a4[i][0]); a4[i][1] = hfma2(g.z, w1.z, a4[i][1]);
                a4[i][0] = hfma2(g.w, w0.w, a4[i][0]); a4[i][1] = hfma2(g.w, w1.w, a4[i][1]);
            }
        }
        #pragma unroll
        for (int i = 0; i < 2; i++)
            #pragma unroll
            for (int j = 0; j < 2; j++) {
                const int col = 2 * cp + j, e = 2 * ep + i;
                WST[col * 36 + e] = blo(a4[i][j]) + bhi(a4[i][j]) + bh2[col];
            }
    }
    __syncthreads();

    // ---- htype (warps 0-5) + NI prep (warps 6-7) ----
    if (tid < 192) {
        const int half = (tid >= 96);
        const int t = tid - 96 * half;
        const int d = t / 3;
        const float hs = hns[d], hb = hnb[d];
        const float fi = f1i_s[t];
        const int e0 = half * 16;
        float s = 0.f;
        #pragma unroll
        for (int e4 = 0; e4 < 4; e4++) {
            const float4 nrm4 = *(const float4*)&EIcT[d * 36 + e0 + 4 * e4];
            const float4 w4   = *(const float4*)&WST[d * 36 + e0 + 4 * e4];
            #pragma unroll
            for (int m = 0; m < 4; m++) {
                const int e = e0 + 4 * e4 + m;
                const float nrm = (m == 0) ? nrm4.x : (m == 1) ? nrm4.y : (m == 2) ? nrm4.z : nrm4.w;
                const float wv  = (m == 0) ? w4.x   : (m == 1) ? w4.y   : (m == 2) ? w4.z   : w4.w;
                const float coef = __fdividef(nrm * hs + hb, fmaxf(nrm, 1e-8f));
                const float relv = fi - __ldg(&f1[(size_t)(bbase + nbr_s[e]) * 96 + t]);
                s += relv * coef * wv;
            }
        }
        HT2[tid] = s;
    } else if (tid < 256) {
        const int c = tid - 192;
        NI[c] = (nodes_s[c] - stats[0]) * stats[1] * lng[c] + lnb[c];
        if (c < 32) NI[64 + c] = MI[c];
    }
    __syncthreads();

    // ---- N1: 256 threads, 2-way K-split, transposed weights ----
    {
        const int col = tid & 127, half = tid >> 7, k0 = half * 48;
        const float* w = &Wn1T_g[col * 96 + k0];
        ull s2 = 0ull;
        #pragma unroll
        for (int q = 0; q < 12; q++) {
            const float4 wv = __ldg((const float4*)&w[4 * q]);
            const float4 nv = *(const float4*)&NI[k0 + 4 * q];
            s2 = ffma2(pk2(nv.x, nv.y), pk2(wv.x, wv.y), s2);
            s2 = ffma2(pk2(nv.z, nv.w), pk2(wv.z, wv.w), s2);
        }
        float lo, hi; up2(s2, lo, hi);
        Ppart[tid] = lo + hi;
    }
    __syncthreads();
    if (tid < 128) N1s[tid] = siluf(Ppart[tid] + Ppart[tid + 128] + bn1[tid]);
    __syncthreads();

    // ---- node_out: 256 threads, 4-way K-split ----
    {
        const int col = tid & 63, q4 = tid >> 6, k0 = 32 * q4;
        const float* w = &Wn2T_g[col * 128 + k0];
        ull s2 = 0ull;
        #pragma unroll
        for (int q = 0; q < 8; q++) {
            const float4 wv = __ldg((const float4*)&w[4 * q]);
            const float4 nv = *(const float4*)&N1s[k0 + 4 * q];
            s2 = ffma2(pk2(nv.x, nv.y), pk2(wv.x, wv.y), s2);
            s2 = ffma2(pk2(nv.z, nv.w), pk2(wv.z, wv.w), s2);
        }
        float lo, hi; up2(s2, lo, hi);
        Ppart[tid] = lo + hi;
    }
    __syncthreads();
    if (tid < 64) {
        const float v = Ppart[tid] + Ppart[tid + 64] + Ppart[tid + 128] + Ppart[tid + 192]
                      + bn2[tid] + nodes_s[tid];
        nouts[tid] = v;
        out[(size_t)node * 64 + tid] = v;
    }
    __syncthreads();

    // ---- gate: 128 threads, 4-way K-split ----
    if (tid < 128) {
        const int col = tid & 31, q4 = tid >> 5, k0 = 16 * q4;
        const float* w = &WgT_g[col * 64 + k0];
        ull s2 = 0ull;
        #pragma unroll
        for (int q = 0; q < 4; q++) {
            const float4 wv = __ldg((const float4*)&w[4 * q]);
            const float4 nv = *(const float4*)&nouts[k0 + 4 * q];
            s2 = ffma2(pk2(nv.x, nv.y), pk2(wv.x, wv.y), s2);
            s2 = ffma2(pk2(nv.z, nv.w), pk2(wv.z, wv.w), s2);
        }
        float lo, hi; up2(s2, lo, hi);
        Ppart[tid] = lo + hi;
    }
    __syncthreads();
    if (tid < 32)
        gates[tid] = sigmf(Ppart[tid] + Ppart[tid + 32] + Ppart[tid + 64] + Ppart[tid + 96] + bg[tid]);
    __syncthreads();

    // ---- f1_out ----
    if (tid < 96) {
        const int d = tid / 3;
        const float v = (f1i_s[tid] + HT2[tid] + HT2[96 + tid]) * gates[d];
        out[(size_t)Bb * Nn * D0 + (size_t)node * 96 + tid] = v;
    }
}

extern "C" void kernel_launch(void* const* d_in, const int* in_sizes, int n_in,
                              void* d_out, int out_size) {
    const float* f0   = (const float*)d_in[0];
    const float* f1   = (const float*)d_in[1];
    const int*   nbr  = (const int*)d_in[2];
    const unsigned char* msk = (const unsigned char*)d_in[3];
    const float* rdist= (const float*)d_in[4];
    const float* We1  = (const float*)d_in[5];
    const float* be1  = (const float*)d_in[6];
    const float* We2  = (const float*)d_in[7];
    const float* be2  = (const float*)d_in[8];
    const float* Wh1  = (const float*)d_in[9];
    const float* bh1  = (const float*)d_in[10];
    const float* Wh2  = (const float*)d_in[11];
    const float* bh2  = (const float*)d_in[12];
    const float* Wn1  = (const float*)d_in[13];
    const float* bn1  = (const float*)d_in[14];
    const float* Wn2  = (const float*)d_in[15];
    const float* bn2  = (const float*)d_in[16];
    const float* Wg   = (const float*)d_in[17];
    const float* bg   = (const float*)d_in[18];
    const float* lng  = (const float*)d_in[19];
    const float* lnb  = (const float*)d_in[20];
    const float* hns  = (const float*)d_in[21];
    const float* hnb  = (const float*)d_in[22];
    float* out = (float*)d_out;

    proj_kernel<<<NT / 8, 192>>>(f0, We1, be1);
    prep_kernel<<<88, 256>>>(Wn1, Wn2, Wg);

    const size_t smem_bytes = 13930 * 4;

    cudaFuncSetAttribute(egnn_main, cudaFuncAttributeMaxDynamicSharedMemorySize,
                         (int)smem_bytes);

    egnn_main<<<NT, 256, smem_bytes>>>(
        f0, f1, nbr, msk, rdist, We1,
        We2, be2, Wh1, bh1, Wh2, bh2,
        bn1, bn2, bg, lng, lnb, hns, hnb, out);
}

// round 10
// speedup vs baseline: 1.1121x; 1.1121x over previous
#include <cuda_runtime.h>
#include <math.h>

#define Bb 2
#define Nn 4096
#define NT (Bb*Nn)
#define Kk 32
#define D0 64
#define E2C 322

typedef unsigned long long ull;

__device__ float PI_g[(size_t)NT * E2C + 384];
__device__ float PJ_g[(size_t)NT * E2C + 384];
__device__ float Wn1T_g[128 * 96];
__device__ float Wn2T_g[64 * 128];
__device__ float WgT_g[32 * 64];

__device__ __forceinline__ float siluf(float x) { return x / (1.f + __expf(-x)); }
__device__ __forceinline__ float sigmf(float x) { return 1.f / (1.f + __expf(-x)); }
__device__ __forceinline__ unsigned bf2(float lo, float hi) {
    unsigned r; asm("cvt.rn.bf16x2.f32 %0, %1, %2;" : "=r"(r) : "f"(hi), "f"(lo)); return r;
}
__device__ __forceinline__ unsigned bfsplat(float x) {
    unsigned r; asm("cvt.rn.bf16x2.f32 %0, %1, %1;" : "=r"(r) : "f"(x)); return r;
}
__device__ __forceinline__ unsigned hfma2(unsigned a, unsigned b, unsigned c) {
    unsigned d; asm("fma.rn.bf16x2 %0, %1, %2, %3;" : "=r"(d) : "r"(a), "r"(b), "r"(c)); return d;
}
__device__ __forceinline__ float blo(unsigned u) { return __uint_as_float(u << 16); }
__device__ __forceinline__ float bhi(unsigned u) { return __uint_as_float(u & 0xffff0000u); }
__device__ __forceinline__ ull pk2(float lo, float hi) {
    ull r; asm("mov.b64 %0, {%1, %2};" : "=l"(r) : "f"(lo), "f"(hi)); return r;
}
__device__ __forceinline__ void up2(ull v, float& lo, float& hi) {
    asm("mov.b64 {%0, %1}, %2;" : "=f"(lo), "=f"(hi) : "l"(v));
}
__device__ __forceinline__ ull ffma2(ull a, ull b, ull c) {
    ull d; asm("fma.rn.f32x2 %0, %1, %2, %3;" : "=l"(d) : "l"(a), "l"(b), "l"(c)); return d;
}

// ---------------- per-node projections: 8 nodes/block, register-reuse GEMM
__global__ void __launch_bounds__(192)
proj_kernel(const float* __restrict__ f0, const float* __restrict__ We1,
            const float* __restrict__ be1)
{
    __shared__ ull ndu[8][64];
    const int nb = blockIdx.x * 8;
    const int tid = threadIdx.x;
    for (int idx = tid; idx < 512; idx += 192) {
        const float v = f0[(size_t)nb * 64 + idx];
        ndu[idx >> 6][idx & 63] = pk2(v, v);
    }
    __syncthreads();
    const int p = tid;
    if (p < 161) {
        ull si[8], sj[8];
        #pragma unroll
        for (int n = 0; n < 8; n++) { si[n] = 0ull; sj[n] = 0ull; }
        for (int d = 0; d < 64; d++) {
            const float2 wi = __ldg((const float2*)&We1[(size_t)d * E2C + 2 * p]);
            const float2 wj = __ldg((const float2*)&We1[(size_t)(64 + d) * E2C + 2 * p]);
            const ull wiu = pk2(wi.x, wi.y);
            const ull wju = pk2(wj.x, wj.y);
            #pragma unroll
            for (int n = 0; n < 8; n++) {
                const ull v = ndu[n][d];
                si[n] = ffma2(v, wiu, si[n]);
                sj[n] = ffma2(v, wju, sj[n]);
            }
        }
        const float2 b = *(const float2*)&be1[2 * p];
        #pragma unroll
        for (int n = 0; n < 8; n++) {
            float a0, a1, c0, c1;
            up2(si[n], a0, a1); up2(sj[n], c0, c1);
            *(float2*)&PI_g[(size_t)(nb + n) * E2C + 2 * p] = make_float2(a0 + b.x, a1 + b.y);
            *(float2*)&PJ_g[(size_t)(nb + n) * E2C + 2 * p] = make_float2(c0, c1);
        }
    }
}

// ---------------- transpose small tail weights
__global__ void __launch_bounds__(256)
prep_kernel(const float* __restrict__ Wn1, const float* __restrict__ Wn2,
            const float* __restrict__ Wg)
{
    const int idx = blockIdx.x * 256 + threadIdx.x;
    if (idx < 128 * 96) {
        const int col = idx / 96, k = idx - col * 96;
        Wn1T_g[idx] = Wn1[k * 128 + col];
    } else if (idx < 128 * 96 + 64 * 128) {
        const int j = idx - 128 * 96;
        const int col = j / 128, k = j - col * 128;
        Wn2T_g[j] = Wn2[k * 64 + col];
    } else if (idx < 128 * 96 + 64 * 128 + 32 * 64) {
        const int j = idx - 128 * 96 - 64 * 128;
        const int col = j / 64, k = j - col * 64;
        WgT_g[j] = Wg[k * 32 + col];
    }
}

// ---------------- main fused kernel (R8 GEMM layouts + K-split tail)
__global__ void __launch_bounds__(256, 4)
egnn_main(const float* __restrict__ f0, const float* __restrict__ f1,
          const int* __restrict__ nbr, const unsigned char* __restrict__ msk,
          const float* __restrict__ rdist,
          const float* __restrict__ We1,
          const float* __restrict__ We2, const float* __restrict__ be2,
          const float* __restrict__ Wh1, const float* __restrict__ bh1,
          const float* __restrict__ Wh2, const float* __restrict__ bh2,
          const float* __restrict__ bn1, const float* __restrict__ bn2,
          const float* __restrict__ bg,
          const float* __restrict__ lng, const float* __restrict__ lnb,
          const float* __restrict__ hns, const float* __restrict__ hnb,
          float* __restrict__ out)
{
    extern __shared__ float sm[];
    unsigned* A    = (unsigned*)sm;            // 2688 u32
    unsigned* H1u  = A + 2688;                 // [32 e][164] u32; aliased by G1u
    float*    EIcT = (float*)(H1u + 5248);     // [32 d][36]
    unsigned* EIbT = (unsigned*)(EIcT + 1152); // [33 k][36]
    float*    PI   = (float*)(EIbT + 1188);    // [324]
    unsigned* MSbT = (unsigned*)(PI + 324);    // [32 r][36]
    float*    WST  = (float*)(MSbT + 1152);    // [32 d][36]
    float*    HT2  = WST + 1152;               // [192]
    float*    nodes_s = HT2 + 192;             // [64]
    float*    f1i_s   = nodes_s + 64;          // [96]
    float*    MI   = f1i_s + 96;               // [32]
    float*    NI   = MI + 32;                  // [96]
    float*    N1s  = NI + 96;                  // [128]
    float*    nouts= N1s + 128;                // [64]
    float*    gates= nouts + 64;               // [32]
    float*    maskv= gates + 32;               // [32]
    float*    stats= maskv + 32;               // [2]
    int*      nbr_s= (int*)(stats + 2);        // [32]
    float*    Ppart= (float*)(nbr_s + 32);     // [256]
    unsigned* G1u  = H1u;

    const int tid  = threadIdx.x;
    const int lane = tid & 31;
    const int wrow = tid >> 5;
    const int node = blockIdx.x;
    const int bbase = (node / Nn) * Nn;

    // ---- P0 ----
    if (tid < 64)           nodes_s[tid]    = f0[(size_t)node * 64 + tid];
    else if (tid < 160)     f1i_s[tid - 64] = f1[(size_t)node * 96 + (tid - 64)];
    if (tid < 32)           nbr_s[tid] = nbr[node * Kk + tid];
    else if (tid < 64)      maskv[tid - 32] = (float)msk[node * Kk + tid - 32];
    else if (tid < 96)      EIbT[32 * 36 + (tid - 64)] = bfsplat(rdist[node * Kk + tid - 64]);
    for (int c = tid; c < 324; c += 256)
        PI[c] = (c < E2C) ? PI_g[(size_t)node * E2C + c] : 0.f;
    for (int idx = tid; idx < 11 * 192; idx += 256) {
        const int kr = idx / 192, p = idx - kr * 192;
        unsigned v = 0u;
        if (p < 161) {
            const float2 w = __ldg((const float2*)&We1[(size_t)(128 + kr) * E2C + 2 * p]);
            v = bf2(w.x, w.y);
        }
        A[idx] = v;
    }
    __syncthreads();

    // ---- P1: rel_norm gather + LN stats ----
    #pragma unroll
    for (int i = 0; i < 4; i++) {
        const int e = wrow + 8 * i;
        const float* f1j = f1 + (size_t)(bbase + nbr_s[e]) * 96;
        const float r0 = f1i_s[lane * 3 + 0] - f1j[lane * 3 + 0];
        const float r1 = f1i_s[lane * 3 + 1] - f1j[lane * 3 + 1];
        const float r2 = f1i_s[lane * 3 + 2] - f1j[lane * 3 + 2];
        const float nrm = sqrtf(r0 * r0 + r1 * r1 + r2 * r2);
        EIcT[lane * 36 + e] = nrm;
        EIbT[lane * 36 + e] = bfsplat(nrm);
    }
    if (wrow == 7) {
        float x0 = nodes_s[lane], x1 = nodes_s[lane + 32];
        float s = x0 + x1, ss = x0 * x0 + x1 * x1;
        #pragma unroll
        for (int o = 16; o > 0; o >>= 1) {
            s  += __shfl_down_sync(0xffffffffu, s,  o);
            ss += __shfl_down_sync(0xffffffffu, ss, o);
        }
        if (lane == 0) {
            const float mu  = s * (1.f / 64.f);
            const float var = ss * (1.f / 64.f) - mu * mu;
            stats[0] = mu;
            stats[1] = rsqrtf(var + 1e-5f);
        }
    }
    __syncthreads();

    // ---- GEMM1 (K=33, 3 staged chunks; stride-1 conflict-free weight fetch) ----
    unsigned acc2[4][6];
    #pragma unroll
    for (int i = 0; i < 4; i++)
        #pragma unroll
        for (int jj = 0; jj < 6; jj++) acc2[i][jj] = 0u;

    #pragma unroll
    for (int s = 0; s < 3; s++) {
        for (int kr = 0; kr < 11; kr++) {
            const int k = 11 * s + kr;
            const uint4 ev4 = *(const uint4*)&EIbT[k * 36 + 4 * wrow];
            #pragma unroll
            for (int jj = 0; jj < 6; jj++) {
                const unsigned w = A[kr * 192 + lane + 32 * jj];
                acc2[0][jj] = hfma2(ev4.x, w, acc2[0][jj]);
                acc2[1][jj] = hfma2(ev4.y, w, acc2[1][jj]);
                acc2[2][jj] = hfma2(ev4.z, w, acc2[2][jj]);
                acc2[3][jj] = hfma2(ev4.w, w, acc2[3][jj]);
            }
        }
        __syncthreads();
        if (s < 2) {
            for (int idx = tid; idx < 11 * 192; idx += 256) {
                const int kr = idx / 192, p = idx - kr * 192;
                unsigned v = 0u;
                if (p < 161) {
                    const float2 w = __ldg((const float2*)&We1[(size_t)(128 + 11 * (s + 1) + kr) * E2C + 2 * p]);
                    v = bf2(w.x, w.y);
                }
                A[idx] = v;
            }
            __syncthreads();
        }
    }

    // ---- epilogue: H1 = bf16(silu(acc + PI + PJ)), overlap We2 chunk-0 staging ----
    #pragma unroll
    for (int i = 0; i < 4; i++) {
        const int e = 4 * wrow + i;
        const float* pj = PJ_g + (size_t)(bbase + nbr_s[e]) * E2C;
        #pragma unroll
        for (int jj = 0; jj < 6; jj++) {
            const int p = lane + 32 * jj;
            if (p < 161) {
                const float2 pi2 = *(const float2*)&PI[2 * p];
                const float2 pj2 = __ldg((const float2*)(pj + 2 * p));
                const float h0 = siluf(blo(acc2[i][jj]) + pi2.x + pj2.x);
                const float h1 = siluf(bhi(acc2[i][jj]) + pi2.y + pj2.y);
                H1u[e * 164 + p] = bf2(h0, h1);
            }
        }
    }
    if (tid < 96) H1u[(tid / 3) * 164 + 161 + (tid % 3)] = 0u;
    for (int idx = tid; idx < 21 * 32; idx += 256) {
        const int c8 = idx >> 5, r = idx & 31;
        const int m = r >> 3, q = r & 7;
        const int k = 8 * c8 + 2 * m;
        const float4 w0 = __ldg((const float4*)&We2[k * 32 + 4 * q]);
        const float4 w1 = __ldg((const float4*)&We2[(k + 1) * 32 + 4 * q]);
        A[c8 * 128 + (4 * q + 0) * 4 + m] = bf2(w0.x, w1.x);
        A[c8 * 128 + (4 * q + 1) * 4 + m] = bf2(w0.y, w1.y);
        A[c8 * 128 + (4 * q + 2) * 4 + m] = bf2(w0.z, w1.z);
        A[c8 * 128 + (4 * q + 3) * 4 + m] = bf2(w0.w, w1.w);
    }
    __syncthreads();

    // ---- GEMM2 (4 edges x 1 col per thread; R8 layout) ----
    {
        unsigned a2[4] = {0u, 0u, 0u, 0u};
        const uint4* A4 = (const uint4*)A;
        const uint4* H4 = (const uint4*)H1u;   // row stride 41
        for (int c = 0; c < 21; c++) {
            const uint4 w = A4[c * 32 + lane];
            #pragma unroll
            for (int i = 0; i < 4; i++) {
                const uint4 h = H4[(4 * wrow + i) * 41 + c];
                a2[i] = hfma2(h.x, w.x, a2[i]);
                a2[i] = hfma2(h.y, w.y, a2[i]);
                a2[i] = hfma2(h.z, w.z, a2[i]);
                a2[i] = hfma2(h.w, w.w, a2[i]);
            }
        }
        __syncthreads();
        for (int idx = tid; idx < 20 * 32; idx += 256) {
            const int c8 = idx >> 5, r = idx & 31;
            const int m = r >> 3, q = r & 7;
            const int k = 8 * (21 + c8) + 2 * m;
            float4 w0 = make_float4(0.f, 0.f, 0.f, 0.f), w1 = w0;
            if (k     < E2C) w0 = __ldg((const float4*)&We2[k * 32 + 4 * q]);
            if (k + 1 < E2C) w1 = __ldg((const float4*)&We2[(k + 1) * 32 + 4 * q]);
            A[c8 * 128 + (4 * q + 0) * 4 + m] = bf2(w0.x, w1.x);
            A[c8 * 128 + (4 * q + 1) * 4 + m] = bf2(w0.y, w1.y);
            A[c8 * 128 + (4 * q + 2) * 4 + m] = bf2(w0.z, w1.z);
            A[c8 * 128 + (4 * q + 3) * 4 + m] = bf2(w0.w, w1.w);
        }
        __syncthreads();
        for (int c = 0; c < 20; c++) {
            const uint4 w = A4[c * 32 + lane];
            #pragma unroll
            for (int i = 0; i < 4; i++) {
                const uint4 h = H4[(4 * wrow + i) * 41 + 21 + c];
                a2[i] = hfma2(h.x, w.x, a2[i]);
                a2[i] = hfma2(h.y, w.y, a2[i]);
                a2[i] = hfma2(h.z, w.z, a2[i]);
                a2[i] = hfma2(h.w, w.w, a2[i]);
            }
        }
        #pragma unroll
        for (int i = 0; i < 4; i++) {
            const float m = siluf(blo(a2[i]) + bhi(a2[i]) + be2[lane]);
            MSbT[lane * 36 + 4 * wrow + i] = bfsplat(m);
        }
    }
    __syncthreads();

    // ---- stage Wh1 (warps 0-6) + MI (warp 7) ----
    if (wrow < 7) {
        for (int idx = tid; idx < 1024; idx += 224) {
            const float4 w = __ldg((const float4*)&Wh1[(idx >> 5) * 128 + 4 * (idx & 31)]);
            A[2 * idx]     = bf2(w.x, w.y);
            A[2 * idx + 1] = bf2(w.z, w.w);
        }
    } else {
        float s = 0.f;
        #pragma unroll 8
        for (int e = 0; e < 32; e++)
            s += maskv[e] * blo(MSbT[lane * 36 + e]);
        MI[lane] = s;
    }
    __syncthreads();

    // ---- GEMM3: G1 = silu(MS @ Wh1 + bh1) ----
    unsigned a3[4][2];
    #pragma unroll
    for (int i = 0; i < 4; i++) { a3[i][0] = 0u; a3[i][1] = 0u; }
    #pragma unroll 4
    for (int r = 0; r < 32; r++) {
        const uint4 mv4 = *(const uint4*)&MSbT[r * 36 + 4 * wrow];
        const unsigned w0 = A[r * 64 + lane * 2];
        const unsigned w1 = A[r * 64 + lane * 2 + 1];
        a3[0][0] = hfma2(mv4.x, w0, a3[0][0]); a3[0][1] = hfma2(mv4.x, w1, a3[0][1]);
        a3[1][0] = hfma2(mv4.y, w0, a3[1][0]); a3[1][1] = hfma2(mv4.y, w1, a3[1][1]);
        a3[2][0] = hfma2(mv4.z, w0, a3[2][0]); a3[2][1] = hfma2(mv4.z, w1, a3[2][1]);
        a3[3][0] = hfma2(mv4.w, w0, a3[3][0]); a3[3][1] = hfma2(mv4.w, w1, a3[3][1]);
    }
    __syncthreads();

    // ---- G1 write + stage Wh2 ----
    #pragma unroll
    for (int i = 0; i < 4; i++) {
        const int e = 4 * wrow + i;
        #pragma unroll
        for (int jj = 0; jj < 2; jj++) {
            const int c0 = 4 * lane + 2 * jj;
            const float g0 = siluf(blo(a3[i][jj]) + bh1[c0]);
            const float g1 = siluf(bhi(a3[i][jj]) + bh1[c0 + 1]);
            G1u[e * 68 + lane * 2 + jj] = bf2(g0, g1);
        }
    }
    for (int idx = tid; idx < 512; idx += 256) {
        const int c8 = idx >> 5, r = idx & 31;
        const int m = r >> 3, q = r & 7;
        const int k = 8 * c8 + 2 * m;
        const float4 w0 = __ldg((const float4*)&Wh2[k * 32 + 4 * q]);
        const float4 w1 = __ldg((const float4*)&Wh2[(k + 1) * 32 + 4 * q]);
        A[c8 * 128 + (4 * q + 0) * 4 + m] = bf2(w0.x, w1.x);
        A[c8 * 128 + (4 * q + 1) * 4 + m] = bf2(w0.y, w1.y);
        A[c8 * 128 + (4 * q + 2) * 4 + m] = bf2(w0.z, w1.z);
        A[c8 * 128 + (4 * q + 3) * 4 + m] = bf2(w0.w, w1.w);
    }
    __syncthreads();

    // ---- GEMM4 (4 edges x 1 col; R8 layout) ----
    {
        unsigned a4[4] = {0u, 0u, 0u, 0u};
        const uint4* A4 = (const uint4*)A;
        const uint4* G4 = (const uint4*)G1u;   // row stride 17
        for (int c = 0; c < 16; c++) {
            const uint4 w = A4[c * 32 + lane];
            #pragma unroll
            for (int i = 0; i < 4; i++) {
                const uint4 g = G4[(4 * wrow + i) * 17 + c];
                a4[i] = hfma2(g.x, w.x, a4[i]);
                a4[i] = hfma2(g.y, w.y, a4[i]);
                a4[i] = hfma2(g.z, w.z, a4[i]);
                a4[i] = hfma2(g.w, w.w, a4[i]);
            }
        }
        #pragma unroll
        for (int i = 0; i < 4; i++)
            WST[lane * 36 + 4 * wrow + i] = blo(a4[i]) + bhi(a4[i]) + bh2[lane];
    }
    __syncthreads();

    // ---- htype (warps 0-5) + NI prep (warps 6-7) ----
    if (tid < 192) {
        const int half = (tid >= 96);
        const int t = tid - 96 * half;
        const int d = t / 3;
        const float hs = hns[d], hb = hnb[d];
        const float fi = f1i_s[t];
        const int e0 = half * 16;
        float s = 0.f;
        #pragma unroll
        for (int e4 = 0; e4 < 4; e4++) {
            const float4 nrm4 = *(const float4*)&EIcT[d * 36 + e0 + 4 * e4];
            const float4 w4   = *(const float4*)&WST[d * 36 + e0 + 4 * e4];
            #pragma unroll
            for (int m = 0; m < 4; m++) {
                const int e = e0 + 4 * e4 + m;
                const float nrm = (m == 0) ? nrm4.x : (m == 1) ? nrm4.y : (m == 2) ? nrm4.z : nrm4.w;
                const float wv  = (m == 0) ? w4.x   : (m == 1) ? w4.y   : (m == 2) ? w4.z   : w4.w;
                const float coef = __fdividef(nrm * hs + hb, fmaxf(nrm, 1e-8f));
                const float relv = fi - __ldg(&f1[(size_t)(bbase + nbr_s[e]) * 96 + t]);
                s += relv * coef * wv;
            }
        }
        HT2[tid] = s;
    } else if (tid < 256) {
        const int c = tid - 192;
        NI[c] = (nodes_s[c] - stats[0]) * stats[1] * lng[c] + lnb[c];
        if (c < 32) NI[64 + c] = MI[c];
    }
    __syncthreads();

    // ---- N1: 256 threads, 2-way K-split, transposed weights ----
    {
        const int col = tid & 127, half = tid >> 7, k0 = half * 48;
        const float* w = &Wn1T_g[col * 96 + k0];
        ull s2 = 0ull;
        #pragma unroll
        for (int q = 0; q < 12; q++) {
            const float4 wv = __ldg((const float4*)&w[4 * q]);
            const float4 nv = *(const float4*)&NI[k0 + 4 * q];
            s2 = ffma2(pk2(nv.x, nv.y), pk2(wv.x, wv.y), s2);
            s2 = ffma2(pk2(nv.z, nv.w), pk2(wv.z, wv.w), s2);
        }
        float lo, hi; up2(s2, lo, hi);
        Ppart[tid] = lo + hi;
    }
    __syncthreads();
    if (tid < 128) N1s[tid] = siluf(Ppart[tid] + Ppart[tid + 128] + bn1[tid]);
    __syncthreads();

    // ---- node_out: 256 threads, 4-way K-split ----
    {
        const int col = tid & 63, q4 = tid >> 6, k0 = 32 * q4;
        const float* w = &Wn2T_g[col * 128 + k0];
        ull s2 = 0ull;
        #pragma unroll
        for (int q = 0; q < 8; q++) {
            const float4 wv = __ldg((const float4*)&w[4 * q]);
            const float4 nv = *(const float4*)&N1s[k0 + 4 * q];
            s2 = ffma2(pk2(nv.x, nv.y), pk2(wv.x, wv.y), s2);
            s2 = ffma2(pk2(nv.z, nv.w), pk2(wv.z, wv.w), s2);
        }
        float lo, hi; up2(s2, lo, hi);
        Ppart[tid] = lo + hi;
    }
    __syncthreads();
    if (tid < 64) {
        const float v = Ppart[tid] + Ppart[tid + 64] + Ppart[tid + 128] + Ppart[tid + 192]
                      + bn2[tid] + nodes_s[tid];
        nouts[tid] = v;
        out[(size_t)node * 64 + tid] = v;
    }
    __syncthreads();

    // ---- gate: 128 threads, 4-way K-split ----
    if (tid < 128) {
        const int col = tid & 31, q4 = tid >> 5, k0 = 16 * q4;
        const float* w = &WgT_g[col * 64 + k0];
        ull s2 = 0ull;
        #pragma unroll
        for (int q = 0; q < 4; q++) {
            const float4 wv = __ldg((const float4*)&w[4 * q]);
            const float4 nv = *(const float4*)&nouts[k0 + 4 * q];
            s2 = ffma2(pk2(nv.x, nv.y), pk2(wv.x, wv.y), s2);
            s2 = ffma2(pk2(nv.z, nv.w), pk2(wv.z, wv.w), s2);
        }
        float lo, hi; up2(s2, lo, hi);
        Ppart[tid] = lo + hi;
    }
    __syncthreads();
    if (tid < 32)
        gates[tid] = sigmf(Ppart[tid] + Ppart[tid + 32] + Ppart[tid + 64] + Ppart[tid + 96] + bg[tid]);
    __syncthreads();

    // ---- f1_out ----
    if (tid < 96) {
        const int d = tid / 3;
        const float v = (f1i_s[tid] + HT2[tid] + HT2[96 + tid]) * gates[d];
        out[(size_t)Bb * Nn * D0 + (size_t)node * 96 + tid] = v;
    }
}

extern "C" void kernel_launch(void* const* d_in, const int* in_sizes, int n_in,
                              void* d_out, int out_size) {
    const float* f0   = (const float*)d_in[0];
    const float* f1   = (const float*)d_in[1];
    const int*   nbr  = (const int*)d_in[2];
    const unsigned char* msk = (const unsigned char*)d_in[3];
    const float* rdist= (const float*)d_in[4];
    const float* We1  = (const float*)d_in[5];
    const float* be1  = (const float*)d_in[6];
    const float* We2  = (const float*)d_in[7];
    const float* be2  = (const float*)d_in[8];
    const float* Wh1  = (const float*)d_in[9];
    const float* bh1  = (const float*)d_in[10];
    const float* Wh2  = (const float*)d_in[11];
    const float* bh2  = (const float*)d_in[12];
    const float* Wn1  = (const float*)d_in[13];
    const float* bn1  = (const float*)d_in[14];
    const float* Wn2  = (const float*)d_in[15];
    const float* bn2  = (const float*)d_in[16];
    const float* Wg   = (const float*)d_in[17];
    const float* bg   = (const float*)d_in[18];
    const float* lng  = (const float*)d_in[19];
    const float* lnb  = (const float*)d_in[20];
    const float* hns  = (const float*)d_in[21];
    const float* hnb  = (const float*)d_in[22];
    float* out = (float*)d_out;

    proj_kernel<<<NT / 8, 192>>>(f0, We1, be1);
    prep_kernel<<<88, 256>>>(Wn1, Wn2, Wg);

    const size_t smem_bytes = 13930 * 4;

    cudaFuncSetAttribute(egnn_main, cudaFuncAttributeMaxDynamicSharedMemorySize,
                         (int)smem_bytes);

    egnn_main<<<NT, 256, smem_bytes>>>(
        f0, f1, nbr, msk, rdist, We1,
        We2, be2, Wh1, bh1, Wh2, bh2,
        bn1, bn2, bg, lng, lnb, hns, hnb, out);
}

// round 11
// speedup vs baseline: 1.2794x; 1.1504x over previous
#include <cuda_runtime.h>
#include <math.h>

#define Bb 2
#define Nn 4096
#define NT (Bb*Nn)
#define Kk 32
#define D0 64
#define E2C 322

typedef unsigned long long ull;

__device__ float PI_g[(size_t)NT * E2C + 384];
__device__ float PJ_g[(size_t)NT * E2C + 384];

__device__ __forceinline__ float siluf(float x) { return x / (1.f + __expf(-x)); }
__device__ __forceinline__ float sigmf(float x) { return 1.f / (1.f + __expf(-x)); }
__device__ __forceinline__ unsigned bf2(float lo, float hi) {
    unsigned r; asm("cvt.rn.bf16x2.f32 %0, %1, %2;" : "=r"(r) : "f"(hi), "f"(lo)); return r;
}
__device__ __forceinline__ unsigned bfsplat(float x) {
    unsigned r; asm("cvt.rn.bf16x2.f32 %0, %1, %1;" : "=r"(r) : "f"(x)); return r;
}
__device__ __forceinline__ unsigned hfma2(unsigned a, unsigned b, unsigned c) {
    unsigned d; asm("fma.rn.bf16x2 %0, %1, %2, %3;" : "=r"(d) : "r"(a), "r"(b), "r"(c)); return d;
}
__device__ __forceinline__ float blo(unsigned u) { return __uint_as_float(u << 16); }
__device__ __forceinline__ float bhi(unsigned u) { return __uint_as_float(u & 0xffff0000u); }
__device__ __forceinline__ ull pk2(float lo, float hi) {
    ull r; asm("mov.b64 %0, {%1, %2};" : "=l"(r) : "f"(lo), "f"(hi)); return r;
}
__device__ __forceinline__ void up2(ull v, float& lo, float& hi) {
    asm("mov.b64 {%0, %1}, %2;" : "=f"(lo), "=f"(hi) : "l"(v));
}
__device__ __forceinline__ ull ffma2(ull a, ull b, ull c) {
    ull d; asm("fma.rn.f32x2 %0, %1, %2, %3;" : "=l"(d) : "l"(a), "l"(b), "l"(c)); return d;
}

// ---------------- per-node projections: 8 nodes/block, register-reuse GEMM
__global__ void __launch_bounds__(192)
proj_kernel(const float* __restrict__ f0, const float* __restrict__ We1,
            const float* __restrict__ be1)
{
    __shared__ ull ndu[8][64];
    const int nb = blockIdx.x * 8;
    const int tid = threadIdx.x;
    for (int idx = tid; idx < 512; idx += 192) {
        const float v = f0[(size_t)nb * 64 + idx];
        ndu[idx >> 6][idx & 63] = pk2(v, v);
    }
    __syncthreads();
    const int p = tid;
    if (p < 161) {
        ull si[8], sj[8];
        #pragma unroll
        for (int n = 0; n < 8; n++) { si[n] = 0ull; sj[n] = 0ull; }
        for (int d = 0; d < 64; d++) {
            const float2 wi = __ldg((const float2*)&We1[(size_t)d * E2C + 2 * p]);
            const float2 wj = __ldg((const float2*)&We1[(size_t)(64 + d) * E2C + 2 * p]);
            const ull wiu = pk2(wi.x, wi.y);
            const ull wju = pk2(wj.x, wj.y);
            #pragma unroll
            for (int n = 0; n < 8; n++) {
                const ull v = ndu[n][d];
                si[n] = ffma2(v, wiu, si[n]);
                sj[n] = ffma2(v, wju, sj[n]);
            }
        }
        const float2 b = *(const float2*)&be1[2 * p];
        #pragma unroll
        for (int n = 0; n < 8; n++) {
            float a0, a1, c0, c1;
            up2(si[n], a0, a1); up2(sj[n], c0, c1);
            *(float2*)&PI_g[(size_t)(nb + n) * E2C + 2 * p] = make_float2(a0 + b.x, a1 + b.y);
            *(float2*)&PJ_g[(size_t)(nb + n) * E2C + 2 * p] = make_float2(c0, c1);
        }
    }
}

// ---------------- main fused kernel (R8 base + LDS.64 GEMM1 + conflict-free 2x2 GEMM2/4)
__global__ void __launch_bounds__(256, 4)
egnn_main(const float* __restrict__ f0, const float* __restrict__ f1,
          const int* __restrict__ nbr, const unsigned char* __restrict__ msk,
          const float* __restrict__ rdist,
          const float* __restrict__ We1,
          const float* __restrict__ We2, const float* __restrict__ be2,
          const float* __restrict__ Wh1, const float* __restrict__ bh1,
          const float* __restrict__ Wh2, const float* __restrict__ bh2,
          const float* __restrict__ Wn1, const float* __restrict__ bn1,
          const float* __restrict__ Wn2, const float* __restrict__ bn2,
          const float* __restrict__ Wg,  const float* __restrict__ bg,
          const float* __restrict__ lng, const float* __restrict__ lnb,
          const float* __restrict__ hns, const float* __restrict__ hnb,
          float* __restrict__ out)
{
    extern __shared__ float sm[];
    unsigned* A    = (unsigned*)sm;            // 2688 u32
    unsigned* H1u  = A + 2688;                 // [32 e][164] u32; aliased by G1u
    float*    EIcT = (float*)(H1u + 5248);     // [32 d][36]
    unsigned* EIbT = (unsigned*)(EIcT + 1152); // [33 k][36]
    float*    PI   = (float*)(EIbT + 1188);    // [324]
    unsigned* MSbT = (unsigned*)(PI + 324);    // [32 r][36]
    float*    WST  = (float*)(MSbT + 1152);    // [32 d][36]
    float*    HT2  = WST + 1152;               // [192]
    float*    nodes_s = HT2 + 192;             // [64]
    float*    f1i_s   = nodes_s + 64;          // [96]
    float*    MI   = f1i_s + 96;               // [32]
    float*    NI   = MI + 32;                  // [96]
    float*    N1s  = NI + 96;                  // [128]
    float*    nouts= N1s + 128;                // [64]
    float*    gates= nouts + 64;               // [32]
    float*    maskv= gates + 32;               // [32]
    float*    stats= maskv + 32;               // [2]
    int*      nbr_s= (int*)(stats + 2);        // [32]
    unsigned* G1u  = H1u;

    const int tid  = threadIdx.x;
    const int lane = tid & 31;
    const int wrow = tid >> 5;
    const int node = blockIdx.x;
    const int bbase = (node / Nn) * Nn;

    // ---- P0 ----
    if (tid < 64)           nodes_s[tid]    = f0[(size_t)node * 64 + tid];
    else if (tid < 160)     f1i_s[tid - 64] = f1[(size_t)node * 96 + (tid - 64)];
    if (tid < 32)           nbr_s[tid] = nbr[node * Kk + tid];
    else if (tid < 64)      maskv[tid - 32] = (float)msk[node * Kk + tid - 32];
    else if (tid < 96)      EIbT[32 * 36 + (tid - 64)] = bfsplat(rdist[node * Kk + tid - 64]);
    for (int c = tid; c < 324; c += 256)
        PI[c] = (c < E2C) ? PI_g[(size_t)node * E2C + c] : 0.f;
    for (int idx = tid; idx < 11 * 192; idx += 256) {
        const int kr = idx / 192, p = idx - kr * 192;
        unsigned v = 0u;
        if (p < 161) {
            const float2 w = __ldg((const float2*)&We1[(size_t)(128 + kr) * E2C + 2 * p]);
            v = bf2(w.x, w.y);
        }
        A[idx] = v;
    }
    __syncthreads();

    // ---- P1: rel_norm gather + LN stats ----
    #pragma unroll
    for (int i = 0; i < 4; i++) {
        const int e = wrow + 8 * i;
        const float* f1j = f1 + (size_t)(bbase + nbr_s[e]) * 96;
        const float r0 = f1i_s[lane * 3 + 0] - f1j[lane * 3 + 0];
        const float r1 = f1i_s[lane * 3 + 1] - f1j[lane * 3 + 1];
        const float r2 = f1i_s[lane * 3 + 2] - f1j[lane * 3 + 2];
        const float nrm = sqrtf(r0 * r0 + r1 * r1 + r2 * r2);
        EIcT[lane * 36 + e] = nrm;
        EIbT[lane * 36 + e] = bfsplat(nrm);
    }
    if (wrow == 7) {
        float x0 = nodes_s[lane], x1 = nodes_s[lane + 32];
        float s = x0 + x1, ss = x0 * x0 + x1 * x1;
        #pragma unroll
        for (int o = 16; o > 0; o >>= 1) {
            s  += __shfl_down_sync(0xffffffffu, s,  o);
            ss += __shfl_down_sync(0xffffffffu, ss, o);
        }
        if (lane == 0) {
            const float mu  = s * (1.f / 64.f);
            const float var = ss * (1.f / 64.f) - mu * mu;
            stats[0] = mu;
            stats[1] = rsqrtf(var + 1e-5f);
        }
    }
    __syncthreads();

    // ---- GEMM1 (K=33, 3 staged chunks; LDS.64 weight pairs; p = 64g + 2*lane + h) ----
    unsigned acc2[4][6];
    #pragma unroll
    for (int i = 0; i < 4; i++)
        #pragma unroll
        for (int jj = 0; jj < 6; jj++) acc2[i][jj] = 0u;

    #pragma unroll
    for (int s = 0; s < 3; s++) {
        for (int kr = 0; kr < 11; kr++) {
            const int k = 11 * s + kr;
            const uint4 ev4 = *(const uint4*)&EIbT[k * 36 + 4 * wrow];
            const uint2 wA = *(const uint2*)&A[kr * 192 + 2 * lane];
            const uint2 wB = *(const uint2*)&A[kr * 192 + 64 + 2 * lane];
            const uint2 wC = *(const uint2*)&A[kr * 192 + 128 + 2 * lane];
            acc2[0][0] = hfma2(ev4.x, wA.x, acc2[0][0]); acc2[0][1] = hfma2(ev4.x, wA.y, acc2[0][1]);
            acc2[0][2] = hfma2(ev4.x, wB.x, acc2[0][2]); acc2[0][3] = hfma2(ev4.x, wB.y, acc2[0][3]);
            acc2[0][4] = hfma2(ev4.x, wC.x, acc2[0][4]); acc2[0][5] = hfma2(ev4.x, wC.y, acc2[0][5]);
            acc2[1][0] = hfma2(ev4.y, wA.x, acc2[1][0]); acc2[1][1] = hfma2(ev4.y, wA.y, acc2[1][1]);
            acc2[1][2] = hfma2(ev4.y, wB.x, acc2[1][2]); acc2[1][3] = hfma2(ev4.y, wB.y, acc2[1][3]);
            acc2[1][4] = hfma2(ev4.y, wC.x, acc2[1][4]); acc2[1][5] = hfma2(ev4.y, wC.y, acc2[1][5]);
            acc2[2][0] = hfma2(ev4.z, wA.x, acc2[2][0]); acc2[2][1] = hfma2(ev4.z, wA.y, acc2[2][1]);
            acc2[2][2] = hfma2(ev4.z, wB.x, acc2[2][2]); acc2[2][3] = hfma2(ev4.z, wB.y, acc2[2][3]);
            acc2[2][4] = hfma2(ev4.z, wC.x, acc2[2][4]); acc2[2][5] = hfma2(ev4.z, wC.y, acc2[2][5]);
            acc2[3][0] = hfma2(ev4.w, wA.x, acc2[3][0]); acc2[3][1] = hfma2(ev4.w, wA.y, acc2[3][1]);
            acc2[3][2] = hfma2(ev4.w, wB.x, acc2[3][2]); acc2[3][3] = hfma2(ev4.w, wB.y, acc2[3][3]);
            acc2[3][4] = hfma2(ev4.w, wC.x, acc2[3][4]); acc2[3][5] = hfma2(ev4.w, wC.y, acc2[3][5]);
        }
        __syncthreads();
        if (s < 2) {
            for (int idx = tid; idx < 11 * 192; idx += 256) {
                const int kr = idx / 192, p = idx - kr * 192;
                unsigned v = 0u;
                if (p < 161) {
                    const float2 w = __ldg((const float2*)&We1[(size_t)(128 + 11 * (s + 1) + kr) * E2C + 2 * p]);
                    v = bf2(w.x, w.y);
                }
                A[idx] = v;
            }
            __syncthreads();
        }
    }

    // ---- epilogue: H1 = bf16(silu(acc + PI + PJ)); p = 64*(jj>>1) + 2*lane + (jj&1) ----
    #pragma unroll
    for (int i = 0; i < 4; i++) {
        const int e = 4 * wrow + i;
        const float* pj = PJ_g + (size_t)(bbase + nbr_s[e]) * E2C;
        #pragma unroll
        for (int jj = 0; jj < 6; jj++) {
            const int p = 64 * (jj >> 1) + 2 * lane + (jj & 1);
            if (p < 161) {
                const float2 pi2 = *(const float2*)&PI[2 * p];
                const float2 pj2 = __ldg((const float2*)(pj + 2 * p));
                const float h0 = siluf(blo(acc2[i][jj]) + pi2.x + pj2.x);
                const float h1 = siluf(bhi(acc2[i][jj]) + pi2.y + pj2.y);
                H1u[e * 164 + p] = bf2(h0, h1);
            }
        }
    }
    if (tid < 96) H1u[(tid / 3) * 164 + 161 + (tid % 3)] = 0u;
    for (int idx = tid; idx < 21 * 32; idx += 256) {
        const int c8 = idx >> 5, r = idx & 31;
        const int m = r >> 3, q = r & 7;
        const int k = 8 * c8 + 2 * m;
        const float4 w0 = __ldg((const float4*)&We2[k * 32 + 4 * q]);
        const float4 w1 = __ldg((const float4*)&We2[(k + 1) * 32 + 4 * q]);
        A[c8 * 128 + (4 * q + 0) * 4 + m] = bf2(w0.x, w1.x);
        A[c8 * 128 + (4 * q + 1) * 4 + m] = bf2(w0.y, w1.y);
        A[c8 * 128 + (4 * q + 2) * 4 + m] = bf2(w0.z, w1.z);
        A[c8 * 128 + (4 * q + 3) * 4 + m] = bf2(w0.w, w1.w);
    }
    __syncthreads();

    // ---- GEMM2: 2 edges {2ep,2ep+1} x 2 cols {cp, cp+16}; conflict-free uint4 fetch ----
    {
        const int ep = tid >> 4;      // 0..15
        const int cp = tid & 15;      // 0..15
        unsigned a2[2][2] = {{0u, 0u}, {0u, 0u}};
        const uint4* A4 = (const uint4*)A;
        const uint4* H4 = (const uint4*)H1u;   // row stride 41
        for (int c = 0; c < 21; c++) {
            const uint4 w0 = A4[c * 32 + cp];
            const uint4 w1 = A4[c * 32 + cp + 16];
            #pragma unroll
            for (int i = 0; i < 2; i++) {
                const uint4 h = H4[(2 * ep + i) * 41 + c];
                a2[i][0] = hfma2(h.x, w0.x, a2[i][0]); a2[i][1] = hfma2(h.x, w1.x, a2[i][1]);
                a2[i][0] = hfma2(h.y, w0.y, a2[i][0]); a2[i][1] = hfma2(h.y, w1.y, a2[i][1]);
                a2[i][0] = hfma2(h.z, w0.z, a2[i][0]); a2[i][1] = hfma2(h.z, w1.z, a2[i][1]);
                a2[i][0] = hfma2(h.w, w0.w, a2[i][0]); a2[i][1] = hfma2(h.w, w1.w, a2[i][1]);
            }
        }
        __syncthreads();
        for (int idx = tid; idx < 20 * 32; idx += 256) {
            const int c8 = idx >> 5, r = idx & 31;
            const int m = r >> 3, q = r & 7;
            const int k = 8 * (21 + c8) + 2 * m;
            float4 w0 = make_float4(0.f, 0.f, 0.f, 0.f), w1 = w0;
            if (k     < E2C) w0 = __ldg((const float4*)&We2[k * 32 + 4 * q]);
            if (k + 1 < E2C) w1 = __ldg((const float4*)&We2[(k + 1) * 32 + 4 * q]);
            A[c8 * 128 + (4 * q + 0) * 4 + m] = bf2(w0.x, w1.x);
            A[c8 * 128 + (4 * q + 1) * 4 + m] = bf2(w0.y, w1.y);
            A[c8 * 128 + (4 * q + 2) * 4 + m] = bf2(w0.z, w1.z);
            A[c8 * 128 + (4 * q + 3) * 4 + m] = bf2(w0.w, w1.w);
        }
        __syncthreads();
        for (int c = 0; c < 20; c++) {
            const uint4 w0 = A4[c * 32 + cp];
            const uint4 w1 = A4[c * 32 + cp + 16];
            #pragma unroll
            for (int i = 0; i < 2; i++) {
                const uint4 h = H4[(2 * ep + i) * 41 + 21 + c];
                a2[i][0] = hfma2(h.x, w0.x, a2[i][0]); a2[i][1] = hfma2(h.x, w1.x, a2[i][1]);
                a2[i][0] = hfma2(h.y, w0.y, a2[i][0]); a2[i][1] = hfma2(h.y, w1.y, a2[i][1]);
                a2[i][0] = hfma2(h.z, w0.z, a2[i][0]); a2[i][1] = hfma2(h.z, w1.z, a2[i][1]);
                a2[i][0] = hfma2(h.w, w0.w, a2[i][0]); a2[i][1] = hfma2(h.w, w1.w, a2[i][1]);
            }
        }
        #pragma unroll
        for (int i = 0; i < 2; i++)
            #pragma unroll
            for (int j = 0; j < 2; j++) {
                const int col = cp + 16 * j, e = 2 * ep + i;
                const float m = siluf(blo(a2[i][j]) + bhi(a2[i][j]) + be2[col]);
                MSbT[col * 36 + e] = bfsplat(m);
            }
    }
    __syncthreads();

    // ---- stage Wh1 (warps 0-6) + MI (warp 7) ----
    if (wrow < 7) {
        for (int idx = tid; idx < 1024; idx += 224) {
            const float4 w = __ldg((const float4*)&Wh1[(idx >> 5) * 128 + 4 * (idx & 31)]);
            A[2 * idx]     = bf2(w.x, w.y);
            A[2 * idx + 1] = bf2(w.z, w.w);
        }
    } else {
        float s = 0.f;
        #pragma unroll 8
        for (int e = 0; e < 32; e++)
            s += maskv[e] * blo(MSbT[lane * 36 + e]);
        MI[lane] = s;
    }
    __syncthreads();

    // ---- GEMM3: G1 = silu(MS @ Wh1 + bh1) ----
    unsigned a3[4][2];
    #pragma unroll
    for (int i = 0; i < 4; i++) { a3[i][0] = 0u; a3[i][1] = 0u; }
    #pragma unroll 4
    for (int r = 0; r < 32; r++) {
        const uint4 mv4 = *(const uint4*)&MSbT[r * 36 + 4 * wrow];
        const uint2 w = *(const uint2*)&A[r * 64 + lane * 2];
        a3[0][0] = hfma2(mv4.x, w.x, a3[0][0]); a3[0][1] = hfma2(mv4.x, w.y, a3[0][1]);
        a3[1][0] = hfma2(mv4.y, w.x, a3[1][0]); a3[1][1] = hfma2(mv4.y, w.y, a3[1][1]);
        a3[2][0] = hfma2(mv4.z, w.x, a3[2][0]); a3[2][1] = hfma2(mv4.z, w.y, a3[2][1]);
        a3[3][0] = hfma2(mv4.w, w.x, a3[3][0]); a3[3][1] = hfma2(mv4.w, w.y, a3[3][1]);
    }
    __syncthreads();

    // ---- G1 write + stage Wh2 ----
    #pragma unroll
    for (int i = 0; i < 4; i++) {
        const int e = 4 * wrow + i;
        #pragma unroll
        for (int jj = 0; jj < 2; jj++) {
            const int c0 = 4 * lane + 2 * jj;
            const float g0 = siluf(blo(a3[i][jj]) + bh1[c0]);
            const float g1 = siluf(bhi(a3[i][jj]) + bh1[c0 + 1]);
            G1u[e * 68 + lane * 2 + jj] = bf2(g0, g1);
        }
    }
    for (int idx = tid; idx < 512; idx += 256) {
        const int c8 = idx >> 5, r = idx & 31;
        const int m = r >> 3, q = r & 7;
        const int k = 8 * c8 + 2 * m;
        const float4 w0 = __ldg((const float4*)&Wh2[k * 32 + 4 * q]);
        const float4 w1 = __ldg((const float4*)&Wh2[(k + 1) * 32 + 4 * q]);
        A[c8 * 128 + (4 * q + 0) * 4 + m] = bf2(w0.x, w1.x);
        A[c8 * 128 + (4 * q + 1) * 4 + m] = bf2(w0.y, w1.y);
        A[c8 * 128 + (4 * q + 2) * 4 + m] = bf2(w0.z, w1.z);
        A[c8 * 128 + (4 * q + 3) * 4 + m] = bf2(w0.w, w1.w);
    }
    __syncthreads();

    // ---- GEMM4: 2 edges x 2 cols {cp, cp+16} ----
    {
        const int ep = tid >> 4;
        const int cp = tid & 15;
        unsigned a4[2][2] = {{0u, 0u}, {0u, 0u}};
        const uint4* A4 = (const uint4*)A;
        const uint4* G4 = (const uint4*)G1u;   // row stride 17
        for (int c = 0; c < 16; c++) {
            const uint4 w0 = A4[c * 32 + cp];
            const uint4 w1 = A4[c * 32 + cp + 16];
            #pragma unroll
            for (int i = 0; i < 2; i++) {
                const uint4 g = G4[(2 * ep + i) * 17 + c];
                a4[i][0] = hfma2(g.x, w0.x, a4[i][0]); a4[i][1] = hfma2(g.x, w1.x, a4[i][1]);
                a4[i][0] = hfma2(g.y, w0.y, a4[i][0]); a4[i][1] = hfma2(g.y, w1.y, a4[i][1]);
                a4[i][0] = hfma2(g.z, w0.z, a4[i][0]); a4[i][1] = hfma2(g.z, w1.z, a4[i][1]);
                a4[i][0] = hfma2(g.w, w0.w, a4[i][0]); a4[i][1] = hfma2(g.w, w1.w, a4[i][1]);
            }
        }
        #pragma unroll
        for (int i = 0; i < 2; i++)
            #pragma unroll
            for (int j = 0; j < 2; j++) {
                const int col = cp + 16 * j, e = 2 * ep + i;
                WST[col * 36 + e] = blo(a4[i][j]) + bhi(a4[i][j]) + bh2[col];
            }
    }
    __syncthreads();

    // ---- htype (warps 0-5) + NI prep (warps 6-7) ----
    if (tid < 192) {
        const int half = (tid >= 96);
        const int t = tid - 96 * half;
        const int d = t / 3;
        const float hs = hns[d], hb = hnb[d];
        const float fi = f1i_s[t];
        const int e0 = half * 16;
        float s = 0.f;
        #pragma unroll
        for (int e4 = 0; e4 < 4; e4++) {
            const float4 nrm4 = *(const float4*)&EIcT[d * 36 + e0 + 4 * e4];
            const float4 w4   = *(const float4*)&WST[d * 36 + e0 + 4 * e4];
            #pragma unroll
            for (int m = 0; m < 4; m++) {
                const int e = e0 + 4 * e4 + m;
                const float nrm = (m == 0) ? nrm4.x : (m == 1) ? nrm4.y : (m == 2) ? nrm4.z : nrm4.w;
                const float wv  = (m == 0) ? w4.x   : (m == 1) ? w4.y   : (m == 2) ? w4.z   : w4.w;
                const float coef = __fdividef(nrm * hs + hb, fmaxf(nrm, 1e-8f));
                const float relv = fi - __ldg(&f1[(size_t)(bbase + nbr_s[e]) * 96 + t]);
                s += relv * coef * wv;
            }
        }
        HT2[tid] = s;
    } else if (tid < 256) {
        const int c = tid - 192;
        NI[c] = (nodes_s[c] - stats[0]) * stats[1] * lng[c] + lnb[c];
        if (c < 32) NI[64 + c] = MI[c];
    }
    __syncthreads();

    // ---- N1[128] = silu(node_in @ Wn1 + bn1) ----
    if (tid < 128) {
        float a = 0.f;
        #pragma unroll 8
        for (int r = 0; r < 96; r++) a += NI[r] * __ldg(&Wn1[r * 128 + tid]);
        N1s[tid] = siluf(a + bn1[tid]);
    }
    __syncthreads();

    // ---- node_out[64] = N1 @ Wn2 + bn2 + nodes ----
    if (tid < 64) {
        float a = 0.f;
        #pragma unroll 8
        for (int r = 0; r < 128; r++) a += N1s[r] * __ldg(&Wn2[r * 64 + tid]);
        const float v = a + bn2[tid] + nodes_s[tid];
        nouts[tid] = v;
        out[(size_t)node * 64 + tid] = v;
    }
    __syncthreads();

    // ---- gate[32] = sigmoid(node_out @ Wg + bg) ----
    if (tid < 32) {
        float a = 0.f;
        #pragma unroll 8
        for (int r = 0; r < 64; r++) a += nouts[r] * __ldg(&Wg[r * 32 + tid]);
        gates[tid] = sigmf(a + bg[tid]);
    }
    __syncthreads();

    // ---- f1_out ----
    if (tid < 96) {
        const int d = tid / 3;
        const float v = (f1i_s[tid] + HT2[tid] + HT2[96 + tid]) * gates[d];
        out[(size_t)Bb * Nn * D0 + (size_t)node * 96 + tid] = v;
    }
}

extern "C" void kernel_launch(void* const* d_in, const int* in_sizes, int n_in,
                              void* d_out, int out_size) {
    const float* f0   = (const float*)d_in[0];
    const float* f1   = (const float*)d_in[1];
    const int*   nbr  = (const int*)d_in[2];
    const unsigned char* msk = (const unsigned char*)d_in[3];
    const float* rdist= (const float*)d_in[4];
    const float* We1  = (const float*)d_in[5];
    const float* be1  = (const float*)d_in[6];
    const float* We2  = (const float*)d_in[7];
    const float* be2  = (const float*)d_in[8];
    const float* Wh1  = (const float*)d_in[9];
    const float* bh1  = (const float*)d_in[10];
    const float* Wh2  = (const float*)d_in[11];
    const float* bh2  = (const float*)d_in[12];
    const float* Wn1  = (const float*)d_in[13];
    const float* bn1  = (const float*)d_in[14];
    const float* Wn2  = (const float*)d_in[15];
    const float* bn2  = (const float*)d_in[16];
    const float* Wg   = (const float*)d_in[17];
    const float* bg   = (const float*)d_in[18];
    const float* lng  = (const float*)d_in[19];
    const float* lnb  = (const float*)d_in[20];
    const float* hns  = (const float*)d_in[21];
    const float* hnb  = (const float*)d_in[22];
    float* out = (float*)d_out;

    proj_kernel<<<NT / 8, 192>>>(f0, We1, be1);

    const size_t smem_bytes = 13674 * 4;

    cudaFuncSetAttribute(egnn_main, cudaFuncAttributeMaxDynamicSharedMemorySize,
                         (int)smem_bytes);

    egnn_main<<<NT, 256, smem_bytes>>>(
        f0, f1, nbr, msk, rdist, We1,
        We2, be2, Wh1, bh1, Wh2, bh2,
        Wn1, bn1, Wn2, bn2, Wg, bg, lng, lnb, hns, hnb, out);
}

// round 12
// speedup vs baseline: 1.5626x; 1.2213x over previous
#include <cuda_runtime.h>
#include <math.h>

#define Bb 2
#define Nn 4096
#define NT (Bb*Nn)
#define Kk 32
#define D0 64
#define E2C 322

typedef unsigned long long ull;

__device__ float PI_g[(size_t)NT * E2C + 384];
__device__ float PJ_g[(size_t)NT * E2C + 384];
__device__ __align__(16) ull Wf2_g[2688];   // We2 frags: 21 ks x 4 nt x 32 lanes
__device__ __align__(16) ull Wf3_g[1024];   // Wh1 frags: 2 ks x 16 nt x 32
__device__ __align__(16) ull Wf4_g[1024];   // Wh2 frags: 8 ks x 4 nt x 32

__device__ __forceinline__ float siluf(float x) { return x / (1.f + __expf(-x)); }
__device__ __forceinline__ float sigmf(float x) { return 1.f / (1.f + __expf(-x)); }
__device__ __forceinline__ unsigned bf2(float lo, float hi) {
    unsigned r; asm("cvt.rn.bf16x2.f32 %0, %1, %2;" : "=r"(r) : "f"(hi), "f"(lo)); return r;
}
__device__ __forceinline__ unsigned bfsplat(float x) {
    unsigned r; asm("cvt.rn.bf16x2.f32 %0, %1, %1;" : "=r"(r) : "f"(x)); return r;
}
__device__ __forceinline__ unsigned hfma2(unsigned a, unsigned b, unsigned c) {
    unsigned d; asm("fma.rn.bf16x2 %0, %1, %2, %3;" : "=r"(d) : "r"(a), "r"(b), "r"(c)); return d;
}
__device__ __forceinline__ float blo(unsigned u) { return __uint_as_float(u << 16); }
__device__ __forceinline__ float bhi(unsigned u) { return __uint_as_float(u & 0xffff0000u); }
__device__ __forceinline__ ull pk2(float lo, float hi) {
    ull r; asm("mov.b64 %0, {%1, %2};" : "=l"(r) : "f"(lo), "f"(hi)); return r;
}
__device__ __forceinline__ void up2(ull v, float& lo, float& hi) {
    asm("mov.b64 {%0, %1}, %2;" : "=f"(lo), "=f"(hi) : "l"(v));
}
__device__ __forceinline__ ull ffma2(ull a, ull b, ull c) {
    ull d; asm("fma.rn.f32x2 %0, %1, %2, %3;" : "=l"(d) : "l"(a), "l"(b), "l"(c)); return d;
}
__device__ __forceinline__ void mma16816(float& d0, float& d1, float& d2, float& d3,
    unsigned a0, unsigned a1, unsigned a2, unsigned a3, unsigned b0, unsigned b1)
{
    asm("mma.sync.aligned.m16n8k16.row.col.f32.bf16.bf16.f32 "
        "{%0,%1,%2,%3}, {%4,%5,%6,%7}, {%8,%9}, {%0,%1,%2,%3};"
        : "+f"(d0), "+f"(d1), "+f"(d2), "+f"(d3)
        : "r"(a0), "r"(a1), "r"(a2), "r"(a3), "r"(b0), "r"(b1));
}

// ---------------- per-node projections: 8 nodes/block, register-reuse GEMM
__global__ void __launch_bounds__(192)
proj_kernel(const float* __restrict__ f0, const float* __restrict__ We1,
            const float* __restrict__ be1)
{
    __shared__ ull ndu[8][64];
    const int nb = blockIdx.x * 8;
    const int tid = threadIdx.x;
    for (int idx = tid; idx < 512; idx += 192) {
        const float v = f0[(size_t)nb * 64 + idx];
        ndu[idx >> 6][idx & 63] = pk2(v, v);
    }
    __syncthreads();
    const int p = tid;
    if (p < 161) {
        ull si[8], sj[8];
        #pragma unroll
        for (int n = 0; n < 8; n++) { si[n] = 0ull; sj[n] = 0ull; }
        for (int d = 0; d < 64; d++) {
            const float2 wi = __ldg((const float2*)&We1[(size_t)d * E2C + 2 * p]);
            const float2 wj = __ldg((const float2*)&We1[(size_t)(64 + d) * E2C + 2 * p]);
            const ull wiu = pk2(wi.x, wi.y);
            const ull wju = pk2(wj.x, wj.y);
            #pragma unroll
            for (int n = 0; n < 8; n++) {
                const ull v = ndu[n][d];
                si[n] = ffma2(v, wiu, si[n]);
                sj[n] = ffma2(v, wju, sj[n]);
            }
        }
        const float2 b = *(const float2*)&be1[2 * p];
        #pragma unroll
        for (int n = 0; n < 8; n++) {
            float a0, a1, c0, c1;
            up2(si[n], a0, a1); up2(sj[n], c0, c1);
            *(float2*)&PI_g[(size_t)(nb + n) * E2C + 2 * p] = make_float2(a0 + b.x, a1 + b.y);
            *(float2*)&PJ_g[(size_t)(nb + n) * E2C + 2 * p] = make_float2(c0, c1);
        }
    }
}

// ---------------- pre-pack B fragments for mma (per-lane order)
__global__ void __launch_bounds__(256)
prep_frag(const float* __restrict__ We2, const float* __restrict__ Wh1,
          const float* __restrict__ Wh2)
{
    const int idx = blockIdx.x * 256 + threadIdx.x;
    if (idx < 2688) {                       // Wf2: ks 0..20, nt 0..3
        const int lane = idx & 31, nt = (idx >> 5) & 3, ks = idx >> 7;
        const int g = lane >> 2, tg = lane & 3;
        const int n = 8 * nt + g;
        const int k = 16 * ks + 2 * tg;
        const float w00 = (k     < E2C) ? We2[k * 32 + n]       : 0.f;
        const float w01 = (k + 1 < E2C) ? We2[(k + 1) * 32 + n] : 0.f;
        const float w10 = (k + 8 < E2C) ? We2[(k + 8) * 32 + n] : 0.f;
        const float w11 = (k + 9 < E2C) ? We2[(k + 9) * 32 + n] : 0.f;
        Wf2_g[idx] = (ull)bf2(w00, w01) | ((ull)bf2(w10, w11) << 32);
    } else if (idx < 2688 + 1024) {         // Wf3: ks 0..1, nt 0..15
        const int j = idx - 2688;
        const int lane = j & 31, nt = (j >> 5) & 15, ks = j >> 9;
        const int g = lane >> 2, tg = lane & 3;
        const int n = 8 * nt + g;
        const int k = 16 * ks + 2 * tg;
        Wf3_g[j] = (ull)bf2(Wh1[k * 128 + n], Wh1[(k + 1) * 128 + n])
                 | ((ull)bf2(Wh1[(k + 8) * 128 + n], Wh1[(k + 9) * 128 + n]) << 32);
    } else if (idx < 2688 + 2048) {         // Wf4: ks 0..7, nt 0..3
        const int j = idx - 2688 - 1024;
        const int lane = j & 31, nt = (j >> 5) & 3, ks = j >> 7;
        const int g = lane >> 2, tg = lane & 3;
        const int n = 8 * nt + g;
        const int k = 16 * ks + 2 * tg;
        Wf4_g[j] = (ull)bf2(Wh2[k * 32 + n], Wh2[(k + 1) * 32 + n])
                 | ((ull)bf2(Wh2[(k + 8) * 32 + n], Wh2[(k + 9) * 32 + n]) << 32);
    }
}

// ---------------- main fused kernel: GEMM1 hfma2, GEMM2/3/4 tensor-core mma
__global__ void __launch_bounds__(256, 4)
egnn_main(const float* __restrict__ f0, const float* __restrict__ f1,
          const int* __restrict__ nbr, const unsigned char* __restrict__ msk,
          const float* __restrict__ rdist,
          const float* __restrict__ We1,
          const float* __restrict__ be2, const float* __restrict__ bh1,
          const float* __restrict__ bh2,
          const float* __restrict__ Wn1, const float* __restrict__ bn1,
          const float* __restrict__ Wn2, const float* __restrict__ bn2,
          const float* __restrict__ Wg,  const float* __restrict__ bg,
          const float* __restrict__ lng, const float* __restrict__ lnb,
          const float* __restrict__ hns, const float* __restrict__ hnb,
          float* __restrict__ out)
{
    extern __shared__ float sm[];
    unsigned* A    = (unsigned*)sm;            // 2816 u32: staging (GEMM1 weights / B-frags)
    unsigned* H1u  = A + 2816;                 // [32 e][172] u32 bf16-pairs; aliased by G1u
    float*    EIcT = (float*)(H1u + 5504);     // [32 d][36]
    unsigned* EIbT = (unsigned*)(EIcT + 1152); // [33 k][36] splat
    float*    PI   = (float*)(EIbT + 1188);    // [324]
    unsigned* MSbP = (unsigned*)(PI + 324);    // [32 e][20] m_ij bf16 pairs
    float*    WST  = (float*)(MSbP + 640);     // [32 d][36] w fp32 (transposed)
    float*    HT2  = WST + 1152;               // [192]
    float*    nodes_s = HT2 + 192;             // [64]
    float*    f1i_s   = nodes_s + 64;          // [96]
    float*    MI   = f1i_s + 96;               // [32]
    float*    NI   = MI + 32;                  // [96]
    float*    N1s  = NI + 96;                  // [128]
    float*    nouts= N1s + 128;                // [64]
    float*    gates= nouts + 64;               // [32]
    float*    maskv= gates + 32;               // [32]
    float*    stats= maskv + 32;               // [2]
    int*      nbr_s= (int*)(stats + 2);        // [32]
    unsigned* G1u  = H1u;                      // alias: [32 e][68] u32
    const uint2* Au2 = (const uint2*)A;

    const int tid  = threadIdx.x;
    const int lane = tid & 31;
    const int wrow = tid >> 5;
    const int g    = lane >> 2;
    const int tg   = lane & 3;
    const int node = blockIdx.x;
    const int bbase = (node / Nn) * Nn;

    // ---- P0 ----
    if (tid < 64)           nodes_s[tid]    = f0[(size_t)node * 64 + tid];
    else if (tid < 160)     f1i_s[tid - 64] = f1[(size_t)node * 96 + (tid - 64)];
    if (tid < 32)           nbr_s[tid] = nbr[node * Kk + tid];
    else if (tid < 64)      maskv[tid - 32] = (float)msk[node * Kk + tid - 32];
    else if (tid < 96)      EIbT[32 * 36 + (tid - 64)] = bfsplat(rdist[node * Kk + tid - 64]);
    for (int c = tid; c < 324; c += 256)
        PI[c] = (c < E2C) ? PI_g[(size_t)node * E2C + c] : 0.f;
    for (int idx = tid; idx < 11 * 192; idx += 256) {
        const int kr = idx / 192, p = idx - kr * 192;
        unsigned v = 0u;
        if (p < 161) {
            const float2 w = __ldg((const float2*)&We1[(size_t)(128 + kr) * E2C + 2 * p]);
            v = bf2(w.x, w.y);
        }
        A[idx] = v;
    }
    __syncthreads();

    // ---- P1: rel_norm gather + LN stats ----
    #pragma unroll
    for (int i = 0; i < 4; i++) {
        const int e = wrow + 8 * i;
        const float* f1j = f1 + (size_t)(bbase + nbr_s[e]) * 96;
        const float r0 = f1i_s[lane * 3 + 0] - f1j[lane * 3 + 0];
        const float r1 = f1i_s[lane * 3 + 1] - f1j[lane * 3 + 1];
        const float r2 = f1i_s[lane * 3 + 2] - f1j[lane * 3 + 2];
        const float nrm = sqrtf(r0 * r0 + r1 * r1 + r2 * r2);
        EIcT[lane * 36 + e] = nrm;
        EIbT[lane * 36 + e] = bfsplat(nrm);
    }
    if (wrow == 7) {
        float x0 = nodes_s[lane], x1 = nodes_s[lane + 32];
        float s = x0 + x1, ss = x0 * x0 + x1 * x1;
        #pragma unroll
        for (int o = 16; o > 0; o >>= 1) {
            s  += __shfl_down_sync(0xffffffffu, s,  o);
            ss += __shfl_down_sync(0xffffffffu, ss, o);
        }
        if (lane == 0) {
            const float mu  = s * (1.f / 64.f);
            const float var = ss * (1.f / 64.f) - mu * mu;
            stats[0] = mu;
            stats[1] = rsqrtf(var + 1e-5f);
        }
    }
    __syncthreads();

    // ---- GEMM1 (K=33, hfma2, 3 staged chunks; stride-1 conflict-free) ----
    unsigned acc2[4][6];
    #pragma unroll
    for (int i = 0; i < 4; i++)
        #pragma unroll
        for (int jj = 0; jj < 6; jj++) acc2[i][jj] = 0u;

    #pragma unroll
    for (int s = 0; s < 3; s++) {
        for (int kr = 0; kr < 11; kr++) {
            const int k = 11 * s + kr;
            const uint4 ev4 = *(const uint4*)&EIbT[k * 36 + 4 * wrow];
            #pragma unroll
            for (int jj = 0; jj < 6; jj++) {
                const unsigned w = A[kr * 192 + lane + 32 * jj];
                acc2[0][jj] = hfma2(ev4.x, w, acc2[0][jj]);
                acc2[1][jj] = hfma2(ev4.y, w, acc2[1][jj]);
                acc2[2][jj] = hfma2(ev4.z, w, acc2[2][jj]);
                acc2[3][jj] = hfma2(ev4.w, w, acc2[3][jj]);
            }
        }
        __syncthreads();
        if (s < 2) {
            for (int idx = tid; idx < 11 * 192; idx += 256) {
                const int kr = idx / 192, p = idx - kr * 192;
                unsigned v = 0u;
                if (p < 161) {
                    const float2 w = __ldg((const float2*)&We1[(size_t)(128 + 11 * (s + 1) + kr) * E2C + 2 * p]);
                    v = bf2(w.x, w.y);
                }
                A[idx] = v;
            }
            __syncthreads();
        }
    }

    // ---- epilogue: H1 writes (stride 172), zero pads, Wf2 chunk-A memcpy ----
    #pragma unroll
    for (int i = 0; i < 4; i++) {
        const int e = 4 * wrow + i;
        const float* pj = PJ_g + (size_t)(bbase + nbr_s[e]) * E2C;
        #pragma unroll
        for (int jj = 0; jj < 6; jj++) {
            const int p = lane + 32 * jj;
            if (p < 161) {
                const float2 pi2 = *(const float2*)&PI[2 * p];
                const float2 pj2 = __ldg((const float2*)(pj + 2 * p));
                const float h0 = siluf(blo(acc2[i][jj]) + pi2.x + pj2.x);
                const float h1 = siluf(bhi(acc2[i][jj]) + pi2.y + pj2.y);
                H1u[e * 172 + p] = bf2(h0, h1);
            }
        }
    }
    if (tid < 224) H1u[(tid / 7) * 172 + 161 + (tid % 7)] = 0u;  // zero pairs 161..167
    for (int i = tid; i < 704; i += 256)                          // Wf2 ks 0..10
        ((uint4*)A)[i] = __ldg((const uint4*)Wf2_g + i);
    __syncthreads();

    // ---- GEMM2 (tensor): 8 warp-tiles m16n8, K=336, 2 staged chunks ----
    {
        const int mt = wrow & 1, nt = wrow >> 1;       // m-tile, n-tile
        const int e0 = 16 * mt + g;
        float d0 = 0.f, d1 = 0.f, d2 = 0.f, d3 = 0.f;
        #pragma unroll
        for (int ks = 0; ks < 11; ks++) {
            const unsigned a0 = H1u[e0 * 172 + 8 * ks + tg];
            const unsigned a1 = H1u[(e0 + 8) * 172 + 8 * ks + tg];
            const unsigned a2 = H1u[e0 * 172 + 8 * ks + 4 + tg];
            const unsigned a3 = H1u[(e0 + 8) * 172 + 8 * ks + 4 + tg];
            const uint2 b = Au2[(ks * 4 + nt) * 32 + lane];
            mma16816(d0, d1, d2, d3, a0, a1, a2, a3, b.x, b.y);
        }
        __syncthreads();
        for (int i = tid; i < 640; i += 256)           // Wf2 ks 11..20
            ((uint4*)A)[i] = __ldg((const uint4*)Wf2_g + 704 + i);
        __syncthreads();
        #pragma unroll
        for (int ks = 11; ks < 21; ks++) {
            const unsigned a0 = H1u[e0 * 172 + 8 * ks + tg];
            const unsigned a1 = H1u[(e0 + 8) * 172 + 8 * ks + tg];
            const unsigned a2 = H1u[e0 * 172 + 8 * ks + 4 + tg];
            const unsigned a3 = H1u[(e0 + 8) * 172 + 8 * ks + 4 + tg];
            const uint2 b = Au2[((ks - 11) * 4 + nt) * 32 + lane];
            mma16816(d0, d1, d2, d3, a0, a1, a2, a3, b.x, b.y);
        }
        const int col0 = 8 * nt + 2 * tg;
        const float b0 = be2[col0], b1 = be2[col0 + 1];
        MSbP[e0 * 20 + 4 * nt + tg]       = bf2(siluf(d0 + b0), siluf(d1 + b1));
        MSbP[(e0 + 8) * 20 + 4 * nt + tg] = bf2(siluf(d2 + b0), siluf(d3 + b1));
    }
    __syncthreads();

    // ---- stage Wf3 (warps 0-6) + MI (warp 7) ----
    if (wrow < 7) {
        for (int i = tid; i < 512; i += 224)
            ((uint4*)A)[i] = __ldg((const uint4*)Wf3_g + i);
    } else {
        float s = 0.f;
        #pragma unroll 8
        for (int e = 0; e < 32; e++) {
            const unsigned u = MSbP[e * 20 + (lane >> 1)];
            s += maskv[e] * ((lane & 1) ? bhi(u) : blo(u));
        }
        MI[lane] = s;
    }
    __syncthreads();

    // ---- GEMM3 (tensor): 32 tiles, 4 per warp, K=32 ----
    {
        const int mt = wrow & 1, nt0 = wrow >> 1;
        const int e0 = 16 * mt + g;
        float d[4][4];
        #pragma unroll
        for (int t = 0; t < 4; t++)
            #pragma unroll
            for (int q = 0; q < 4; q++) d[t][q] = 0.f;
        #pragma unroll
        for (int ks = 0; ks < 2; ks++) {
            const unsigned a0 = MSbP[e0 * 20 + 8 * ks + tg];
            const unsigned a1 = MSbP[(e0 + 8) * 20 + 8 * ks + tg];
            const unsigned a2 = MSbP[e0 * 20 + 8 * ks + 4 + tg];
            const unsigned a3 = MSbP[(e0 + 8) * 20 + 8 * ks + 4 + tg];
            #pragma unroll
            for (int t = 0; t < 4; t++) {
                const int nt = nt0 + 4 * t;
                const uint2 b = Au2[(ks * 16 + nt) * 32 + lane];
                mma16816(d[t][0], d[t][1], d[t][2], d[t][3], a0, a1, a2, a3, b.x, b.y);
            }
        }
        __syncthreads();   // A reads done; H1u reads (GEMM2) done -> G1u writes safe
        #pragma unroll
        for (int t = 0; t < 4; t++) {
            const int nt = nt0 + 4 * t;
            const int col0 = 8 * nt + 2 * tg;
            const float b0 = bh1[col0], b1 = bh1[col0 + 1];
            G1u[e0 * 68 + 4 * nt + tg]       = bf2(siluf(d[t][0] + b0), siluf(d[t][1] + b1));
            G1u[(e0 + 8) * 68 + 4 * nt + tg] = bf2(siluf(d[t][2] + b0), siluf(d[t][3] + b1));
        }
        for (int i = tid; i < 512; i += 256)           // stage Wf4
            ((uint4*)A)[i] = __ldg((const uint4*)Wf4_g + i);
    }
    __syncthreads();

    // ---- GEMM4 (tensor): 8 tiles, 1 per warp, K=128 ----
    {
        const int mt = wrow & 1, nt = wrow >> 1;
        const int e0 = 16 * mt + g;
        float d0 = 0.f, d1 = 0.f, d2 = 0.f, d3 = 0.f;
        #pragma unroll
        for (int ks = 0; ks < 8; ks++) {
            const unsigned a0 = G1u[e0 * 68 + 8 * ks + tg];
            const unsigned a1 = G1u[(e0 + 8) * 68 + 8 * ks + tg];
            const unsigned a2 = G1u[e0 * 68 + 8 * ks + 4 + tg];
            const unsigned a3 = G1u[(e0 + 8) * 68 + 8 * ks + 4 + tg];
            const uint2 b = Au2[(ks * 4 + nt) * 32 + lane];
            mma16816(d0, d1, d2, d3, a0, a1, a2, a3, b.x, b.y);
        }
        const int col0 = 8 * nt + 2 * tg;
        WST[col0 * 36 + e0]           = d0 + bh2[col0];
        WST[(col0 + 1) * 36 + e0]     = d1 + bh2[col0 + 1];
        WST[col0 * 36 + e0 + 8]       = d2 + bh2[col0];
        WST[(col0 + 1) * 36 + e0 + 8] = d3 + bh2[col0 + 1];
    }
    __syncthreads();

    // ---- htype (warps 0-5) + NI prep (warps 6-7) ----
    if (tid < 192) {
        const int half = (tid >= 96);
        const int t = tid - 96 * half;
        const int d = t / 3;
        const float hs = hns[d], hb = hnb[d];
        const float fi = f1i_s[t];
        const int e0 = half * 16;
        float s = 0.f;
        #pragma unroll
        for (int e4 = 0; e4 < 4; e4++) {
            const float4 nrm4 = *(const float4*)&EIcT[d * 36 + e0 + 4 * e4];
            const float4 w4   = *(const float4*)&WST[d * 36 + e0 + 4 * e4];
            #pragma unroll
            for (int m = 0; m < 4; m++) {
                const int e = e0 + 4 * e4 + m;
                const float nrm = (m == 0) ? nrm4.x : (m == 1) ? nrm4.y : (m == 2) ? nrm4.z : nrm4.w;
                const float wv  = (m == 0) ? w4.x   : (m == 1) ? w4.y   : (m == 2) ? w4.z   : w4.w;
                const float coef = __fdividef(nrm * hs + hb, fmaxf(nrm, 1e-8f));
                const float relv = fi - __ldg(&f1[(size_t)(bbase + nbr_s[e]) * 96 + t]);
                s += relv * coef * wv;
            }
        }
        HT2[tid] = s;
    } else if (tid < 256) {
        const int c = tid - 192;
        NI[c] = (nodes_s[c] - stats[0]) * stats[1] * lng[c] + lnb[c];
        if (c < 32) NI[64 + c] = MI[c];
    }
    __syncthreads();

    // ---- N1[128] = silu(node_in @ Wn1 + bn1) ----
    if (tid < 128) {
        float a = 0.f;
        #pragma unroll 8
        for (int r = 0; r < 96; r++) a += NI[r] * __ldg(&Wn1[r * 128 + tid]);
        N1s[tid] = siluf(a + bn1[tid]);
    }
    __syncthreads();

    // ---- node_out[64] = N1 @ Wn2 + bn2 + nodes ----
    if (tid < 64) {
        float a = 0.f;
        #pragma unroll 8
        for (int r = 0; r < 128; r++) a += N1s[r] * __ldg(&Wn2[r * 64 + tid]);
        const float v = a + bn2[tid] + nodes_s[tid];
        nouts[tid] = v;
        out[(size_t)node * 64 + tid] = v;
    }
    __syncthreads();

    // ---- gate[32] = sigmoid(node_out @ Wg + bg) ----
    if (tid < 32) {
        float a = 0.f;
        #pragma unroll 8
        for (int r = 0; r < 64; r++) a += nouts[r] * __ldg(&Wg[r * 32 + tid]);
        gates[tid] = sigmf(a + bg[tid]);
    }
    __syncthreads();

    // ---- f1_out ----
    if (tid < 96) {
        const int d = tid / 3;
        const float v = (f1i_s[tid] + HT2[tid] + HT2[96 + tid]) * gates[d];
        out[(size_t)Bb * Nn * D0 + (size_t)node * 96 + tid] = v;
    }
}

extern "C" void kernel_launch(void* const* d_in, const int* in_sizes, int n_in,
                              void* d_out, int out_size) {
    const float* f0   = (const float*)d_in[0];
    const float* f1   = (const float*)d_in[1];
    const int*   nbr  = (const int*)d_in[2];
    const unsigned char* msk = (const unsigned char*)d_in[3];
    const float* rdist= (const float*)d_in[4];
    const float* We1  = (const float*)d_in[5];
    const float* be1  = (const float*)d_in[6];
    const float* We2  = (const float*)d_in[7];
    const float* be2  = (const float*)d_in[8];
    const float* Wh1  = (const float*)d_in[9];
    const float* bh1  = (const float*)d_in[10];
    const float* Wh2  = (const float*)d_in[11];
    const float* bh2  = (const float*)d_in[12];
    const float* Wn1  = (const float*)d_in[13];
    const float* bn1  = (const float*)d_in[14];
    const float* Wn2  = (const float*)d_in[15];
    const float* bn2  = (const float*)d_in[16];
    const float* Wg   = (const float*)d_in[17];
    const float* bg   = (const float*)d_in[18];
    const float* lng  = (const float*)d_in[19];
    const float* lnb  = (const float*)d_in[20];
    const float* hns  = (const float*)d_in[21];
    const float* hnb  = (const float*)d_in[22];
    float* out = (float*)d_out;

    proj_kernel<<<NT / 8, 192>>>(f0, We1, be1);
    prep_frag<<<19, 256>>>(We2, Wh1, Wh2);

    const size_t smem_bytes = 13546 * 4;

    cudaFuncSetAttribute(egnn_main, cudaFuncAttributeMaxDynamicSharedMemorySize,
                         (int)smem_bytes);

    egnn_main<<<NT, 256, smem_bytes>>>(
        f0, f1, nbr, msk, rdist, We1,
        be2, bh1, bh2,
        Wn1, bn1, Wn2, bn2, Wg, bg, lng, lnb, hns, hnb, out);
}

// round 13
// speedup vs baseline: 1.8357x; 1.1748x over previous
#include <cuda_runtime.h>
#include <math.h>

#define Bb 2
#define Nn 4096
#define NT (Bb*Nn)
#define Kk 32
#define D0 64
#define E2C 322

typedef unsigned long long ull;

__device__ float PI_g[(size_t)NT * E2C + 384];
__device__ float PJ_g[(size_t)NT * E2C + 384];
__device__ __align__(16) ull Wf1_g[4032];   // We1-tail frags: 3 chunks x 3 ks x 14 ntl x 32
__device__ __align__(16) ull Wf2_g[2688];   // We2 frags: 21 ks x 4 nt x 32
__device__ __align__(16) ull Wf3_g[1024];   // Wh1 frags: 2 ks x 16 nt x 32
__device__ __align__(16) ull Wf4_g[1024];   // Wh2 frags: 8 ks x 4 nt x 32

__device__ __forceinline__ float siluf(float x) { return x / (1.f + __expf(-x)); }
__device__ __forceinline__ float sigmf(float x) { return 1.f / (1.f + __expf(-x)); }
__device__ __forceinline__ unsigned bf2(float lo, float hi) {
    unsigned r; asm("cvt.rn.bf16x2.f32 %0, %1, %2;" : "=r"(r) : "f"(hi), "f"(lo)); return r;
}
__device__ __forceinline__ float blo(unsigned u) { return __uint_as_float(u << 16); }
__device__ __forceinline__ float bhi(unsigned u) { return __uint_as_float(u & 0xffff0000u); }
__device__ __forceinline__ ull pk2(float lo, float hi) {
    ull r; asm("mov.b64 %0, {%1, %2};" : "=l"(r) : "f"(lo), "f"(hi)); return r;
}
__device__ __forceinline__ void up2(ull v, float& lo, float& hi) {
    asm("mov.b64 {%0, %1}, %2;" : "=f"(lo), "=f"(hi) : "l"(v));
}
__device__ __forceinline__ ull ffma2(ull a, ull b, ull c) {
    ull d; asm("fma.rn.f32x2 %0, %1, %2, %3;" : "=l"(d) : "l"(a), "l"(b), "l"(c)); return d;
}
__device__ __forceinline__ void mma16816(float& d0, float& d1, float& d2, float& d3,
    unsigned a0, unsigned a1, unsigned a2, unsigned a3, unsigned b0, unsigned b1)
{
    asm("mma.sync.aligned.m16n8k16.row.col.f32.bf16.bf16.f32 "
        "{%0,%1,%2,%3}, {%4,%5,%6,%7}, {%8,%9}, {%0,%1,%2,%3};"
        : "+f"(d0), "+f"(d1), "+f"(d2), "+f"(d3)
        : "r"(a0), "r"(a1), "r"(a2), "r"(a3), "r"(b0), "r"(b1));
}

// ---------------- per-node projections
__global__ void __launch_bounds__(192)
proj_kernel(const float* __restrict__ f0, const float* __restrict__ We1,
            const float* __restrict__ be1)
{
    __shared__ ull ndu[8][64];
    const int nb = blockIdx.x * 8;
    const int tid = threadIdx.x;
    for (int idx = tid; idx < 512; idx += 192) {
        const float v = f0[(size_t)nb * 64 + idx];
        ndu[idx >> 6][idx & 63] = pk2(v, v);
    }
    __syncthreads();
    const int p = tid;
    if (p < 161) {
        ull si[8], sj[8];
        #pragma unroll
        for (int n = 0; n < 8; n++) { si[n] = 0ull; sj[n] = 0ull; }
        #pragma unroll 4
        for (int d = 0; d < 64; d++) {
            const float2 wi = __ldg((const float2*)&We1[(size_t)d * E2C + 2 * p]);
            const float2 wj = __ldg((const float2*)&We1[(size_t)(64 + d) * E2C + 2 * p]);
            const ull wiu = pk2(wi.x, wi.y);
            const ull wju = pk2(wj.x, wj.y);
            #pragma unroll
            for (int n = 0; n < 8; n++) {
                const ull v = ndu[n][d];
                si[n] = ffma2(v, wiu, si[n]);
                sj[n] = ffma2(v, wju, sj[n]);
            }
        }
        const float2 b = *(const float2*)&be1[2 * p];
        #pragma unroll
        for (int n = 0; n < 8; n++) {
            float a0, a1, c0, c1;
            up2(si[n], a0, a1); up2(sj[n], c0, c1);
            *(float2*)&PI_g[(size_t)(nb + n) * E2C + 2 * p] = make_float2(a0 + b.x, a1 + b.y);
            *(float2*)&PJ_g[(size_t)(nb + n) * E2C + 2 * p] = make_float2(c0, c1);
        }
    }
}

// ---------------- pre-pack B fragments
__global__ void __launch_bounds__(256)
prep_frag(const float* __restrict__ We1, const float* __restrict__ We2,
          const float* __restrict__ Wh1, const float* __restrict__ Wh2)
{
    const int idx = blockIdx.x * 256 + threadIdx.x;
    if (idx < 4032) {                       // Wf1: chunk c, ks 0..2, ntl 0..13
        const int lane = idx & 31;
        int j = idx >> 5;
        const int ntl = j % 14; j /= 14;
        const int ks = j % 3;
        const int c  = j / 3;
        const int g = lane >> 2, tg = lane & 3;
        const int n = 8 * (14 * c + ntl) + g;
        const int k = 16 * ks + 2 * tg;
        float w00 = 0.f, w01 = 0.f, w10 = 0.f, w11 = 0.f;
        if (n < E2C) {
            if (k     < 33) w00 = We1[(size_t)(128 + k)     * E2C + n];
            if (k + 1 < 33) w01 = We1[(size_t)(128 + k + 1) * E2C + n];
            if (k + 8 < 33) w10 = We1[(size_t)(128 + k + 8) * E2C + n];
            if (k + 9 < 33) w11 = We1[(size_t)(128 + k + 9) * E2C + n];
        }
        Wf1_g[idx] = (ull)bf2(w00, w01) | ((ull)bf2(w10, w11) << 32);
    } else if (idx < 4032 + 2688) {         // Wf2
        const int j = idx - 4032;
        const int lane = j & 31, nt = (j >> 5) & 3, ks = j >> 7;
        const int g = lane >> 2, tg = lane & 3;
        const int n = 8 * nt + g;
        const int k = 16 * ks + 2 * tg;
        const float w00 = (k     < E2C) ? We2[k * 32 + n]       : 0.f;
        const float w01 = (k + 1 < E2C) ? We2[(k + 1) * 32 + n] : 0.f;
        const float w10 = (k + 8 < E2C) ? We2[(k + 8) * 32 + n] : 0.f;
        const float w11 = (k + 9 < E2C) ? We2[(k + 9) * 32 + n] : 0.f;
        Wf2_g[j] = (ull)bf2(w00, w01) | ((ull)bf2(w10, w11) << 32);
    } else if (idx < 4032 + 2688 + 1024) {  // Wf3
        const int j = idx - 4032 - 2688;
        const int lane = j & 31, nt = (j >> 5) & 15, ks = j >> 9;
        const int g = lane >> 2, tg = lane & 3;
        const int n = 8 * nt + g;
        const int k = 16 * ks + 2 * tg;
        Wf3_g[j] = (ull)bf2(Wh1[k * 128 + n], Wh1[(k + 1) * 128 + n])
                 | ((ull)bf2(Wh1[(k + 8) * 128 + n], Wh1[(k + 9) * 128 + n]) << 32);
    } else if (idx < 4032 + 2688 + 2048) {  // Wf4
        const int j = idx - 4032 - 2688 - 1024;
        const int lane = j & 31, nt = (j >> 5) & 3, ks = j >> 7;
        const int g = lane >> 2, tg = lane & 3;
        const int n = 8 * nt + g;
        const int k = 16 * ks + 2 * tg;
        Wf4_g[j] = (ull)bf2(Wh2[k * 32 + n], Wh2[(k + 1) * 32 + n])
                 | ((ull)bf2(Wh2[(k + 8) * 32 + n], Wh2[(k + 9) * 32 + n]) << 32);
    }
}

// ---------------- main fused kernel: all four edge GEMMs on tensor cores
__global__ void __launch_bounds__(256, 4)
egnn_main(const float* __restrict__ f0, const float* __restrict__ f1,
          const int* __restrict__ nbr, const unsigned char* __restrict__ msk,
          const float* __restrict__ rdist,
          const float* __restrict__ be2, const float* __restrict__ bh1,
          const float* __restrict__ bh2,
          const float* __restrict__ Wn1, const float* __restrict__ bn1,
          const float* __restrict__ Wn2, const float* __restrict__ bn2,
          const float* __restrict__ Wg,  const float* __restrict__ bg,
          const float* __restrict__ lng, const float* __restrict__ lnb,
          const float* __restrict__ hns, const float* __restrict__ hnb,
          float* __restrict__ out)
{
    extern __shared__ float sm[];
    unsigned* A    = (unsigned*)sm;            // 2816 u32 staging
    unsigned* H1u  = A + 2816;                 // [32 e][172] u32; aliased by G1u
    float*    EIcT = (float*)(H1u + 5504);     // [32 d][36]
    unsigned* EIbP = (unsigned*)(EIcT + 1152); // [32 e][28] edge_in col-pairs (24 used)
    float*    PI   = (float*)(EIbP + 896);     // [324]
    unsigned* MSbP = (unsigned*)(PI + 324);    // [32 e][20]
    float*    WST  = (float*)(MSbP + 640);     // [32 d][36]
    float*    HT2  = WST + 1152;               // [192]
    float*    nodes_s = HT2 + 192;             // [64]
    float*    f1i_s   = nodes_s + 64;          // [96]
    float*    MI   = f1i_s + 96;               // [32]
    float*    NI   = MI + 32;                  // [96]
    float*    N1s  = NI + 96;                  // [128]
    float*    nouts= N1s + 128;                // [64]
    float*    gates= nouts + 64;               // [32]
    float*    maskv= gates + 32;               // [32]
    float*    stats= maskv + 32;               // [2]
    int*      nbr_s= (int*)(stats + 2);        // [32]
    float*    rdist_s = (float*)(nbr_s + 32);  // [32]
    unsigned* G1u  = H1u;
    const uint2* Au2 = (const uint2*)A;
    const ull*   Aull = (const ull*)A;

    const int tid  = threadIdx.x;
    const int lane = tid & 31;
    const int wrow = tid >> 5;
    const int g    = lane >> 2;
    const int tg   = lane & 3;
    const int node = blockIdx.x;
    const int bbase = (node / Nn) * Nn;

    // ---- P0: loads + H1 zero-pads + Wf1 chunk-0 stage ----
    if (tid < 64)           nodes_s[tid]    = f0[(size_t)node * 64 + tid];
    else if (tid < 160)     f1i_s[tid - 64] = f1[(size_t)node * 96 + (tid - 64)];
    if (tid < 32)           nbr_s[tid] = nbr[node * Kk + tid];
    else if (tid < 64)      maskv[tid - 32] = (float)msk[node * Kk + tid - 32];
    else if (tid < 96)      rdist_s[tid - 64] = rdist[node * Kk + tid - 64];
    for (int c = tid; c < 324; c += 256)
        PI[c] = (c < E2C) ? PI_g[(size_t)node * E2C + c] : 0.f;
    if (tid < 224) H1u[(tid / 7) * 172 + 161 + (tid % 7)] = 0u;
    for (int i = tid; i < 672; i += 256)
        ((uint4*)A)[i] = __ldg((const uint4*)Wf1_g + i);
    __syncthreads();

    // ---- P1: rel_norm -> EIcT + LN stats ----
    #pragma unroll
    for (int i = 0; i < 4; i++) {
        const int e = wrow + 8 * i;
        const float* f1j = f1 + (size_t)(bbase + nbr_s[e]) * 96;
        const float r0 = f1i_s[lane * 3 + 0] - f1j[lane * 3 + 0];
        const float r1 = f1i_s[lane * 3 + 1] - f1j[lane * 3 + 1];
        const float r2 = f1i_s[lane * 3 + 2] - f1j[lane * 3 + 2];
        EIcT[lane * 36 + e] = sqrtf(r0 * r0 + r1 * r1 + r2 * r2);
    }
    if (wrow == 7) {
        float x0 = nodes_s[lane], x1 = nodes_s[lane + 32];
        float s = x0 + x1, ss = x0 * x0 + x1 * x1;
        #pragma unroll
        for (int o = 16; o > 0; o >>= 1) {
            s  += __shfl_down_sync(0xffffffffu, s,  o);
            ss += __shfl_down_sync(0xffffffffu, ss, o);
        }
        if (lane == 0) {
            const float mu  = s * (1.f / 64.f);
            const float var = ss * (1.f / 64.f) - mu * mu;
            stats[0] = mu;
            stats[1] = rsqrtf(var + 1e-5f);
        }
    }
    __syncthreads();

    // ---- P1b: pack edge_in pairs into EIbP (stride 28, conflict-free for frags) ----
    for (int idx = tid; idx < 768; idx += 256) {
        const int e = idx / 24, kp = idx - 24 * (idx / 24);
        unsigned v;
        if (kp < 16)       v = bf2(EIcT[(2 * kp) * 36 + e], EIcT[(2 * kp + 1) * 36 + e]);
        else if (kp == 16) v = bf2(rdist_s[e], 0.f);
        else               v = 0u;
        EIbP[e * 28 + kp] = v;
    }
    __syncthreads();

    // ---- GEMM1 (tensor): M=32, N=336(pad), K=48(pad); 3 staged chunks of 14 n-tiles ----
    #pragma unroll
    for (int c = 0; c < 3; c++) {
        if (c > 0) {
            __syncthreads();
            for (int i = tid; i < 672; i += 256)
                ((uint4*)A)[i] = __ldg((const uint4*)Wf1_g + c * 672 + i);
            __syncthreads();
        }
        #pragma unroll
        for (int tt = 0; tt < 4; tt++) {
            const int t = wrow + 8 * tt;
            if (t < 28) {
                const int ntl = t >> 1, mt = t & 1;
                const int nt = 14 * c + ntl;
                const int e0 = 16 * mt + g;
                float d0 = 0.f, d1 = 0.f, d2 = 0.f, d3 = 0.f;
                #pragma unroll
                for (int ks = 0; ks < 3; ks++) {
                    const unsigned a0 = EIbP[e0 * 28 + 8 * ks + tg];
                    const unsigned a1 = EIbP[(e0 + 8) * 28 + 8 * ks + tg];
                    const unsigned a2 = EIbP[e0 * 28 + 8 * ks + 4 + tg];
                    const unsigned a3 = EIbP[(e0 + 8) * 28 + 8 * ks + 4 + tg];
                    const ull b = Aull[(ks * 14 + ntl) * 32 + lane];
                    mma16816(d0, d1, d2, d3, a0, a1, a2, a3, (unsigned)b, (unsigned)(b >> 32));
                }
                const int p = 4 * nt + tg;
                if (p < 161) {
                    const float2 pi2 = *(const float2*)&PI[2 * p];
                    const float2 pjA = __ldg((const float2*)(PJ_g + (size_t)(bbase + nbr_s[e0]) * E2C + 2 * p));
                    const float2 pjB = __ldg((const float2*)(PJ_g + (size_t)(bbase + nbr_s[e0 + 8]) * E2C + 2 * p));
                    H1u[e0 * 172 + p]       = bf2(siluf(d0 + pi2.x + pjA.x), siluf(d1 + pi2.y + pjA.y));
                    H1u[(e0 + 8) * 172 + p] = bf2(siluf(d2 + pi2.x + pjB.x), siluf(d3 + pi2.y + pjB.y));
                }
            }
        }
    }
    __syncthreads();

    // ---- stage Wf2 chunk A (ks 0..10) ----
    for (int i = tid; i < 704; i += 256)
        ((uint4*)A)[i] = __ldg((const uint4*)Wf2_g + i);
    __syncthreads();

    // ---- GEMM2 (tensor): 8 warp-tiles m16n8, K=336, 2 staged chunks ----
    {
        const int mt = wrow & 1, nt = wrow >> 1;
        const int e0 = 16 * mt + g;
        float d0 = 0.f, d1 = 0.f, d2 = 0.f, d3 = 0.f;
        #pragma unroll
        for (int ks = 0; ks < 11; ks++) {
            const unsigned a0 = H1u[e0 * 172 + 8 * ks + tg];
            const unsigned a1 = H1u[(e0 + 8) * 172 + 8 * ks + tg];
            const unsigned a2 = H1u[e0 * 172 + 8 * ks + 4 + tg];
            const unsigned a3 = H1u[(e0 + 8) * 172 + 8 * ks + 4 + tg];
            const uint2 b = Au2[(ks * 4 + nt) * 32 + lane];
            mma16816(d0, d1, d2, d3, a0, a1, a2, a3, b.x, b.y);
        }
        __syncthreads();
        for (int i = tid; i < 640; i += 256)
            ((uint4*)A)[i] = __ldg((const uint4*)Wf2_g + 704 + i);
        __syncthreads();
        #pragma unroll
        for (int ks = 11; ks < 21; ks++) {
            const unsigned a0 = H1u[e0 * 172 + 8 * ks + tg];
            const unsigned a1 = H1u[(e0 + 8) * 172 + 8 * ks + tg];
            const unsigned a2 = H1u[e0 * 172 + 8 * ks + 4 + tg];
            const unsigned a3 = H1u[(e0 + 8) * 172 + 8 * ks + 4 + tg];
            const uint2 b = Au2[((ks - 11) * 4 + nt) * 32 + lane];
            mma16816(d0, d1, d2, d3, a0, a1, a2, a3, b.x, b.y);
        }
        const int col0 = 8 * nt + 2 * tg;
        const float b0 = be2[col0], b1 = be2[col0 + 1];
        MSbP[e0 * 20 + 4 * nt + tg]       = bf2(siluf(d0 + b0), siluf(d1 + b1));
        MSbP[(e0 + 8) * 20 + 4 * nt + tg] = bf2(siluf(d2 + b0), siluf(d3 + b1));
    }
    __syncthreads();

    // ---- stage Wf3 (warps 0-6) + MI (warp 7) ----
    if (wrow < 7) {
        for (int i = tid; i < 512; i += 224)
            ((uint4*)A)[i] = __ldg((const uint4*)Wf3_g + i);
    } else {
        float s = 0.f;
        #pragma unroll 8
        for (int e = 0; e < 32; e++) {
            const unsigned u = MSbP[e * 20 + (lane >> 1)];
            s += maskv[e] * ((lane & 1) ? bhi(u) : blo(u));
        }
        MI[lane] = s;
    }
    __syncthreads();

    // ---- GEMM3 (tensor): 32 tiles, 4 per warp, K=32 ----
    {
        const int mt = wrow & 1, nt0 = wrow >> 1;
        const int e0 = 16 * mt + g;
        float d[4][4];
        #pragma unroll
        for (int t = 0; t < 4; t++)
            #pragma unroll
            for (int q = 0; q < 4; q++) d[t][q] = 0.f;
        #pragma unroll
        for (int ks = 0; ks < 2; ks++) {
            const unsigned a0 = MSbP[e0 * 20 + 8 * ks + tg];
            const unsigned a1 = MSbP[(e0 + 8) * 20 + 8 * ks + tg];
            const unsigned a2 = MSbP[e0 * 20 + 8 * ks + 4 + tg];
            const unsigned a3 = MSbP[(e0 + 8) * 20 + 8 * ks + 4 + tg];
            #pragma unroll
            for (int t = 0; t < 4; t++) {
                const int nt = nt0 + 4 * t;
                const uint2 b = Au2[(ks * 16 + nt) * 32 + lane];
                mma16816(d[t][0], d[t][1], d[t][2], d[t][3], a0, a1, a2, a3, b.x, b.y);
            }
        }
        __syncthreads();
        #pragma unroll
        for (int t = 0; t < 4; t++) {
            const int nt = nt0 + 4 * t;
            const int col0 = 8 * nt + 2 * tg;
            const float b0 = bh1[col0], b1 = bh1[col0 + 1];
            G1u[e0 * 68 + 4 * nt + tg]       = bf2(siluf(d[t][0] + b0), siluf(d[t][1] + b1));
            G1u[(e0 + 8) * 68 + 4 * nt + tg] = bf2(siluf(d[t][2] + b0), siluf(d[t][3] + b1));
        }
        for (int i = tid; i < 512; i += 256)
            ((uint4*)A)[i] = __ldg((const uint4*)Wf4_g + i);
    }
    __syncthreads();

    // ---- GEMM4 (tensor): 8 tiles, 1 per warp, K=128 ----
    {
        const int mt = wrow & 1, nt = wrow >> 1;
        const int e0 = 16 * mt + g;
        float d0 = 0.f, d1 = 0.f, d2 = 0.f, d3 = 0.f;
        #pragma unroll
        for (int ks = 0; ks < 8; ks++) {
            const unsigned a0 = G1u[e0 * 68 + 8 * ks + tg];
            const unsigned a1 = G1u[(e0 + 8) * 68 + 8 * ks + tg];
            const unsigned a2 = G1u[e0 * 68 + 8 * ks + 4 + tg];
            const unsigned a3 = G1u[(e0 + 8) * 68 + 8 * ks + 4 + tg];
            const uint2 b = Au2[(ks * 4 + nt) * 32 + lane];
            mma16816(d0, d1, d2, d3, a0, a1, a2, a3, b.x, b.y);
        }
        const int col0 = 8 * nt + 2 * tg;
        WST[col0 * 36 + e0]           = d0 + bh2[col0];
        WST[(col0 + 1) * 36 + e0]     = d1 + bh2[col0 + 1];
        WST[col0 * 36 + e0 + 8]       = d2 + bh2[col0];
        WST[(col0 + 1) * 36 + e0 + 8] = d3 + bh2[col0 + 1];
    }
    __syncthreads();

    // ---- htype (warps 0-5) + NI prep (warps 6-7) ----
    if (tid < 192) {
        const int half = (tid >= 96);
        const int t = tid - 96 * half;
        const int d = t / 3;
        const float hs = hns[d], hb = hnb[d];
        const float fi = f1i_s[t];
        const int e0 = half * 16;
        float s = 0.f;
        #pragma unroll
        for (int e4 = 0; e4 < 4; e4++) {
            const float4 nrm4 = *(const float4*)&EIcT[d * 36 + e0 + 4 * e4];
            const float4 w4   = *(const float4*)&WST[d * 36 + e0 + 4 * e4];
            #pragma unroll
            for (int m = 0; m < 4; m++) {
                const int e = e0 + 4 * e4 + m;
                const float nrm = (m == 0) ? nrm4.x : (m == 1) ? nrm4.y : (m == 2) ? nrm4.z : nrm4.w;
                const float wv  = (m == 0) ? w4.x   : (m == 1) ? w4.y   : (m == 2) ? w4.z   : w4.w;
                const float coef = __fdividef(nrm * hs + hb, fmaxf(nrm, 1e-8f));
                const float relv = fi - __ldg(&f1[(size_t)(bbase + nbr_s[e]) * 96 + t]);
                s += relv * coef * wv;
            }
        }
        HT2[tid] = s;
    } else if (tid < 256) {
        const int c = tid - 192;
        NI[c] = (nodes_s[c] - stats[0]) * stats[1] * lng[c] + lnb[c];
        if (c < 32) NI[64 + c] = MI[c];
    }
    __syncthreads();

    // ---- N1[128] = silu(node_in @ Wn1 + bn1) ----
    if (tid < 128) {
        float a = 0.f;
        #pragma unroll 8
        for (int r = 0; r < 96; r++) a += NI[r] * __ldg(&Wn1[r * 128 + tid]);
        N1s[tid] = siluf(a + bn1[tid]);
    }
    __syncthreads();

    // ---- node_out[64] = N1 @ Wn2 + bn2 + nodes ----
    if (tid < 64) {
        float a = 0.f;
        #pragma unroll 8
        for (int r = 0; r < 128; r++) a += N1s[r] * __ldg(&Wn2[r * 64 + tid]);
        const float v = a + bn2[tid] + nodes_s[tid];
        nouts[tid] = v;
        out[(size_t)node * 64 + tid] = v;
    }
    __syncthreads();

    // ---- gate[32] = sigmoid(node_out @ Wg + bg) ----
    if (tid < 32) {
        float a = 0.f;
        #pragma unroll 8
        for (int r = 0; r < 64; r++) a += nouts[r] * __ldg(&Wg[r * 32 + tid]);
        gates[tid] = sigmf(a + bg[tid]);
    }
    __syncthreads();

    // ---- f1_out ----
    if (tid < 96) {
        const int d = tid / 3;
        const float v = (f1i_s[tid] + HT2[tid] + HT2[96 + tid]) * gates[d];
        out[(size_t)Bb * Nn * D0 + (size_t)node * 96 + tid] = v;
    }
}

extern "C" void kernel_launch(void* const* d_in, const int* in_sizes, int n_in,
                              void* d_out, int out_size) {
    const float* f0   = (const float*)d_in[0];
    const float* f1   = (const float*)d_in[1];
    const int*   nbr  = (const int*)d_in[2];
    const unsigned char* msk = (const unsigned char*)d_in[3];
    const float* rdist= (const float*)d_in[4];
    const float* We1  = (const float*)d_in[5];
    const float* be1  = (const float*)d_in[6];
    const float* We2  = (const float*)d_in[7];
    const float* be2  = (const float*)d_in[8];
    const float* Wh1  = (const float*)d_in[9];
    const float* bh1  = (const float*)d_in[10];
    const float* Wh2  = (const float*)d_in[11];
    const float* bh2  = (const float*)d_in[12];
    const float* Wn1  = (const float*)d_in[13];
    const float* bn1  = (const float*)d_in[14];
    const float* Wn2  = (const float*)d_in[15];
    const float* bn2  = (const float*)d_in[16];
    const float* Wg   = (const float*)d_in[17];
    const float* bg   = (const float*)d_in[18];
    const float* lng  = (const float*)d_in[19];
    const float* lnb  = (const float*)d_in[20];
    const float* hns  = (const float*)d_in[21];
    const float* hnb  = (const float*)d_in[22];
    float* out = (float*)d_out;

    proj_kernel<<<NT / 8, 192>>>(f0, We1, be1);
    prep_frag<<<35, 256>>>(We1, We2, Wh1, Wh2);

    const size_t smem_bytes = 13286 * 4;

    cudaFuncSetAttribute(egnn_main, cudaFuncAttributeMaxDynamicSharedMemorySize,
                         (int)smem_bytes);

    egnn_main<<<NT, 256, smem_bytes>>>(
        f0, f1, nbr, msk, rdist,
        be2, bh1, bh2,
        Wn1, bn1, Wn2, bn2, Wg, bg, lng, lnb, hns, hnb, out);
}

// round 14
// speedup vs baseline: 2.1200x; 1.1549x over previous
#include <cuda_runtime.h>
#include <math.h>

#define Bb 2
#define Nn 4096
#define NT (Bb*Nn)
#define Kk 32
#define D0 64
#define E2C 322

typedef unsigned long long ull;

__device__ float PI_g[(size_t)NT * E2C + 384];
__device__ float PJ_g[(size_t)NT * E2C + 384];
__device__ __align__(16) ull Wf1_g[4032];   // We1-tail frags: [nt 0..41][ks 0..2][32]
__device__ __align__(16) ull Wf2_g[2688];   // We2 frags: [ks 0..20][nt 0..3][32]
__device__ __align__(16) ull Wf3_g[1024];   // Wh1 frags: [ks 0..1][nt 0..15][32]
__device__ __align__(16) ull Wf4_g[1024];   // Wh2 frags: [ks 0..7][nt 0..3][32]

__device__ __forceinline__ float siluf(float x) { return x / (1.f + __expf(-x)); }
__device__ __forceinline__ float sigmf(float x) { return 1.f / (1.f + __expf(-x)); }
__device__ __forceinline__ unsigned bf2(float lo, float hi) {
    unsigned r; asm("cvt.rn.bf16x2.f32 %0, %1, %2;" : "=r"(r) : "f"(hi), "f"(lo)); return r;
}
__device__ __forceinline__ float blo(unsigned u) { return __uint_as_float(u << 16); }
__device__ __forceinline__ float bhi(unsigned u) { return __uint_as_float(u & 0xffff0000u); }
__device__ __forceinline__ ull pk2(float lo, float hi) {
    ull r; asm("mov.b64 %0, {%1, %2};" : "=l"(r) : "f"(lo), "f"(hi)); return r;
}
__device__ __forceinline__ void up2(ull v, float& lo, float& hi) {
    asm("mov.b64 {%0, %1}, %2;" : "=f"(lo), "=f"(hi) : "l"(v));
}
__device__ __forceinline__ ull ffma2(ull a, ull b, ull c) {
    ull d; asm("fma.rn.f32x2 %0, %1, %2, %3;" : "=l"(d) : "l"(a), "l"(b), "l"(c)); return d;
}
__device__ __forceinline__ void mma16816(float& d0, float& d1, float& d2, float& d3,
    unsigned a0, unsigned a1, unsigned a2, unsigned a3, unsigned b0, unsigned b1)
{
    asm("mma.sync.aligned.m16n8k16.row.col.f32.bf16.bf16.f32 "
        "{%0,%1,%2,%3}, {%4,%5,%6,%7}, {%8,%9}, {%0,%1,%2,%3};"
        : "+f"(d0), "+f"(d1), "+f"(d2), "+f"(d3)
        : "r"(a0), "r"(a1), "r"(a2), "r"(a3), "r"(b0), "r"(b1));
}

// ---------------- per-node projections: PI/PJ split across thread halves
__global__ void __launch_bounds__(384)
proj_kernel(const float* __restrict__ f0, const float* __restrict__ We1,
            const float* __restrict__ be1)
{
    __shared__ ull ndu[8][64];
    const int nb = blockIdx.x * 8;
    const int tid = threadIdx.x;
    for (int idx = tid; idx < 512; idx += 384) {
        const float v = f0[(size_t)nb * 64 + idx];
        ndu[idx >> 6][idx & 63] = pk2(v, v);
    }
    __syncthreads();
    const int half = (tid >= 192);
    const int p = tid - 192 * half;
    if (p < 161) {
        ull s[8];
        #pragma unroll
        for (int n = 0; n < 8; n++) s[n] = 0ull;
        const float* W = We1 + (size_t)(64 * half) * E2C + 2 * p;
        #pragma unroll 4
        for (int d = 0; d < 64; d++) {
            const float2 w = __ldg((const float2*)(W + (size_t)d * E2C));
            const ull wu = pk2(w.x, w.y);
            #pragma unroll
            for (int n = 0; n < 8; n++) s[n] = ffma2(ndu[n][d], wu, s[n]);
        }
        if (half == 0) {
            const float2 b = *(const float2*)&be1[2 * p];
            #pragma unroll
            for (int n = 0; n < 8; n++) {
                float a0, a1; up2(s[n], a0, a1);
                *(float2*)&PI_g[(size_t)(nb + n) * E2C + 2 * p] = make_float2(a0 + b.x, a1 + b.y);
            }
        } else {
            #pragma unroll
            for (int n = 0; n < 8; n++) {
                float a0, a1; up2(s[n], a0, a1);
                *(float2*)&PJ_g[(size_t)(nb + n) * E2C + 2 * p] = make_float2(a0, a1);
            }
        }
    }
}

// ---------------- pre-pack B fragments
__global__ void __launch_bounds__(256)
prep_frag(const float* __restrict__ We1, const float* __restrict__ We2,
          const float* __restrict__ Wh1, const float* __restrict__ Wh2)
{
    const int idx = blockIdx.x * 256 + threadIdx.x;
    if (idx < 4032) {                       // Wf1: [nt][ks][lane]
        const int lane = idx & 31;
        const int j = idx >> 5;
        const int ks = j % 3, nt = j / 3;
        const int g = lane >> 2, tg = lane & 3;
        const int n = 8 * nt + g;
        const int k = 16 * ks + 2 * tg;
        float w00 = 0.f, w01 = 0.f, w10 = 0.f, w11 = 0.f;
        if (n < E2C) {
            if (k     < 33) w00 = We1[(size_t)(128 + k)     * E2C + n];
            if (k + 1 < 33) w01 = We1[(size_t)(128 + k + 1) * E2C + n];
            if (k + 8 < 33) w10 = We1[(size_t)(128 + k + 8) * E2C + n];
            if (k + 9 < 33) w11 = We1[(size_t)(128 + k + 9) * E2C + n];
        }
        Wf1_g[idx] = (ull)bf2(w00, w01) | ((ull)bf2(w10, w11) << 32);
    } else if (idx < 4032 + 2688) {         // Wf2
        const int j = idx - 4032;
        const int lane = j & 31, nt = (j >> 5) & 3, ks = j >> 7;
        const int g = lane >> 2, tg = lane & 3;
        const int n = 8 * nt + g;
        const int k = 16 * ks + 2 * tg;
        const float w00 = (k     < E2C) ? We2[k * 32 + n]       : 0.f;
        const float w01 = (k + 1 < E2C) ? We2[(k + 1) * 32 + n] : 0.f;
        const float w10 = (k + 8 < E2C) ? We2[(k + 8) * 32 + n] : 0.f;
        const float w11 = (k + 9 < E2C) ? We2[(k + 9) * 32 + n] : 0.f;
        Wf2_g[j] = (ull)bf2(w00, w01) | ((ull)bf2(w10, w11) << 32);
    } else if (idx < 4032 + 2688 + 1024) {  // Wf3
        const int j = idx - 4032 - 2688;
        const int lane = j & 31, nt = (j >> 5) & 15, ks = j >> 9;
        const int g = lane >> 2, tg = lane & 3;
        const int n = 8 * nt + g;
        const int k = 16 * ks + 2 * tg;
        Wf3_g[j] = (ull)bf2(Wh1[k * 128 + n], Wh1[(k + 1) * 128 + n])
                 | ((ull)bf2(Wh1[(k + 8) * 128 + n], Wh1[(k + 9) * 128 + n]) << 32);
    } else if (idx < 4032 + 2688 + 2048) {  // Wf4
        const int j = idx - 4032 - 2688 - 1024;
        const int lane = j & 31, nt = (j >> 5) & 3, ks = j >> 7;
        const int g = lane >> 2, tg = lane & 3;
        const int n = 8 * nt + g;
        const int k = 16 * ks + 2 * tg;
        Wf4_g[j] = (ull)bf2(Wh2[k * 32 + n], Wh2[(k + 1) * 32 + n])
                 | ((ull)bf2(Wh2[(k + 8) * 32 + n], Wh2[(k + 9) * 32 + n]) << 32);
    }
}

// ---------------- main fused kernel: tensor GEMMs with direct-LDG B fragments
__global__ void __launch_bounds__(256, 4)
egnn_main(const float* __restrict__ f0, const float* __restrict__ f1,
          const int* __restrict__ nbr, const unsigned char* __restrict__ msk,
          const float* __restrict__ rdist,
          const float* __restrict__ be2, const float* __restrict__ bh1,
          const float* __restrict__ bh2,
          const float* __restrict__ Wn1, const float* __restrict__ bn1,
          const float* __restrict__ Wn2, const float* __restrict__ bn2,
          const float* __restrict__ Wg,  const float* __restrict__ bg,
          const float* __restrict__ lng, const float* __restrict__ lnb,
          const float* __restrict__ hns, const float* __restrict__ hnb,
          float* __restrict__ out)
{
    extern __shared__ float sm[];
    unsigned* H1u  = (unsigned*)sm;            // [32 e][172] u32; aliased by G1u
    float*    EIcT = (float*)(H1u + 5504);     // [32 d][36]
    unsigned* EIbP = (unsigned*)(EIcT + 1152); // [32 e][28]
    float*    PI   = (float*)(EIbP + 896);     // [324]
    unsigned* MSbP = (unsigned*)(PI + 324);    // [32 e][20]
    float*    WST  = (float*)(MSbP + 640);     // [32 d][36]
    float*    HT2  = WST + 1152;               // [192]
    float*    nodes_s = HT2 + 192;             // [64]
    float*    f1i_s   = nodes_s + 64;          // [96]
    float*    NI   = f1i_s + 96;               // [96]
    float*    N1s  = NI + 96;                  // [128]
    float*    nouts= N1s + 128;                // [64]
    float*    gates= nouts + 64;               // [32]
    float*    maskv= gates + 32;               // [32]
    float*    stats= maskv + 32;               // [2]
    int*      nbr_s= (int*)(stats + 2);        // [32]
    float*    rdist_s = (float*)(nbr_s + 32);  // [32]
    unsigned* G1u  = H1u;

    const int tid  = threadIdx.x;
    const int lane = tid & 31;
    const int wrow = tid >> 5;
    const int g    = lane >> 2;
    const int tg   = lane & 3;
    const int node = blockIdx.x;
    const int bbase = (node / Nn) * Nn;

    // ---- P0 ----
    if (tid < 64)           nodes_s[tid]    = f0[(size_t)node * 64 + tid];
    else if (tid < 160)     f1i_s[tid - 64] = f1[(size_t)node * 96 + (tid - 64)];
    if (tid < 32)           nbr_s[tid] = nbr[node * Kk + tid];
    else if (tid < 64)      maskv[tid - 32] = (float)msk[node * Kk + tid - 32];
    else if (tid < 96)      rdist_s[tid - 64] = rdist[node * Kk + tid - 64];
    for (int c = tid; c < 324; c += 256)
        PI[c] = (c < E2C) ? PI_g[(size_t)node * E2C + c] : 0.f;
    if (tid < 224) H1u[(tid / 7) * 172 + 161 + (tid % 7)] = 0u;
    __syncthreads();

    // ---- P1: rel_norm -> EIcT + LN stats ----
    #pragma unroll
    for (int i = 0; i < 4; i++) {
        const int e = wrow + 8 * i;
        const float* f1j = f1 + (size_t)(bbase + nbr_s[e]) * 96;
        const float r0 = f1i_s[lane * 3 + 0] - f1j[lane * 3 + 0];
        const float r1 = f1i_s[lane * 3 + 1] - f1j[lane * 3 + 1];
        const float r2 = f1i_s[lane * 3 + 2] - f1j[lane * 3 + 2];
        EIcT[lane * 36 + e] = sqrtf(r0 * r0 + r1 * r1 + r2 * r2);
    }
    if (wrow == 7) {
        float x0 = nodes_s[lane], x1 = nodes_s[lane + 32];
        float s = x0 + x1, ss = x0 * x0 + x1 * x1;
        #pragma unroll
        for (int o = 16; o > 0; o >>= 1) {
            s  += __shfl_down_sync(0xffffffffu, s,  o);
            ss += __shfl_down_sync(0xffffffffu, ss, o);
        }
        if (lane == 0) {
            const float mu  = s * (1.f / 64.f);
            const float var = ss * (1.f / 64.f) - mu * mu;
            stats[0] = mu;
            stats[1] = rsqrtf(var + 1e-5f);
        }
    }
    __syncthreads();

    // ---- P1b: pack edge_in pairs into EIbP ----
    for (int idx = tid; idx < 768; idx += 256) {
        const int e = idx / 24, kp = idx - 24 * (idx / 24);
        unsigned v;
        if (kp < 16)       v = bf2(EIcT[(2 * kp) * 36 + e], EIcT[(2 * kp + 1) * 36 + e]);
        else if (kp == 16) v = bf2(rdist_s[e], 0.f);
        else               v = 0u;
        EIbP[e * 28 + kp] = v;
    }
    __syncthreads();

    // ---- GEMM1 (tensor): 84 tiles, ~11 per warp, b-frags direct from L2 ----
    #pragma unroll
    for (int tt = 0; tt < 11; tt++) {
        const int t = wrow + 8 * tt;
        if (t < 84) {
            const int mt = t & 1, nt = t >> 1;
            const int e0 = 16 * mt + g;
            float d0 = 0.f, d1 = 0.f, d2 = 0.f, d3 = 0.f;
            #pragma unroll
            for (int ks = 0; ks < 3; ks++) {
                const unsigned a0 = EIbP[e0 * 28 + 8 * ks + tg];
                const unsigned a1 = EIbP[(e0 + 8) * 28 + 8 * ks + tg];
                const unsigned a2 = EIbP[e0 * 28 + 8 * ks + 4 + tg];
                const unsigned a3 = EIbP[(e0 + 8) * 28 + 8 * ks + 4 + tg];
                const ull b = __ldg(&Wf1_g[(nt * 3 + ks) * 32 + lane]);
                mma16816(d0, d1, d2, d3, a0, a1, a2, a3, (unsigned)b, (unsigned)(b >> 32));
            }
            const int p = 4 * nt + tg;
            if (p < 161) {
                const float2 pi2 = *(const float2*)&PI[2 * p];
                const float2 pjA = __ldg((const float2*)(PJ_g + (size_t)(bbase + nbr_s[e0]) * E2C + 2 * p));
                const float2 pjB = __ldg((const float2*)(PJ_g + (size_t)(bbase + nbr_s[e0 + 8]) * E2C + 2 * p));
                H1u[e0 * 172 + p]       = bf2(siluf(d0 + pi2.x + pjA.x), siluf(d1 + pi2.y + pjA.y));
                H1u[(e0 + 8) * 172 + p] = bf2(siluf(d2 + pi2.x + pjB.x), siluf(d3 + pi2.y + pjB.y));
            }
        }
    }
    __syncthreads();

    // ---- GEMM2 (tensor): K=336, b-frags direct ----
    {
        const int mt = wrow & 1, nt = wrow >> 1;
        const int e0 = 16 * mt + g;
        float d0 = 0.f, d1 = 0.f, d2 = 0.f, d3 = 0.f;
        #pragma unroll
        for (int ks = 0; ks < 21; ks++) {
            const unsigned a0 = H1u[e0 * 172 + 8 * ks + tg];
            const unsigned a1 = H1u[(e0 + 8) * 172 + 8 * ks + tg];
            const unsigned a2 = H1u[e0 * 172 + 8 * ks + 4 + tg];
            const unsigned a3 = H1u[(e0 + 8) * 172 + 8 * ks + 4 + tg];
            const ull b = __ldg(&Wf2_g[(ks * 4 + nt) * 32 + lane]);
            mma16816(d0, d1, d2, d3, a0, a1, a2, a3, (unsigned)b, (unsigned)(b >> 32));
        }
        const int col0 = 8 * nt + 2 * tg;
        const float b0 = be2[col0], b1 = be2[col0 + 1];
        MSbP[e0 * 20 + 4 * nt + tg]       = bf2(siluf(d0 + b0), siluf(d1 + b1));
        MSbP[(e0 + 8) * 20 + 4 * nt + tg] = bf2(siluf(d2 + b0), siluf(d3 + b1));
    }
    __syncthreads();

    // ---- GEMM3 (tensor): 32 tiles, b-frags direct; writes G1u (aliases H1u, safe) ----
    {
        const int mt = wrow & 1, nt0 = wrow >> 1;
        const int e0 = 16 * mt + g;
        float d[4][4];
        #pragma unroll
        for (int t = 0; t < 4; t++)
            #pragma unroll
            for (int q = 0; q < 4; q++) d[t][q] = 0.f;
        #pragma unroll
        for (int ks = 0; ks < 2; ks++) {
            const unsigned a0 = MSbP[e0 * 20 + 8 * ks + tg];
            const unsigned a1 = MSbP[(e0 + 8) * 20 + 8 * ks + tg];
            const unsigned a2 = MSbP[e0 * 20 + 8 * ks + 4 + tg];
            const unsigned a3 = MSbP[(e0 + 8) * 20 + 8 * ks + 4 + tg];
            #pragma unroll
            for (int t = 0; t < 4; t++) {
                const int nt = nt0 + 4 * t;
                const ull b = __ldg(&Wf3_g[(ks * 16 + nt) * 32 + lane]);
                mma16816(d[t][0], d[t][1], d[t][2], d[t][3], a0, a1, a2, a3,
                         (unsigned)b, (unsigned)(b >> 32));
            }
        }
        #pragma unroll
        for (int t = 0; t < 4; t++) {
            const int nt = nt0 + 4 * t;
            const int col0 = 8 * nt + 2 * tg;
            const float b0 = bh1[col0], b1 = bh1[col0 + 1];
            G1u[e0 * 68 + 4 * nt + tg]       = bf2(siluf(d[t][0] + b0), siluf(d[t][1] + b1));
            G1u[(e0 + 8) * 68 + 4 * nt + tg] = bf2(siluf(d[t][2] + b0), siluf(d[t][3] + b1));
        }
    }
    __syncthreads();

    // ---- GEMM4 (tensor): K=128, b-frags direct ----
    {
        const int mt = wrow & 1, nt = wrow >> 1;
        const int e0 = 16 * mt + g;
        float d0 = 0.f, d1 = 0.f, d2 = 0.f, d3 = 0.f;
        #pragma unroll
        for (int ks = 0; ks < 8; ks++) {
            const unsigned a0 = G1u[e0 * 68 + 8 * ks + tg];
            const unsigned a1 = G1u[(e0 + 8) * 68 + 8 * ks + tg];
            const unsigned a2 = G1u[e0 * 68 + 8 * ks + 4 + tg];
            const unsigned a3 = G1u[(e0 + 8) * 68 + 8 * ks + 4 + tg];
            const ull b = __ldg(&Wf4_g[(ks * 4 + nt) * 32 + lane]);
            mma16816(d0, d1, d2, d3, a0, a1, a2, a3, (unsigned)b, (unsigned)(b >> 32));
        }
        const int col0 = 8 * nt + 2 * tg;
        WST[col0 * 36 + e0]           = d0 + bh2[col0];
        WST[(col0 + 1) * 36 + e0]     = d1 + bh2[col0 + 1];
        WST[col0 * 36 + e0 + 8]       = d2 + bh2[col0];
        WST[(col0 + 1) * 36 + e0 + 8] = d3 + bh2[col0 + 1];
    }
    __syncthreads();

    // ---- htype (warps 0-5) + NI prep incl. inline MI (warps 6-7) ----
    if (tid < 192) {
        const int half = (tid >= 96);
        const int t = tid - 96 * half;
        const int d = t / 3;
        const float hs = hns[d], hb = hnb[d];
        const float fi = f1i_s[t];
        const int e0 = half * 16;
        float s = 0.f;
        #pragma unroll
        for (int e4 = 0; e4 < 4; e4++) {
            const float4 nrm4 = *(const float4*)&EIcT[d * 36 + e0 + 4 * e4];
            const float4 w4   = *(const float4*)&WST[d * 36 + e0 + 4 * e4];
            #pragma unroll
            for (int m = 0; m < 4; m++) {
                const int e = e0 + 4 * e4 + m;
                const float nrm = (m == 0) ? nrm4.x : (m == 1) ? nrm4.y : (m == 2) ? nrm4.z : nrm4.w;
                const float wv  = (m == 0) ? w4.x   : (m == 1) ? w4.y   : (m == 2) ? w4.z   : w4.w;
                const float coef = __fdividef(nrm * hs + hb, fmaxf(nrm, 1e-8f));
                const float relv = fi - __ldg(&f1[(size_t)(bbase + nbr_s[e]) * 96 + t]);
                s += relv * coef * wv;
            }
        }
        HT2[tid] = s;
    } else if (tid < 256) {
        const int c = tid - 192;
        NI[c] = (nodes_s[c] - stats[0]) * stats[1] * lng[c] + lnb[c];
        if (c < 32) {
            float s = 0.f;
            #pragma unroll 8
            for (int e = 0; e < 32; e++) {
                const unsigned u = MSbP[e * 20 + (c >> 1)];
                s += maskv[e] * ((c & 1) ? bhi(u) : blo(u));
            }
            NI[64 + c] = s;
        }
    }
    __syncthreads();

    // ---- N1[128] = silu(node_in @ Wn1 + bn1) ----
    if (tid < 128) {
        float a = 0.f;
        #pragma unroll 8
        for (int r = 0; r < 96; r++) a += NI[r] * __ldg(&Wn1[r * 128 + tid]);
        N1s[tid] = siluf(a + bn1[tid]);
    }
    __syncthreads();

    // ---- node_out[64] = N1 @ Wn2 + bn2 + nodes ----
    if (tid < 64) {
        float a = 0.f;
        #pragma unroll 8
        for (int r = 0; r < 128; r++) a += N1s[r] * __ldg(&Wn2[r * 64 + tid]);
        const float v = a + bn2[tid] + nodes_s[tid];
        nouts[tid] = v;
        out[(size_t)node * 64 + tid] = v;
    }
    __syncthreads();

    // ---- gate[32] = sigmoid(node_out @ Wg + bg) ----
    if (tid < 32) {
        float a = 0.f;
        #pragma unroll 8
        for (int r = 0; r < 64; r++) a += nouts[r] * __ldg(&Wg[r * 32 + tid]);
        gates[tid] = sigmf(a + bg[tid]);
    }
    __syncthreads();

    // ---- f1_out ----
    if (tid < 96) {
        const int d = tid / 3;
        const float v = (f1i_s[tid] + HT2[tid] + HT2[96 + tid]) * gates[d];
        out[(size_t)Bb * Nn * D0 + (size_t)node * 96 + tid] = v;
    }
}

extern "C" void kernel_launch(void* const* d_in, const int* in_sizes, int n_in,
                              void* d_out, int out_size) {
    const float* f0   = (const float*)d_in[0];
    const float* f1   = (const float*)d_in[1];
    const int*   nbr  = (const int*)d_in[2];
    const unsigned char* msk = (const unsigned char*)d_in[3];
    const float* rdist= (const float*)d_in[4];
    const float* We1  = (const float*)d_in[5];
    const float* be1  = (const float*)d_in[6];
    const float* We2  = (const float*)d_in[7];
    const float* be2  = (const float*)d_in[8];
    const float* Wh1  = (const float*)d_in[9];
    const float* bh1  = (const float*)d_in[10];
    const float* Wh2  = (const float*)d_in[11];
    const float* bh2  = (const float*)d_in[12];
    const float* Wn1  = (const float*)d_in[13];
    const float* bn1  = (const float*)d_in[14];
    const float* Wn2  = (const float*)d_in[15];
    const float* bn2  = (const float*)d_in[16];
    const float* Wg   = (const float*)d_in[17];
    const float* bg   = (const float*)d_in[18];
    const float* lng  = (const float*)d_in[19];
    const float* lnb  = (const float*)d_in[20];
    const float* hns  = (const float*)d_in[21];
    const float* hnb  = (const float*)d_in[22];
    float* out = (float*)d_out;

    proj_kernel<<<NT / 8, 384>>>(f0, We1, be1);
    prep_frag<<<35, 256>>>(We1, We2, Wh1, Wh2);

    const size_t smem_bytes = 10438 * 4;

    cudaFuncSetAttribute(egnn_main, cudaFuncAttributeMaxDynamicSharedMemorySize,
                         (int)smem_bytes);

    egnn_main<<<NT, 256, smem_bytes>>>(
        f0, f1, nbr, msk, rdist,
        be2, bh1, bh2,
        Wn1, bn1, Wn2, bn2, Wg, bg, lng, lnb, hns, hnb, out);
}

// round 15
// speedup vs baseline: 2.3199x; 1.0943x over previous
#include <cuda_runtime.h>
#include <math.h>

#define Bb 2
#define Nn 4096
#define NT (Bb*Nn)
#define Kk 32
#define D0 64
#define E2C 322

typedef unsigned long long ull;

__device__ float PI_g[(size_t)NT * E2C + 384];
__device__ float PJ_g[(size_t)NT * E2C + 384];
__device__ __align__(16) ull Wf1_g[4032];   // We1-tail frags: [nt 0..41][ks 0..2][32]
__device__ __align__(16) ull Wf2_g[2688];   // We2 frags: [ks 0..20][nt 0..3][32]
__device__ __align__(16) ull Wf3_g[1024];   // Wh1 frags: [ks 0..1][nt 0..15][32]
__device__ __align__(16) ull Wf4_g[1024];   // Wh2 frags: [ks 0..7][nt 0..3][32]

__device__ __forceinline__ float siluf(float x) { return x / (1.f + __expf(-x)); }
__device__ __forceinline__ float sigmf(float x) { return 1.f / (1.f + __expf(-x)); }
__device__ __forceinline__ unsigned bf2(float lo, float hi) {
    unsigned r; asm("cvt.rn.bf16x2.f32 %0, %1, %2;" : "=r"(r) : "f"(hi), "f"(lo)); return r;
}
__device__ __forceinline__ float blo(unsigned u) { return __uint_as_float(u << 16); }
__device__ __forceinline__ float bhi(unsigned u) { return __uint_as_float(u & 0xffff0000u); }
__device__ __forceinline__ ull pk2(float lo, float hi) {
    ull r; asm("mov.b64 %0, {%1, %2};" : "=l"(r) : "f"(lo), "f"(hi)); return r;
}
__device__ __forceinline__ void up2(ull v, float& lo, float& hi) {
    asm("mov.b64 {%0, %1}, %2;" : "=f"(lo), "=f"(hi) : "l"(v));
}
__device__ __forceinline__ ull ffma2(ull a, ull b, ull c) {
    ull d; asm("fma.rn.f32x2 %0, %1, %2, %3;" : "=l"(d) : "l"(a), "l"(b), "l"(c)); return d;
}
__device__ __forceinline__ void mma16816(float& d0, float& d1, float& d2, float& d3,
    unsigned a0, unsigned a1, unsigned a2, unsigned a3, unsigned b0, unsigned b1)
{
    asm("mma.sync.aligned.m16n8k16.row.col.f32.bf16.bf16.f32 "
        "{%0,%1,%2,%3}, {%4,%5,%6,%7}, {%8,%9}, {%0,%1,%2,%3};"
        : "+f"(d0), "+f"(d1), "+f"(d2), "+f"(d3)
        : "r"(a0), "r"(a1), "r"(a2), "r"(a3), "r"(b0), "r"(b1));
}

// ---------------- per-node projections: 16 nodes/block, PI/PJ split halves
__global__ void __launch_bounds__(384)
proj_kernel(const float* __restrict__ f0, const float* __restrict__ We1,
            const float* __restrict__ be1)
{
    __shared__ ull ndu[16][64];
    const int nb = blockIdx.x * 16;
    const int tid = threadIdx.x;
    for (int idx = tid; idx < 1024; idx += 384) {
        const float v = f0[(size_t)nb * 64 + idx];
        ndu[idx >> 6][idx & 63] = pk2(v, v);
    }
    __syncthreads();
    const int half = (tid >= 192);
    const int p = tid - 192 * half;
    if (p < 161) {
        ull s[16];
        #pragma unroll
        for (int n = 0; n < 16; n++) s[n] = 0ull;
        const float* W = We1 + (size_t)(64 * half) * E2C + 2 * p;
        #pragma unroll 4
        for (int d = 0; d < 64; d++) {
            const float2 w = __ldg((const float2*)(W + (size_t)d * E2C));
            const ull wu = pk2(w.x, w.y);
            #pragma unroll
            for (int n = 0; n < 16; n++) s[n] = ffma2(ndu[n][d], wu, s[n]);
        }
        if (half == 0) {
            const float2 b = *(const float2*)&be1[2 * p];
            #pragma unroll
            for (int n = 0; n < 16; n++) {
                float a0, a1; up2(s[n], a0, a1);
                *(float2*)&PI_g[(size_t)(nb + n) * E2C + 2 * p] = make_float2(a0 + b.x, a1 + b.y);
            }
        } else {
            #pragma unroll
            for (int n = 0; n < 16; n++) {
                float a0, a1; up2(s[n], a0, a1);
                *(float2*)&PJ_g[(size_t)(nb + n) * E2C + 2 * p] = make_float2(a0, a1);
            }
        }
    }
}

// ---------------- pre-pack B fragments
__global__ void __launch_bounds__(256)
prep_frag(const float* __restrict__ We1, const float* __restrict__ We2,
          const float* __restrict__ Wh1, const float* __restrict__ Wh2)
{
    const int idx = blockIdx.x * 256 + threadIdx.x;
    if (idx < 4032) {                       // Wf1: [nt][ks][lane]
        const int lane = idx & 31;
        const int j = idx >> 5;
        const int ks = j % 3, nt = j / 3;
        const int g = lane >> 2, tg = lane & 3;
        const int n = 8 * nt + g;
        const int k = 16 * ks + 2 * tg;
        float w00 = 0.f, w01 = 0.f, w10 = 0.f, w11 = 0.f;
        if (n < E2C) {
            if (k     < 33) w00 = We1[(size_t)(128 + k)     * E2C + n];
            if (k + 1 < 33) w01 = We1[(size_t)(128 + k + 1) * E2C + n];
            if (k + 8 < 33) w10 = We1[(size_t)(128 + k + 8) * E2C + n];
            if (k + 9 < 33) w11 = We1[(size_t)(128 + k + 9) * E2C + n];
        }
        Wf1_g[idx] = (ull)bf2(w00, w01) | ((ull)bf2(w10, w11) << 32);
    } else if (idx < 4032 + 2688) {         // Wf2
        const int j = idx - 4032;
        const int lane = j & 31, nt = (j >> 5) & 3, ks = j >> 7;
        const int g = lane >> 2, tg = lane & 3;
        const int n = 8 * nt + g;
        const int k = 16 * ks + 2 * tg;
        const float w00 = (k     < E2C) ? We2[k * 32 + n]       : 0.f;
        const float w01 = (k + 1 < E2C) ? We2[(k + 1) * 32 + n] : 0.f;
        const float w10 = (k + 8 < E2C) ? We2[(k + 8) * 32 + n] : 0.f;
        const float w11 = (k + 9 < E2C) ? We2[(k + 9) * 32 + n] : 0.f;
        Wf2_g[j] = (ull)bf2(w00, w01) | ((ull)bf2(w10, w11) << 32);
    } else if (idx < 4032 + 2688 + 1024) {  // Wf3
        const int j = idx - 4032 - 2688;
        const int lane = j & 31, nt = (j >> 5) & 15, ks = j >> 9;
        const int g = lane >> 2, tg = lane & 3;
        const int n = 8 * nt + g;
        const int k = 16 * ks + 2 * tg;
        Wf3_g[j] = (ull)bf2(Wh1[k * 128 + n], Wh1[(k + 1) * 128 + n])
                 | ((ull)bf2(Wh1[(k + 8) * 128 + n], Wh1[(k + 9) * 128 + n]) << 32);
    } else if (idx < 4032 + 2688 + 2048) {  // Wf4
        const int j = idx - 4032 - 2688 - 1024;
        const int lane = j & 31, nt = (j >> 5) & 3, ks = j >> 7;
        const int g = lane >> 2, tg = lane & 3;
        const int n = 8 * nt + g;
        const int k = 16 * ks + 2 * tg;
        Wf4_g[j] = (ull)bf2(Wh2[k * 32 + n], Wh2[(k + 1) * 32 + n])
                 | ((ull)bf2(Wh2[(k + 8) * 32 + n], Wh2[(k + 9) * 32 + n]) << 32);
    }
}

// ---------------- main fused kernel: tensor GEMMs with direct-LDG B fragments
__global__ void __launch_bounds__(256, 5)
egnn_main(const float* __restrict__ f0, const float* __restrict__ f1,
          const int* __restrict__ nbr, const unsigned char* __restrict__ msk,
          const float* __restrict__ rdist,
          const float* __restrict__ be2, const float* __restrict__ bh1,
          const float* __restrict__ bh2,
          const float* __restrict__ Wn1, const float* __restrict__ bn1,
          const float* __restrict__ Wn2, const float* __restrict__ bn2,
          const float* __restrict__ Wg,  const float* __restrict__ bg,
          const float* __restrict__ lng, const float* __restrict__ lnb,
          const float* __restrict__ hns, const float* __restrict__ hnb,
          float* __restrict__ out)
{
    extern __shared__ float sm[];
    unsigned* H1u  = (unsigned*)sm;            // [32 e][172] u32; aliased by G1u
    float*    EIcT = (float*)(H1u + 5504);     // [32 d][36]
    unsigned* EIbP = (unsigned*)(EIcT + 1152); // [32 e][28]
    float*    PI   = (float*)(EIbP + 896);     // [324]
    unsigned* MSbP = (unsigned*)(PI + 324);    // [32 e][20]
    float*    WST  = (float*)(MSbP + 640);     // [32 d][36]
    float*    HT2  = WST + 1152;               // [192]
    float*    nodes_s = HT2 + 192;             // [64]
    float*    f1i_s   = nodes_s + 64;          // [96]
    float*    NI   = f1i_s + 96;               // [96]
    float*    N1s  = NI + 96;                  // [128]
    float*    nouts= N1s + 128;                // [64]
    float*    gates= nouts + 64;               // [32]
    float*    maskv= gates + 32;               // [32]
    float*    stats= maskv + 32;               // [2]
    int*      nbr_s= (int*)(stats + 2);        // [32]
    float*    rdist_s = (float*)(nbr_s + 32);  // [32]
    unsigned* G1u  = H1u;

    const int tid  = threadIdx.x;
    const int lane = tid & 31;
    const int wrow = tid >> 5;
    const int g    = lane >> 2;
    const int tg   = lane & 3;
    const int node = blockIdx.x;
    const int bbase = (node / Nn) * Nn;

    // ---- P0 ----
    if (tid < 64)           nodes_s[tid]    = f0[(size_t)node * 64 + tid];
    else if (tid < 160)     f1i_s[tid - 64] = f1[(size_t)node * 96 + (tid - 64)];
    if (tid < 32)           nbr_s[tid] = nbr[node * Kk + tid];
    else if (tid < 64)      maskv[tid - 32] = (float)msk[node * Kk + tid - 32];
    else if (tid < 96)      rdist_s[tid - 64] = rdist[node * Kk + tid - 64];
    for (int c = tid; c < 324; c += 256)
        PI[c] = (c < E2C) ? PI_g[(size_t)node * E2C + c] : 0.f;
    if (tid < 224) H1u[(tid / 7) * 172 + 161 + (tid % 7)] = 0u;
    __syncthreads();

    // ---- P1: rel_norm -> EIcT + LN stats ----
    #pragma unroll
    for (int i = 0; i < 4; i++) {
        const int e = wrow + 8 * i;
        const float* f1j = f1 + (size_t)(bbase + nbr_s[e]) * 96;
        const float r0 = f1i_s[lane * 3 + 0] - f1j[lane * 3 + 0];
        const float r1 = f1i_s[lane * 3 + 1] - f1j[lane * 3 + 1];
        const float r2 = f1i_s[lane * 3 + 2] - f1j[lane * 3 + 2];
        EIcT[lane * 36 + e] = sqrtf(r0 * r0 + r1 * r1 + r2 * r2);
    }
    if (wrow == 7) {
        float x0 = nodes_s[lane], x1 = nodes_s[lane + 32];
        float s = x0 + x1, ss = x0 * x0 + x1 * x1;
        #pragma unroll
        for (int o = 16; o > 0; o >>= 1) {
            s  += __shfl_down_sync(0xffffffffu, s,  o);
            ss += __shfl_down_sync(0xffffffffu, ss, o);
        }
        if (lane == 0) {
            const float mu  = s * (1.f / 64.f);
            const float var = ss * (1.f / 64.f) - mu * mu;
            stats[0] = mu;
            stats[1] = rsqrtf(var + 1e-5f);
        }
    }
    __syncthreads();

    // ---- P1b: pack edge_in pairs into EIbP ----
    for (int idx = tid; idx < 768; idx += 256) {
        const int e = idx / 24, kp = idx - 24 * (idx / 24);
        unsigned v;
        if (kp < 16)       v = bf2(EIcT[(2 * kp) * 36 + e], EIcT[(2 * kp + 1) * 36 + e]);
        else if (kp == 16) v = bf2(rdist_s[e], 0.f);
        else               v = 0u;
        EIbP[e * 28 + kp] = v;
    }
    __syncthreads();

    // ---- GEMM1 (tensor): 84 tiles, b-frags direct from L2 ----
    #pragma unroll
    for (int tt = 0; tt < 11; tt++) {
        const int t = wrow + 8 * tt;
        if (t < 84) {
            const int mt = t & 1, nt = t >> 1;
            const int e0 = 16 * mt + g;
            float d0 = 0.f, d1 = 0.f, d2 = 0.f, d3 = 0.f;
            #pragma unroll
            for (int ks = 0; ks < 3; ks++) {
                const unsigned a0 = EIbP[e0 * 28 + 8 * ks + tg];
                const unsigned a1 = EIbP[(e0 + 8) * 28 + 8 * ks + tg];
                const unsigned a2 = EIbP[e0 * 28 + 8 * ks + 4 + tg];
                const unsigned a3 = EIbP[(e0 + 8) * 28 + 8 * ks + 4 + tg];
                const ull b = __ldg(&Wf1_g[(nt * 3 + ks) * 32 + lane]);
                mma16816(d0, d1, d2, d3, a0, a1, a2, a3, (unsigned)b, (unsigned)(b >> 32));
            }
            const int p = 4 * nt + tg;
            if (p < 161) {
                const float2 pi2 = *(const float2*)&PI[2 * p];
                const float2 pjA = __ldg((const float2*)(PJ_g + (size_t)(bbase + nbr_s[e0]) * E2C + 2 * p));
                const float2 pjB = __ldg((const float2*)(PJ_g + (size_t)(bbase + nbr_s[e0 + 8]) * E2C + 2 * p));
                H1u[e0 * 172 + p]       = bf2(siluf(d0 + pi2.x + pjA.x), siluf(d1 + pi2.y + pjA.y));
                H1u[(e0 + 8) * 172 + p] = bf2(siluf(d2 + pi2.x + pjB.x), siluf(d3 + pi2.y + pjB.y));
            }
        }
    }
    __syncthreads();

    // ---- GEMM2 (tensor): K=336 ----
    {
        const int mt = wrow & 1, nt = wrow >> 1;
        const int e0 = 16 * mt + g;
        float d0 = 0.f, d1 = 0.f, d2 = 0.f, d3 = 0.f;
        #pragma unroll
        for (int ks = 0; ks < 21; ks++) {
            const unsigned a0 = H1u[e0 * 172 + 8 * ks + tg];
            const unsigned a1 = H1u[(e0 + 8) * 172 + 8 * ks + tg];
            const unsigned a2 = H1u[e0 * 172 + 8 * ks + 4 + tg];
            const unsigned a3 = H1u[(e0 + 8) * 172 + 8 * ks + 4 + tg];
            const ull b = __ldg(&Wf2_g[(ks * 4 + nt) * 32 + lane]);
            mma16816(d0, d1, d2, d3, a0, a1, a2, a3, (unsigned)b, (unsigned)(b >> 32));
        }
        const int col0 = 8 * nt + 2 * tg;
        const float b0 = be2[col0], b1 = be2[col0 + 1];
        MSbP[e0 * 20 + 4 * nt + tg]       = bf2(siluf(d0 + b0), siluf(d1 + b1));
        MSbP[(e0 + 8) * 20 + 4 * nt + tg] = bf2(siluf(d2 + b0), siluf(d3 + b1));
    }
    __syncthreads();

    // ---- GEMM3 (tensor): 32 tiles; writes G1u (aliases H1u, safe) ----
    {
        const int mt = wrow & 1, nt0 = wrow >> 1;
        const int e0 = 16 * mt + g;
        float d[4][4];
        #pragma unroll
        for (int t = 0; t < 4; t++)
            #pragma unroll
            for (int q = 0; q < 4; q++) d[t][q] = 0.f;
        #pragma unroll
        for (int ks = 0; ks < 2; ks++) {
            const unsigned a0 = MSbP[e0 * 20 + 8 * ks + tg];
            const unsigned a1 = MSbP[(e0 + 8) * 20 + 8 * ks + tg];
            const unsigned a2 = MSbP[e0 * 20 + 8 * ks + 4 + tg];
            const unsigned a3 = MSbP[(e0 + 8) * 20 + 8 * ks + 4 + tg];
            #pragma unroll
            for (int t = 0; t < 4; t++) {
                const int nt = nt0 + 4 * t;
                const ull b = __ldg(&Wf3_g[(ks * 16 + nt) * 32 + lane]);
                mma16816(d[t][0], d[t][1], d[t][2], d[t][3], a0, a1, a2, a3,
                         (unsigned)b, (unsigned)(b >> 32));
            }
        }
        #pragma unroll
        for (int t = 0; t < 4; t++) {
            const int nt = nt0 + 4 * t;
            const int col0 = 8 * nt + 2 * tg;
            const float b0 = bh1[col0], b1 = bh1[col0 + 1];
            G1u[e0 * 68 + 4 * nt + tg]       = bf2(siluf(d[t][0] + b0), siluf(d[t][1] + b1));
            G1u[(e0 + 8) * 68 + 4 * nt + tg] = bf2(siluf(d[t][2] + b0), siluf(d[t][3] + b1));
        }
    }
    __syncthreads();

    // ---- GEMM4 (tensor): K=128 ----
    {
        const int mt = wrow & 1, nt = wrow >> 1;
        const int e0 = 16 * mt + g;
        float d0 = 0.f, d1 = 0.f, d2 = 0.f, d3 = 0.f;
        #pragma unroll
        for (int ks = 0; ks < 8; ks++) {
            const unsigned a0 = G1u[e0 * 68 + 8 * ks + tg];
            const unsigned a1 = G1u[(e0 + 8) * 68 + 8 * ks + tg];
            const unsigned a2 = G1u[e0 * 68 + 8 * ks + 4 + tg];
            const unsigned a3 = G1u[(e0 + 8) * 68 + 8 * ks + 4 + tg];
            const ull b = __ldg(&Wf4_g[(ks * 4 + nt) * 32 + lane]);
            mma16816(d0, d1, d2, d3, a0, a1, a2, a3, (unsigned)b, (unsigned)(b >> 32));
        }
        const int col0 = 8 * nt + 2 * tg;
        WST[col0 * 36 + e0]           = d0 + bh2[col0];
        WST[(col0 + 1) * 36 + e0]     = d1 + bh2[col0 + 1];
        WST[col0 * 36 + e0 + 8]       = d2 + bh2[col0];
        WST[(col0 + 1) * 36 + e0 + 8] = d3 + bh2[col0 + 1];
    }
    __syncthreads();

    // ---- htype (warps 0-5) + NI prep incl. inline MI (warps 6-7) ----
    if (tid < 192) {
        const int half = (tid >= 96);
        const int t = tid - 96 * half;
        const int d = t / 3;
        const float hs = hns[d], hb = hnb[d];
        const float fi = f1i_s[t];
        const int e0 = half * 16;
        float s = 0.f;
        #pragma unroll
        for (int e4 = 0; e4 < 4; e4++) {
            const float4 nrm4 = *(const float4*)&EIcT[d * 36 + e0 + 4 * e4];
            const float4 w4   = *(const float4*)&WST[d * 36 + e0 + 4 * e4];
            #pragma unroll
            for (int m = 0; m < 4; m++) {
                const int e = e0 + 4 * e4 + m;
                const float nrm = (m == 0) ? nrm4.x : (m == 1) ? nrm4.y : (m == 2) ? nrm4.z : nrm4.w;
                const float wv  = (m == 0) ? w4.x   : (m == 1) ? w4.y   : (m == 2) ? w4.z   : w4.w;
                const float coef = __fdividef(nrm * hs + hb, fmaxf(nrm, 1e-8f));
                const float relv = fi - __ldg(&f1[(size_t)(bbase + nbr_s[e]) * 96 + t]);
                s += relv * coef * wv;
            }
        }
        HT2[tid] = s;
    } else if (tid < 256) {
        const int c = tid - 192;
        NI[c] = (nodes_s[c] - stats[0]) * stats[1] * lng[c] + lnb[c];
        if (c < 32) {
            float s = 0.f;
            #pragma unroll 8
            for (int e = 0; e < 32; e++) {
                const unsigned u = MSbP[e * 20 + (c >> 1)];
                s += maskv[e] * ((c & 1) ? bhi(u) : blo(u));
            }
            NI[64 + c] = s;
        }
    }
    __syncthreads();

    // ---- N1[128] = silu(node_in @ Wn1 + bn1) ----
    if (tid < 128) {
        float a = 0.f;
        #pragma unroll 8
        for (int r = 0; r < 96; r++) a += NI[r] * __ldg(&Wn1[r * 128 + tid]);
        N1s[tid] = siluf(a + bn1[tid]);
    }
    __syncthreads();

    // ---- node_out[64] = N1 @ Wn2 + bn2 + nodes ----
    if (tid < 64) {
        float a = 0.f;
        #pragma unroll 8
        for (int r = 0; r < 128; r++) a += N1s[r] * __ldg(&Wn2[r * 64 + tid]);
        const float v = a + bn2[tid] + nodes_s[tid];
        nouts[tid] = v;
        out[(size_t)node * 64 + tid] = v;
    }
    __syncthreads();

    // ---- gate[32] = sigmoid(node_out @ Wg + bg) ----
    if (tid < 32) {
        float a = 0.f;
        #pragma unroll 8
        for (int r = 0; r < 64; r++) a += nouts[r] * __ldg(&Wg[r * 32 + tid]);
        gates[tid] = sigmf(a + bg[tid]);
    }
    __syncthreads();

    // ---- f1_out ----
    if (tid < 96) {
        const int d = tid / 3;
        const float v = (f1i_s[tid] + HT2[tid] + HT2[96 + tid]) * gates[d];
        out[(size_t)Bb * Nn * D0 + (size_t)node * 96 + tid] = v;
    }
}

extern "C" void kernel_launch(void* const* d_in, const int* in_sizes, int n_in,
                              void* d_out, int out_size) {
    const float* f0   = (const float*)d_in[0];
    const float* f1   = (const float*)d_in[1];
    const int*   nbr  = (const int*)d_in[2];
    const unsigned char* msk = (const unsigned char*)d_in[3];
    const float* rdist= (const float*)d_in[4];
    const float* We1  = (const float*)d_in[5];
    const float* be1  = (const float*)d_in[6];
    const float* We2  = (const float*)d_in[7];
    const float* be2  = (const float*)d_in[8];
    const float* Wh1  = (const float*)d_in[9];
    const float* bh1  = (const float*)d_in[10];
    const float* Wh2  = (const float*)d_in[11];
    const float* bh2  = (const float*)d_in[12];
    const float* Wn1  = (const float*)d_in[13];
    const float* bn1  = (const float*)d_in[14];
    const float* Wn2  = (const float*)d_in[15];
    const float* bn2  = (const float*)d_in[16];
    const float* Wg   = (const float*)d_in[17];
    const float* bg   = (const float*)d_in[18];
    const float* lng  = (const float*)d_in[19];
    const float* lnb  = (const float*)d_in[20];
    const float* hns  = (const float*)d_in[21];
    const float* hnb  = (const float*)d_in[22];
    float* out = (float*)d_out;

    proj_kernel<<<NT / 16, 384>>>(f0, We1, be1);
    prep_frag<<<35, 256>>>(We1, We2, Wh1, Wh2);

    const size_t smem_bytes = 10438 * 4;

    cudaFuncSetAttribute(egnn_main, cudaFuncAttributeMaxDynamicSharedMemorySize,
                         (int)smem_bytes);

    egnn_main<<<NT, 256, smem_bytes>>>(
        f0, f1, nbr, msk, rdist,
        be2, bh1, bh2,
        Wn1, bn1, Wn2, bn2, Wg, bg, lng, lnb, hns, hnb, out);
}

// round 16
// speedup vs baseline: 2.5028x; 1.0789x over previous
#include <cuda_runtime.h>
#include <math.h>

#define Bb 2
#define Nn 4096
#define NT (Bb*Nn)
#define Kk 32
#define D0 64
#define E2C 322

typedef unsigned long long ull;

__device__ float PI_g[(size_t)NT * E2C + 384];
__device__ float PJ_g[(size_t)NT * E2C + 384];
__device__ __align__(16) ull Wfp_g[10496];  // We1 rows 0..127 frags: [p 0..1][nt 0..40][ks 0..3][32]
__device__ __align__(16) ull Wf1_g[4032];   // We1-tail frags: [nt 0..41][ks 0..2][32]
__device__ __align__(16) ull Wf2_g[2688];   // We2 frags: [ks 0..20][nt 0..3][32]
__device__ __align__(16) ull Wf3_g[1024];   // Wh1 frags: [ks 0..1][nt 0..15][32]
__device__ __align__(16) ull Wf4_g[1024];   // Wh2 frags: [ks 0..7][nt 0..3][32]

__device__ __forceinline__ float siluf(float x) { return x / (1.f + __expf(-x)); }
__device__ __forceinline__ float sigmf(float x) { return 1.f / (1.f + __expf(-x)); }
__device__ __forceinline__ unsigned bf2(float lo, float hi) {
    unsigned r; asm("cvt.rn.bf16x2.f32 %0, %1, %2;" : "=r"(r) : "f"(hi), "f"(lo)); return r;
}
__device__ __forceinline__ float blo(unsigned u) { return __uint_as_float(u << 16); }
__device__ __forceinline__ float bhi(unsigned u) { return __uint_as_float(u & 0xffff0000u); }
__device__ __forceinline__ void mma16816(float& d0, float& d1, float& d2, float& d3,
    unsigned a0, unsigned a1, unsigned a2, unsigned a3, unsigned b0, unsigned b1)
{
    asm("mma.sync.aligned.m16n8k16.row.col.f32.bf16.bf16.f32 "
        "{%0,%1,%2,%3}, {%4,%5,%6,%7}, {%8,%9}, {%0,%1,%2,%3};"
        : "+f"(d0), "+f"(d1), "+f"(d2), "+f"(d3)
        : "r"(a0), "r"(a1), "r"(a2), "r"(a3), "r"(b0), "r"(b1));
}

// ---------------- proj on tensor cores: [32 nodes] x [644 cols] per block
__global__ void __launch_bounds__(256)
proj_tc(const float* __restrict__ f0, const float* __restrict__ be1)
{
    __shared__ unsigned NDbP[32 * 36];
    __shared__ float be1s[328];
    const int nb = blockIdx.x * 32;
    const int tid = threadIdx.x;
    const int lane = tid & 31;
    const int wrow = tid >> 5;
    const int g = lane >> 2;
    const int tg = lane & 3;

    for (int idx = tid; idx < 1024; idx += 256) {
        const int n = idx >> 5, kp = idx & 31;
        const float2 v = *(const float2*)&f0[(size_t)(nb + n) * 64 + 2 * kp];
        NDbP[n * 36 + kp] = bf2(v.x, v.y);
    }
    for (int c = tid; c < 328; c += 256) be1s[c] = (c < E2C) ? be1[c] : 0.f;
    __syncthreads();

    #pragma unroll
    for (int tt = 0; tt < 21; tt++) {
        const int t = wrow + 8 * tt;
        if (t < 164) {
            const int mt = t & 1;
            const int ntp = t >> 1;
            const int p = (ntp >= 41);
            const int nt = ntp - 41 * p;
            const int e0 = 16 * mt + g;
            float d0 = 0.f, d1 = 0.f, d2 = 0.f, d3 = 0.f;
            #pragma unroll
            for (int ks = 0; ks < 4; ks++) {
                const unsigned a0 = NDbP[e0 * 36 + 8 * ks + tg];
                const unsigned a1 = NDbP[(e0 + 8) * 36 + 8 * ks + tg];
                const unsigned a2 = NDbP[e0 * 36 + 8 * ks + 4 + tg];
                const unsigned a3 = NDbP[(e0 + 8) * 36 + 8 * ks + 4 + tg];
                const ull b = __ldg(&Wfp_g[((size_t)(p * 41 + nt) * 4 + ks) * 32 + lane]);
                mma16816(d0, d1, d2, d3, a0, a1, a2, a3, (unsigned)b, (unsigned)(b >> 32));
            }
            const int c0 = 8 * nt + 2 * tg;
            if (c0 < E2C) {
                if (p == 0) {
                    const float2 b2 = *(const float2*)&be1s[c0];
                    *(float2*)&PI_g[(size_t)(nb + e0) * E2C + c0]     = make_float2(d0 + b2.x, d1 + b2.y);
                    *(float2*)&PI_g[(size_t)(nb + e0 + 8) * E2C + c0] = make_float2(d2 + b2.x, d3 + b2.y);
                } else {
                    *(float2*)&PJ_g[(size_t)(nb + e0) * E2C + c0]     = make_float2(d0, d1);
                    *(float2*)&PJ_g[(size_t)(nb + e0 + 8) * E2C + c0] = make_float2(d2, d3);
                }
            }
        }
    }
}

// ---------------- pre-pack B fragments
__global__ void __launch_bounds__(256)
prep_frag(const float* __restrict__ We1, const float* __restrict__ We2,
          const float* __restrict__ Wh1, const float* __restrict__ Wh2)
{
    const int idx = blockIdx.x * 256 + threadIdx.x;
    if (idx < 10496) {                      // Wfp: [p][nt][ks][lane], We1 rows 0..127
        const int lane = idx & 31;
        int j = idx >> 5;
        const int ks = j & 3; j >>= 2;
        const int nt = j % 41;
        const int p  = j / 41;
        const int g = lane >> 2, tg = lane & 3;
        const int n = 8 * nt + g;
        const int k = 64 * p + 16 * ks + 2 * tg;
        float w00 = 0.f, w01 = 0.f, w10 = 0.f, w11 = 0.f;
        if (n < E2C) {
            w00 = We1[(size_t)k * E2C + n];
            w01 = We1[(size_t)(k + 1) * E2C + n];
            w10 = We1[(size_t)(k + 8) * E2C + n];
            w11 = We1[(size_t)(k + 9) * E2C + n];
        }
        Wfp_g[idx] = (ull)bf2(w00, w01) | ((ull)bf2(w10, w11) << 32);
    } else if (idx < 10496 + 4032) {        // Wf1: [nt][ks][lane], We1 rows 128..160
        const int i2 = idx - 10496;
        const int lane = i2 & 31;
        const int j = i2 >> 5;
        const int ks = j % 3, nt = j / 3;
        const int g = lane >> 2, tg = lane & 3;
        const int n = 8 * nt + g;
        const int k = 16 * ks + 2 * tg;
        float w00 = 0.f, w01 = 0.f, w10 = 0.f, w11 = 0.f;
        if (n < E2C) {
            if (k     < 33) w00 = We1[(size_t)(128 + k)     * E2C + n];
            if (k + 1 < 33) w01 = We1[(size_t)(128 + k + 1) * E2C + n];
            if (k + 8 < 33) w10 = We1[(size_t)(128 + k + 8) * E2C + n];
            if (k + 9 < 33) w11 = We1[(size_t)(128 + k + 9) * E2C + n];
        }
        Wf1_g[i2] = (ull)bf2(w00, w01) | ((ull)bf2(w10, w11) << 32);
    } else if (idx < 10496 + 4032 + 2688) { // Wf2
        const int j = idx - 10496 - 4032;
        const int lane = j & 31, nt = (j >> 5) & 3, ks = j >> 7;
        const int g = lane >> 2, tg = lane & 3;
        const int n = 8 * nt + g;
        const int k = 16 * ks + 2 * tg;
        const float w00 = (k     < E2C) ? We2[k * 32 + n]       : 0.f;
        const float w01 = (k + 1 < E2C) ? We2[(k + 1) * 32 + n] : 0.f;
        const float w10 = (k + 8 < E2C) ? We2[(k + 8) * 32 + n] : 0.f;
        const float w11 = (k + 9 < E2C) ? We2[(k + 9) * 32 + n] : 0.f;
        Wf2_g[j] = (ull)bf2(w00, w01) | ((ull)bf2(w10, w11) << 32);
    } else if (idx < 10496 + 4032 + 2688 + 1024) {  // Wf3
        const int j = idx - 10496 - 4032 - 2688;
        const int lane = j & 31, nt = (j >> 5) & 15, ks = j >> 9;
        const int g = lane >> 2, tg = lane & 3;
        const int n = 8 * nt + g;
        const int k = 16 * ks + 2 * tg;
        Wf3_g[j] = (ull)bf2(Wh1[k * 128 + n], Wh1[(k + 1) * 128 + n])
                 | ((ull)bf2(Wh1[(k + 8) * 128 + n], Wh1[(k + 9) * 128 + n]) << 32);
    } else if (idx < 10496 + 4032 + 2688 + 2048) {  // Wf4
        const int j = idx - 10496 - 4032 - 2688 - 1024;
        const int lane = j & 31, nt = (j >> 5) & 3, ks = j >> 7;
        const int g = lane >> 2, tg = lane & 3;
        const int n = 8 * nt + g;
        const int k = 16 * ks + 2 * tg;
        Wf4_g[j] = (ull)bf2(Wh2[k * 32 + n], Wh2[(k + 1) * 32 + n])
                 | ((ull)bf2(Wh2[(k + 8) * 32 + n], Wh2[(k + 9) * 32 + n]) << 32);
    }
}

// ---------------- main fused kernel: tensor GEMMs with direct-LDG B fragments
__global__ void __launch_bounds__(256, 5)
egnn_main(const float* __restrict__ f0, const float* __restrict__ f1,
          const int* __restrict__ nbr, const unsigned char* __restrict__ msk,
          const float* __restrict__ rdist,
          const float* __restrict__ be2, const float* __restrict__ bh1,
          const float* __restrict__ bh2,
          const float* __restrict__ Wn1, const float* __restrict__ bn1,
          const float* __restrict__ Wn2, const float* __restrict__ bn2,
          const float* __restrict__ Wg,  const float* __restrict__ bg,
          const float* __restrict__ lng, const float* __restrict__ lnb,
          const float* __restrict__ hns, const float* __restrict__ hnb,
          float* __restrict__ out)
{
    extern __shared__ float sm[];
    unsigned* H1u  = (unsigned*)sm;            // [32 e][172] u32; aliased by G1u
    float*    EIcT = (float*)(H1u + 5504);     // [32 d][36]
    unsigned* EIbP = (unsigned*)(EIcT + 1152); // [32 e][28]
    float*    PI   = (float*)(EIbP + 896);     // [324]
    unsigned* MSbP = (unsigned*)(PI + 324);    // [32 e][20]
    float*    WST  = (float*)(MSbP + 640);     // [32 d][36]
    float*    HT2  = WST + 1152;               // [192]
    float*    nodes_s = HT2 + 192;             // [64]
    float*    f1i_s   = nodes_s + 64;          // [96]
    float*    NI   = f1i_s + 96;               // [96]
    float*    N1s  = NI + 96;                  // [128]
    float*    nouts= N1s + 128;                // [64]
    float*    gates= nouts + 64;               // [32]
    float*    maskv= gates + 32;               // [32]
    float*    stats= maskv + 32;               // [2]
    int*      nbr_s= (int*)(stats + 2);        // [32]
    float*    rdist_s = (float*)(nbr_s + 32);  // [32]
    unsigned* G1u  = H1u;

    const int tid  = threadIdx.x;
    const int lane = tid & 31;
    const int wrow = tid >> 5;
    const int g    = lane >> 2;
    const int tg   = lane & 3;
    const int node = blockIdx.x;
    const int bbase = (node / Nn) * Nn;

    // ---- P0 ----
    if (tid < 64)           nodes_s[tid]    = f0[(size_t)node * 64 + tid];
    else if (tid < 160)     f1i_s[tid - 64] = f1[(size_t)node * 96 + (tid - 64)];
    if (tid < 32)           nbr_s[tid] = nbr[node * Kk + tid];
    else if (tid < 64)      maskv[tid - 32] = (float)msk[node * Kk + tid - 32];
    else if (tid < 96)      rdist_s[tid - 64] = rdist[node * Kk + tid - 64];
    for (int c = tid; c < 324; c += 256)
        PI[c] = (c < E2C) ? PI_g[(size_t)node * E2C + c] : 0.f;
    if (tid < 224) H1u[(tid / 7) * 172 + 161 + (tid % 7)] = 0u;
    __syncthreads();

    // ---- P1: rel_norm -> EIcT + LN stats ----
    #pragma unroll
    for (int i = 0; i < 4; i++) {
        const int e = wrow + 8 * i;
        const float* f1j = f1 + (size_t)(bbase + nbr_s[e]) * 96;
        const float r0 = f1i_s[lane * 3 + 0] - f1j[lane * 3 + 0];
        const float r1 = f1i_s[lane * 3 + 1] - f1j[lane * 3 + 1];
        const float r2 = f1i_s[lane * 3 + 2] - f1j[lane * 3 + 2];
        EIcT[lane * 36 + e] = sqrtf(r0 * r0 + r1 * r1 + r2 * r2);
    }
    if (wrow == 7) {
        float x0 = nodes_s[lane], x1 = nodes_s[lane + 32];
        float s = x0 + x1, ss = x0 * x0 + x1 * x1;
        #pragma unroll
        for (int o = 16; o > 0; o >>= 1) {
            s  += __shfl_down_sync(0xffffffffu, s,  o);
            ss += __shfl_down_sync(0xffffffffu, ss, o);
        }
        if (lane == 0) {
            const float mu  = s * (1.f / 64.f);
            const float var = ss * (1.f / 64.f) - mu * mu;
            stats[0] = mu;
            stats[1] = rsqrtf(var + 1e-5f);
        }
    }
    __syncthreads();

    // ---- P1b: pack edge_in pairs into EIbP ----
    for (int idx = tid; idx < 768; idx += 256) {
        const int e = idx / 24, kp = idx - 24 * (idx / 24);
        unsigned v;
        if (kp < 16)       v = bf2(EIcT[(2 * kp) * 36 + e], EIcT[(2 * kp + 1) * 36 + e]);
        else if (kp == 16) v = bf2(rdist_s[e], 0.f);
        else               v = 0u;
        EIbP[e * 28 + kp] = v;
    }
    __syncthreads();

    // ---- GEMM1 (tensor): 84 tiles, b-frags direct from L2 ----
    #pragma unroll
    for (int tt = 0; tt < 11; tt++) {
        const int t = wrow + 8 * tt;
        if (t < 84) {
            const int mt = t & 1, nt = t >> 1;
            const int e0 = 16 * mt + g;
            float d0 = 0.f, d1 = 0.f, d2 = 0.f, d3 = 0.f;
            #pragma unroll
            for (int ks = 0; ks < 3; ks++) {
                const unsigned a0 = EIbP[e0 * 28 + 8 * ks + tg];
                const unsigned a1 = EIbP[(e0 + 8) * 28 + 8 * ks + tg];
                const unsigned a2 = EIbP[e0 * 28 + 8 * ks + 4 + tg];
                const unsigned a3 = EIbP[(e0 + 8) * 28 + 8 * ks + 4 + tg];
                const ull b = __ldg(&Wf1_g[(nt * 3 + ks) * 32 + lane]);
                mma16816(d0, d1, d2, d3, a0, a1, a2, a3, (unsigned)b, (unsigned)(b >> 32));
            }
            const int p = 4 * nt + tg;
            if (p < 161) {
                const float2 pi2 = *(const float2*)&PI[2 * p];
                const float2 pjA = __ldg((const float2*)(PJ_g + (size_t)(bbase + nbr_s[e0]) * E2C + 2 * p));
                const float2 pjB = __ldg((const float2*)(PJ_g + (size_t)(bbase + nbr_s[e0 + 8]) * E2C + 2 * p));
                H1u[e0 * 172 + p]       = bf2(siluf(d0 + pi2.x + pjA.x), siluf(d1 + pi2.y + pjA.y));
                H1u[(e0 + 8) * 172 + p] = bf2(siluf(d2 + pi2.x + pjB.x), siluf(d3 + pi2.y + pjB.y));
            }
        }
    }
    __syncthreads();

    // ---- GEMM2 (tensor): K=336 ----
    {
        const int mt = wrow & 1, nt = wrow >> 1;
        const int e0 = 16 * mt + g;
        float d0 = 0.f, d1 = 0.f, d2 = 0.f, d3 = 0.f;
        #pragma unroll
        for (int ks = 0; ks < 21; ks++) {
            const unsigned a0 = H1u[e0 * 172 + 8 * ks + tg];
            const unsigned a1 = H1u[(e0 + 8) * 172 + 8 * ks + tg];
            const unsigned a2 = H1u[e0 * 172 + 8 * ks + 4 + tg];
            const unsigned a3 = H1u[(e0 + 8) * 172 + 8 * ks + 4 + tg];
            const ull b = __ldg(&Wf2_g[(ks * 4 + nt) * 32 + lane]);
            mma16816(d0, d1, d2, d3, a0, a1, a2, a3, (unsigned)b, (unsigned)(b >> 32));
        }
        const int col0 = 8 * nt + 2 * tg;
        const float b0 = be2[col0], b1 = be2[col0 + 1];
        MSbP[e0 * 20 + 4 * nt + tg]       = bf2(siluf(d0 + b0), siluf(d1 + b1));
        MSbP[(e0 + 8) * 20 + 4 * nt + tg] = bf2(siluf(d2 + b0), siluf(d3 + b1));
    }
    __syncthreads();

    // ---- GEMM3 (tensor): 32 tiles; writes G1u (aliases H1u, safe) ----
    {
        const int mt = wrow & 1, nt0 = wrow >> 1;
        const int e0 = 16 * mt + g;
        float d[4][4];
        #pragma unroll
        for (int t = 0; t < 4; t++)
            #pragma unroll
            for (int q = 0; q < 4; q++) d[t][q] = 0.f;
        #pragma unroll
        for (int ks = 0; ks < 2; ks++) {
            const unsigned a0 = MSbP[e0 * 20 + 8 * ks + tg];
            const unsigned a1 = MSbP[(e0 + 8) * 20 + 8 * ks + tg];
            const unsigned a2 = MSbP[e0 * 20 + 8 * ks + 4 + tg];
            const unsigned a3 = MSbP[(e0 + 8) * 20 + 8 * ks + 4 + tg];
            #pragma unroll
            for (int t = 0; t < 4; t++) {
                const int nt = nt0 + 4 * t;
                const ull b = __ldg(&Wf3_g[(ks * 16 + nt) * 32 + lane]);
                mma16816(d[t][0], d[t][1], d[t][2], d[t][3], a0, a1, a2, a3,
                         (unsigned)b, (unsigned)(b >> 32));
            }
        }
        #pragma unroll
        for (int t = 0; t < 4; t++) {
            const int nt = nt0 + 4 * t;
            const int col0 = 8 * nt + 2 * tg;
            const float b0 = bh1[col0], b1 = bh1[col0 + 1];
            G1u[e0 * 68 + 4 * nt + tg]       = bf2(siluf(d[t][0] + b0), siluf(d[t][1] + b1));
            G1u[(e0 + 8) * 68 + 4 * nt + tg] = bf2(siluf(d[t][2] + b0), siluf(d[t][3] + b1));
        }
    }
    __syncthreads();

    // ---- GEMM4 (tensor): K=128 ----
    {
        const int mt = wrow & 1, nt = wrow >> 1;
        const int e0 = 16 * mt + g;
        float d0 = 0.f, d1 = 0.f, d2 = 0.f, d3 = 0.f;
        #pragma unroll
        for (int ks = 0; ks < 8; ks++) {
            const unsigned a0 = G1u[e0 * 68 + 8 * ks + tg];
            const unsigned a1 = G1u[(e0 + 8) * 68 + 8 * ks + tg];
            const unsigned a2 = G1u[e0 * 68 + 8 * ks + 4 + tg];
            const unsigned a3 = G1u[(e0 + 8) * 68 + 8 * ks + 4 + tg];
            const ull b = __ldg(&Wf4_g[(ks * 4 + nt) * 32 + lane]);
            mma16816(d0, d1, d2, d3, a0, a1, a2, a3, (unsigned)b, (unsigned)(b >> 32));
        }
        const int col0 = 8 * nt + 2 * tg;
        WST[col0 * 36 + e0]           = d0 + bh2[col0];
        WST[(col0 + 1) * 36 + e0]     = d1 + bh2[col0 + 1];
        WST[col0 * 36 + e0 + 8]       = d2 + bh2[col0];
        WST[(col0 + 1) * 36 + e0 + 8] = d3 + bh2[col0 + 1];
    }
    __syncthreads();

    // ---- htype (warps 0-5) + NI prep incl. inline MI (warps 6-7) ----
    if (tid < 192) {
        const int half = (tid >= 96);
        const int t = tid - 96 * half;
        const int d = t / 3;
        const float hs = hns[d], hb = hnb[d];
        const float fi = f1i_s[t];
        const int e0 = half * 16;
        float s = 0.f;
        #pragma unroll
        for (int e4 = 0; e4 < 4; e4++) {
            const float4 nrm4 = *(const float4*)&EIcT[d * 36 + e0 + 4 * e4];
            const float4 w4   = *(const float4*)&WST[d * 36 + e0 + 4 * e4];
            #pragma unroll
            for (int m = 0; m < 4; m++) {
                const int e = e0 + 4 * e4 + m;
                const float nrm = (m == 0) ? nrm4.x : (m == 1) ? nrm4.y : (m == 2) ? nrm4.z : nrm4.w;
                const float wv  = (m == 0) ? w4.x   : (m == 1) ? w4.y   : (m == 2) ? w4.z   : w4.w;
                const float coef = __fdividef(nrm * hs + hb, fmaxf(nrm, 1e-8f));
                const float relv = fi - __ldg(&f1[(size_t)(bbase + nbr_s[e]) * 96 + t]);
                s += relv * coef * wv;
            }
        }
        HT2[tid] = s;
    } else if (tid < 256) {
        const int c = tid - 192;
        NI[c] = (nodes_s[c] - stats[0]) * stats[1] * lng[c] + lnb[c];
        if (c < 32) {
            float s = 0.f;
            #pragma unroll 8
            for (int e = 0; e < 32; e++) {
                const unsigned u = MSbP[e * 20 + (c >> 1)];
                s += maskv[e] * ((c & 1) ? bhi(u) : blo(u));
            }
            NI[64 + c] = s;
        }
    }
    __syncthreads();

    // ---- N1[128] = silu(node_in @ Wn1 + bn1) ----
    if (tid < 128) {
        float a = 0.f;
        #pragma unroll 8
        for (int r = 0; r < 96; r++) a += NI[r] * __ldg(&Wn1[r * 128 + tid]);
        N1s[tid] = siluf(a + bn1[tid]);
    }
    __syncthreads();

    // ---- node_out[64] = N1 @ Wn2 + bn2 + nodes ----
    if (tid < 64) {
        float a = 0.f;
        #pragma unroll 8
        for (int r = 0; r < 128; r++) a += N1s[r] * __ldg(&Wn2[r * 64 + tid]);
        const float v = a + bn2[tid] + nodes_s[tid];
        nouts[tid] = v;
        out[(size_t)node * 64 + tid] = v;
    }
    __syncthreads();

    // ---- gate[32] = sigmoid(node_out @ Wg + bg) ----
    if (tid < 32) {
        float a = 0.f;
        #pragma unroll 8
        for (int r = 0; r < 64; r++) a += nouts[r] * __ldg(&Wg[r * 32 + tid]);
        gates[tid] = sigmf(a + bg[tid]);
    }
    __syncthreads();

    // ---- f1_out ----
    if (tid < 96) {
        const int d = tid / 3;
        const float v = (f1i_s[tid] + HT2[tid] + HT2[96 + tid]) * gates[d];
        out[(size_t)Bb * Nn * D0 + (size_t)node * 96 + tid] = v;
    }
}

extern "C" void kernel_launch(void* const* d_in, const int* in_sizes, int n_in,
                              void* d_out, int out_size) {
    const float* f0   = (const float*)d_in[0];
    const float* f1   = (const float*)d_in[1];
    const int*   nbr  = (const int*)d_in[2];
    const unsigned char* msk = (const unsigned char*)d_in[3];
    const float* rdist= (const float*)d_in[4];
    const float* We1  = (const float*)d_in[5];
    const float* be1  = (const float*)d_in[6];
    const float* We2  = (const float*)d_in[7];
    const float* be2  = (const float*)d_in[8];
    const float* Wh1  = (const float*)d_in[9];
    const float* bh1  = (const float*)d_in[10];
    const float* Wh2  = (const float*)d_in[11];
    const float* bh2  = (const float*)d_in[12];
    const float* Wn1  = (const float*)d_in[13];
    const float* bn1  = (const float*)d_in[14];
    const float* Wn2  = (const float*)d_in[15];
    const float* bn2  = (const float*)d_in[16];
    const float* Wg   = (const float*)d_in[17];
    const float* bg   = (const float*)d_in[18];
    const float* lng  = (const float*)d_in[19];
    const float* lnb  = (const float*)d_in[20];
    const float* hns  = (const float*)d_in[21];
    const float* hnb  = (const float*)d_in[22];
    float* out = (float*)d_out;

    prep_frag<<<76, 256>>>(We1, We2, Wh1, Wh2);
    proj_tc<<<NT / 32, 256>>>(f0, be1);

    const size_t smem_bytes = 10438 * 4;

    cudaFuncSetAttribute(egnn_main, cudaFuncAttributeMaxDynamicSharedMemorySize,
                         (int)smem_bytes);

    egnn_main<<<NT, 256, smem_bytes>>>(
        f0, f1, nbr, msk, rdist,
        be2, bh1, bh2,
        Wn1, bn1, Wn2, bn2, Wg, bg, lng, lnb, hns, hnb, out);
}

// round 17
// speedup vs baseline: 3.0988x; 1.2381x over previous
#include <cuda_runtime.h>
#include <math.h>

#define Bb 2
#define Nn 4096
#define NT (Bb*Nn)
#define Kk 32
#define D0 64
#define E2C 322

typedef unsigned long long ull;

__device__ float PI_g[(size_t)NT * E2C + 384];
__device__ float PJ_g[(size_t)NT * E2C + 384];
__device__ float HT_g[(size_t)NT * 96 + 128];
__device__ float MI_g[(size_t)NT * 32 + 128];
__device__ __align__(16) ull Wfp_g[10496];  // We1 rows 0..127
__device__ __align__(16) ull Wf1_g[4032];   // We1 rows 128..160
__device__ __align__(16) ull Wf2_g[2688];   // We2
__device__ __align__(16) ull Wf3_g[1024];   // Wh1
__device__ __align__(16) ull Wf4_g[1024];   // Wh2
__device__ __align__(16) ull Wfn1_g[3072];  // Wn1 [ks 0..5][nt 0..15][32]
__device__ __align__(16) ull Wfn2_g[2048];  // Wn2 [ks 0..7][nt 0..7][32]
__device__ __align__(16) ull Wfg_g[512];    // Wg  [ks 0..3][nt 0..3][32]

__device__ __forceinline__ float siluf(float x) { return x / (1.f + __expf(-x)); }
__device__ __forceinline__ float sigmf(float x) { return 1.f / (1.f + __expf(-x)); }
__device__ __forceinline__ unsigned bf2(float lo, float hi) {
    unsigned r; asm("cvt.rn.bf16x2.f32 %0, %1, %2;" : "=r"(r) : "f"(hi), "f"(lo)); return r;
}
__device__ __forceinline__ float blo(unsigned u) { return __uint_as_float(u << 16); }
__device__ __forceinline__ float bhi(unsigned u) { return __uint_as_float(u & 0xffff0000u); }
__device__ __forceinline__ void mma16816(float& d0, float& d1, float& d2, float& d3,
    unsigned a0, unsigned a1, unsigned a2, unsigned a3, unsigned b0, unsigned b1)
{
    asm("mma.sync.aligned.m16n8k16.row.col.f32.bf16.bf16.f32 "
        "{%0,%1,%2,%3}, {%4,%5,%6,%7}, {%8,%9}, {%0,%1,%2,%3};"
        : "+f"(d0), "+f"(d1), "+f"(d2), "+f"(d3)
        : "r"(a0), "r"(a1), "r"(a2), "r"(a3), "r"(b0), "r"(b1));
}

// ---------------- proj on tensor cores
__global__ void __launch_bounds__(256)
proj_tc(const float* __restrict__ f0, const float* __restrict__ be1)
{
    __shared__ unsigned NDbP[32 * 36];
    __shared__ float be1s[328];
    const int nb = blockIdx.x * 32;
    const int tid = threadIdx.x;
    const int lane = tid & 31;
    const int wrow = tid >> 5;
    const int g = lane >> 2;
    const int tg = lane & 3;

    for (int idx = tid; idx < 1024; idx += 256) {
        const int n = idx >> 5, kp = idx & 31;
        const float2 v = *(const float2*)&f0[(size_t)(nb + n) * 64 + 2 * kp];
        NDbP[n * 36 + kp] = bf2(v.x, v.y);
    }
    for (int c = tid; c < 328; c += 256) be1s[c] = (c < E2C) ? be1[c] : 0.f;
    __syncthreads();

    #pragma unroll
    for (int tt = 0; tt < 21; tt++) {
        const int t = wrow + 8 * tt;
        if (t < 164) {
            const int mt = t & 1;
            const int ntp = t >> 1;
            const int p = (ntp >= 41);
            const int nt = ntp - 41 * p;
            const int e0 = 16 * mt + g;
            float d0 = 0.f, d1 = 0.f, d2 = 0.f, d3 = 0.f;
            #pragma unroll
            for (int ks = 0; ks < 4; ks++) {
                const unsigned a0 = NDbP[e0 * 36 + 8 * ks + tg];
                const unsigned a1 = NDbP[(e0 + 8) * 36 + 8 * ks + tg];
                const unsigned a2 = NDbP[e0 * 36 + 8 * ks + 4 + tg];
                const unsigned a3 = NDbP[(e0 + 8) * 36 + 8 * ks + 4 + tg];
                const ull b = __ldg(&Wfp_g[((size_t)(p * 41 + nt) * 4 + ks) * 32 + lane]);
                mma16816(d0, d1, d2, d3, a0, a1, a2, a3, (unsigned)b, (unsigned)(b >> 32));
            }
            const int c0 = 8 * nt + 2 * tg;
            if (c0 < E2C) {
                if (p == 0) {
                    const float2 b2 = *(const float2*)&be1s[c0];
                    *(float2*)&PI_g[(size_t)(nb + e0) * E2C + c0]     = make_float2(d0 + b2.x, d1 + b2.y);
                    *(float2*)&PI_g[(size_t)(nb + e0 + 8) * E2C + c0] = make_float2(d2 + b2.x, d3 + b2.y);
                } else {
                    *(float2*)&PJ_g[(size_t)(nb + e0) * E2C + c0]     = make_float2(d0, d1);
                    *(float2*)&PJ_g[(size_t)(nb + e0 + 8) * E2C + c0] = make_float2(d2, d3);
                }
            }
        }
    }
}

// ---------------- pre-pack B fragments
__global__ void __launch_bounds__(256)
prep_frag(const float* __restrict__ We1, const float* __restrict__ We2,
          const float* __restrict__ Wh1, const float* __restrict__ Wh2,
          const float* __restrict__ Wn1, const float* __restrict__ Wn2,
          const float* __restrict__ Wg)
{
    const int idx = blockIdx.x * 256 + threadIdx.x;
    const int lane = idx & 31;
    const int g = lane >> 2, tg = lane & 3;
    if (idx < 10496) {                      // Wfp
        int j = idx >> 5;
        const int ks = j & 3; j >>= 2;
        const int nt = j % 41;
        const int p  = j / 41;
        const int n = 8 * nt + g;
        const int k = 64 * p + 16 * ks + 2 * tg;
        float w00 = 0.f, w01 = 0.f, w10 = 0.f, w11 = 0.f;
        if (n < E2C) {
            w00 = We1[(size_t)k * E2C + n];
            w01 = We1[(size_t)(k + 1) * E2C + n];
            w10 = We1[(size_t)(k + 8) * E2C + n];
            w11 = We1[(size_t)(k + 9) * E2C + n];
        }
        Wfp_g[idx] = (ull)bf2(w00, w01) | ((ull)bf2(w10, w11) << 32);
    } else if (idx < 14528) {               // Wf1
        const int i2 = idx - 10496;
        const int j = i2 >> 5;
        const int ks = j % 3, nt = j / 3;
        const int n = 8 * nt + g;
        const int k = 16 * ks + 2 * tg;
        float w00 = 0.f, w01 = 0.f, w10 = 0.f, w11 = 0.f;
        if (n < E2C) {
            if (k     < 33) w00 = We1[(size_t)(128 + k)     * E2C + n];
            if (k + 1 < 33) w01 = We1[(size_t)(128 + k + 1) * E2C + n];
            if (k + 8 < 33) w10 = We1[(size_t)(128 + k + 8) * E2C + n];
            if (k + 9 < 33) w11 = We1[(size_t)(128 + k + 9) * E2C + n];
        }
        Wf1_g[i2] = (ull)bf2(w00, w01) | ((ull)bf2(w10, w11) << 32);
    } else if (idx < 17216) {               // Wf2
        const int j = idx - 14528;
        const int nt = (j >> 5) & 3, ks = j >> 7;
        const int n = 8 * nt + g;
        const int k = 16 * ks + 2 * tg;
        const float w00 = (k     < E2C) ? We2[k * 32 + n]       : 0.f;
        const float w01 = (k + 1 < E2C) ? We2[(k + 1) * 32 + n] : 0.f;
        const float w10 = (k + 8 < E2C) ? We2[(k + 8) * 32 + n] : 0.f;
        const float w11 = (k + 9 < E2C) ? We2[(k + 9) * 32 + n] : 0.f;
        Wf2_g[j] = (ull)bf2(w00, w01) | ((ull)bf2(w10, w11) << 32);
    } else if (idx < 18240) {               // Wf3
        const int j = idx - 17216;
        const int nt = (j >> 5) & 15, ks = j >> 9;
        const int n = 8 * nt + g;
        const int k = 16 * ks + 2 * tg;
        Wf3_g[j] = (ull)bf2(Wh1[k * 128 + n], Wh1[(k + 1) * 128 + n])
                 | ((ull)bf2(Wh1[(k + 8) * 128 + n], Wh1[(k + 9) * 128 + n]) << 32);
    } else if (idx < 19264) {               // Wf4
        const int j = idx - 18240;
        const int nt = (j >> 5) & 3, ks = j >> 7;
        const int n = 8 * nt + g;
        const int k = 16 * ks + 2 * tg;
        Wf4_g[j] = (ull)bf2(Wh2[k * 32 + n], Wh2[(k + 1) * 32 + n])
                 | ((ull)bf2(Wh2[(k + 8) * 32 + n], Wh2[(k + 9) * 32 + n]) << 32);
    } else if (idx < 22336) {               // Wfn1 [ks][nt][lane]
        const int j = idx - 19264;
        const int jj = j >> 5;
        const int nt = jj & 15, ks = jj >> 4;
        const int n = 8 * nt + g;
        const int k = 16 * ks + 2 * tg;
        Wfn1_g[j] = (ull)bf2(Wn1[k * 128 + n], Wn1[(k + 1) * 128 + n])
                  | ((ull)bf2(Wn1[(k + 8) * 128 + n], Wn1[(k + 9) * 128 + n]) << 32);
    } else if (idx < 24384) {               // Wfn2 [ks][nt][lane]
        const int j = idx - 22336;
        const int jj = j >> 5;
        const int nt = jj & 7, ks = jj >> 3;
        const int n = 8 * nt + g;
        const int k = 16 * ks + 2 * tg;
        Wfn2_g[j] = (ull)bf2(Wn2[k * 64 + n], Wn2[(k + 1) * 64 + n])
                  | ((ull)bf2(Wn2[(k + 8) * 64 + n], Wn2[(k + 9) * 64 + n]) << 32);
    } else if (idx < 24896) {               // Wfg [ks][nt][lane]
        const int j = idx - 24384;
        const int jj = j >> 5;
        const int nt = jj & 3, ks = jj >> 2;
        const int n = 8 * nt + g;
        const int k = 16 * ks + 2 * tg;
        Wfg_g[j] = (ull)bf2(Wg[k * 32 + n], Wg[(k + 1) * 32 + n])
                 | ((ull)bf2(Wg[(k + 8) * 32 + n], Wg[(k + 9) * 32 + n]) << 32);
    }
}

// ---------------- main fused kernel: edge pipeline only
__global__ void __launch_bounds__(256, 5)
egnn_main(const float* __restrict__ f0, const float* __restrict__ f1,
          const int* __restrict__ nbr, const unsigned char* __restrict__ msk,
          const float* __restrict__ rdist,
          const float* __restrict__ be2, const float* __restrict__ bh1,
          const float* __restrict__ bh2,
          const float* __restrict__ hns, const float* __restrict__ hnb)
{
    extern __shared__ float sm[];
    unsigned* H1u  = (unsigned*)sm;            // [32 e][172] u32; aliased by G1u
    float*    EIcT = (float*)(H1u + 5504);     // [32 d][36]
    unsigned* EIbP = (unsigned*)(EIcT + 1152); // [32 e][28]
    float*    PI   = (float*)(EIbP + 896);     // [324]
    unsigned* MSbP = (unsigned*)(PI + 324);    // [32 e][20]
    float*    WST  = (float*)(MSbP + 640);     // [32 d][36]
    float*    HT2  = WST + 1152;               // [192]
    float*    f1i_s= HT2 + 192;                // [96]
    float*    maskv= f1i_s + 96;               // [32]
    int*      nbr_s= (int*)(maskv + 32);       // [32]
    float*    rdist_s = (float*)(nbr_s + 32);  // [32]
    unsigned* G1u  = H1u;

    const int tid  = threadIdx.x;
    const int lane = tid & 31;
    const int wrow = tid >> 5;
    const int g    = lane >> 2;
    const int tg   = lane & 3;
    const int node = blockIdx.x;
    const int bbase = (node / Nn) * Nn;

    // ---- P0 ----
    if (tid < 96)           f1i_s[tid] = f1[(size_t)node * 96 + tid];
    else if (tid < 128)     nbr_s[tid - 96] = nbr[node * Kk + tid - 96];
    else if (tid < 160)     maskv[tid - 128] = (float)msk[node * Kk + tid - 128];
    else if (tid < 192)     rdist_s[tid - 160] = rdist[node * Kk + tid - 160];
    for (int c = tid; c < 324; c += 256)
        PI[c] = (c < E2C) ? PI_g[(size_t)node * E2C + c] : 0.f;
    if (tid < 224) H1u[(tid / 7) * 172 + 161 + (tid % 7)] = 0u;
    __syncthreads();

    // ---- P1: rel_norm -> EIcT ----
    #pragma unroll
    for (int i = 0; i < 4; i++) {
        const int e = wrow + 8 * i;
        const float* f1j = f1 + (size_t)(bbase + nbr_s[e]) * 96;
        const float r0 = f1i_s[lane * 3 + 0] - f1j[lane * 3 + 0];
        const float r1 = f1i_s[lane * 3 + 1] - f1j[lane * 3 + 1];
        const float r2 = f1i_s[lane * 3 + 2] - f1j[lane * 3 + 2];
        EIcT[lane * 36 + e] = sqrtf(r0 * r0 + r1 * r1 + r2 * r2);
    }
    __syncthreads();

    // ---- P1b: pack edge_in pairs ----
    for (int idx = tid; idx < 768; idx += 256) {
        const int e = idx / 24, kp = idx - 24 * (idx / 24);
        unsigned v;
        if (kp < 16)       v = bf2(EIcT[(2 * kp) * 36 + e], EIcT[(2 * kp + 1) * 36 + e]);
        else if (kp == 16) v = bf2(rdist_s[e], 0.f);
        else               v = 0u;
        EIbP[e * 28 + kp] = v;
    }
    __syncthreads();

    // ---- GEMM1 (tensor) ----
    #pragma unroll
    for (int tt = 0; tt < 11; tt++) {
        const int t = wrow + 8 * tt;
        if (t < 84) {
            const int mt = t & 1, nt = t >> 1;
            const int e0 = 16 * mt + g;
            float d0 = 0.f, d1 = 0.f, d2 = 0.f, d3 = 0.f;
            #pragma unroll
            for (int ks = 0; ks < 3; ks++) {
                const unsigned a0 = EIbP[e0 * 28 + 8 * ks + tg];
                const unsigned a1 = EIbP[(e0 + 8) * 28 + 8 * ks + tg];
                const unsigned a2 = EIbP[e0 * 28 + 8 * ks + 4 + tg];
                const unsigned a3 = EIbP[(e0 + 8) * 28 + 8 * ks + 4 + tg];
                const ull b = __ldg(&Wf1_g[(nt * 3 + ks) * 32 + lane]);
                mma16816(d0, d1, d2, d3, a0, a1, a2, a3, (unsigned)b, (unsigned)(b >> 32));
            }
            const int p = 4 * nt + tg;
            if (p < 161) {
                const float2 pi2 = *(const float2*)&PI[2 * p];
                const float2 pjA = __ldg((const float2*)(PJ_g + (size_t)(bbase + nbr_s[e0]) * E2C + 2 * p));
                const float2 pjB = __ldg((const float2*)(PJ_g + (size_t)(bbase + nbr_s[e0 + 8]) * E2C + 2 * p));
                H1u[e0 * 172 + p]       = bf2(siluf(d0 + pi2.x + pjA.x), siluf(d1 + pi2.y + pjA.y));
                H1u[(e0 + 8) * 172 + p] = bf2(siluf(d2 + pi2.x + pjB.x), siluf(d3 + pi2.y + pjB.y));
            }
        }
    }
    __syncthreads();

    // ---- GEMM2 (tensor): K=336 ----
    {
        const int mt = wrow & 1, nt = wrow >> 1;
        const int e0 = 16 * mt + g;
        float d0 = 0.f, d1 = 0.f, d2 = 0.f, d3 = 0.f;
        #pragma unroll
        for (int ks = 0; ks < 21; ks++) {
            const unsigned a0 = H1u[e0 * 172 + 8 * ks + tg];
            const unsigned a1 = H1u[(e0 + 8) * 172 + 8 * ks + tg];
            const unsigned a2 = H1u[e0 * 172 + 8 * ks + 4 + tg];
            const unsigned a3 = H1u[(e0 + 8) * 172 + 8 * ks + 4 + tg];
            const ull b = __ldg(&Wf2_g[(ks * 4 + nt) * 32 + lane]);
            mma16816(d0, d1, d2, d3, a0, a1, a2, a3, (unsigned)b, (unsigned)(b >> 32));
        }
        const int col0 = 8 * nt + 2 * tg;
        const float b0 = be2[col0], b1 = be2[col0 + 1];
        MSbP[e0 * 20 + 4 * nt + tg]       = bf2(siluf(d0 + b0), siluf(d1 + b1));
        MSbP[(e0 + 8) * 20 + 4 * nt + tg] = bf2(siluf(d2 + b0), siluf(d3 + b1));
    }
    __syncthreads();

    // ---- GEMM3 (tensor) ----
    {
        const int mt = wrow & 1, nt0 = wrow >> 1;
        const int e0 = 16 * mt + g;
        float d[4][4];
        #pragma unroll
        for (int t = 0; t < 4; t++)
            #pragma unroll
            for (int q = 0; q < 4; q++) d[t][q] = 0.f;
        #pragma unroll
        for (int ks = 0; ks < 2; ks++) {
            const unsigned a0 = MSbP[e0 * 20 + 8 * ks + tg];
            const unsigned a1 = MSbP[(e0 + 8) * 20 + 8 * ks + tg];
            const unsigned a2 = MSbP[e0 * 20 + 8 * ks + 4 + tg];
            const unsigned a3 = MSbP[(e0 + 8) * 20 + 8 * ks + 4 + tg];
            #pragma unroll
            for (int t = 0; t < 4; t++) {
                const int nt = nt0 + 4 * t;
                const ull b = __ldg(&Wf3_g[(ks * 16 + nt) * 32 + lane]);
                mma16816(d[t][0], d[t][1], d[t][2], d[t][3], a0, a1, a2, a3,
                         (unsigned)b, (unsigned)(b >> 32));
            }
        }
        #pragma unroll
        for (int t = 0; t < 4; t++) {
            const int nt = nt0 + 4 * t;
            const int col0 = 8 * nt + 2 * tg;
            const float b0 = bh1[col0], b1 = bh1[col0 + 1];
            G1u[e0 * 68 + 4 * nt + tg]       = bf2(siluf(d[t][0] + b0), siluf(d[t][1] + b1));
            G1u[(e0 + 8) * 68 + 4 * nt + tg] = bf2(siluf(d[t][2] + b0), siluf(d[t][3] + b1));
        }
    }
    __syncthreads();

    // ---- GEMM4 (tensor): K=128 ----
    {
        const int mt = wrow & 1, nt = wrow >> 1;
        const int e0 = 16 * mt + g;
        float d0 = 0.f, d1 = 0.f, d2 = 0.f, d3 = 0.f;
        #pragma unroll
        for (int ks = 0; ks < 8; ks++) {
            const unsigned a0 = G1u[e0 * 68 + 8 * ks + tg];
            const unsigned a1 = G1u[(e0 + 8) * 68 + 8 * ks + tg];
            const unsigned a2 = G1u[e0 * 68 + 8 * ks + 4 + tg];
            const unsigned a3 = G1u[(e0 + 8) * 68 + 8 * ks + 4 + tg];
            const ull b = __ldg(&Wf4_g[(ks * 4 + nt) * 32 + lane]);
            mma16816(d0, d1, d2, d3, a0, a1, a2, a3, (unsigned)b, (unsigned)(b >> 32));
        }
        const int col0 = 8 * nt + 2 * tg;
        WST[col0 * 36 + e0]           = d0 + bh2[col0];
        WST[(col0 + 1) * 36 + e0]     = d1 + bh2[col0 + 1];
        WST[col0 * 36 + e0 + 8]       = d2 + bh2[col0];
        WST[(col0 + 1) * 36 + e0 + 8] = d3 + bh2[col0 + 1];
    }
    __syncthreads();

    // ---- htype (warps 0-5) + MI write (warps 6) ----
    if (tid < 192) {
        const int half = (tid >= 96);
        const int t = tid - 96 * half;
        const int d = t / 3;
        const float hs = hns[d], hb = hnb[d];
        const float fi = f1i_s[t];
        const int e0 = half * 16;
        float s = 0.f;
        #pragma unroll
        for (int e4 = 0; e4 < 4; e4++) {
            const float4 nrm4 = *(const float4*)&EIcT[d * 36 + e0 + 4 * e4];
            const float4 w4   = *(const float4*)&WST[d * 36 + e0 + 4 * e4];
            #pragma unroll
            for (int m = 0; m < 4; m++) {
                const int e = e0 + 4 * e4 + m;
                const float nrm = (m == 0) ? nrm4.x : (m == 1) ? nrm4.y : (m == 2) ? nrm4.z : nrm4.w;
                const float wv  = (m == 0) ? w4.x   : (m == 1) ? w4.y   : (m == 2) ? w4.z   : w4.w;
                const float coef = __fdividef(nrm * hs + hb, fmaxf(nrm, 1e-8f));
                const float relv = fi - __ldg(&f1[(size_t)(bbase + nbr_s[e]) * 96 + t]);
                s += relv * coef * wv;
            }
        }
        HT2[tid] = s;
    } else if (tid < 224) {
        const int c = tid - 192;
        float s = 0.f;
        #pragma unroll 8
        for (int e = 0; e < 32; e++) {
            const unsigned u = MSbP[e * 20 + (c >> 1)];
            s += maskv[e] * ((c & 1) ? bhi(u) : blo(u));
        }
        MI_g[(size_t)node * 32 + c] = s;
    }
    __syncthreads();

    if (tid < 96)
        HT_g[(size_t)node * 96 + tid] = HT2[tid] + HT2[96 + tid];
}

// ---------------- node tail kernel: batched node MLPs on tensor cores (32 nodes/block)
__global__ void __launch_bounds__(256)
node_tail(const float* __restrict__ f0, const float* __restrict__ f1,
          const float* __restrict__ bn1, const float* __restrict__ bn2,
          const float* __restrict__ bg,
          const float* __restrict__ lng, const float* __restrict__ lnb,
          float* __restrict__ out)
{
    __shared__ float    nodes_s[32 * 64];
    __shared__ unsigned NIbP[32 * 52];
    __shared__ unsigned N1bP[32 * 36];
    __shared__ unsigned NObP[32 * 36];
    __shared__ float    gates_s[32 * 32];
    __shared__ float    stats_s[32][2];

    const int nb = blockIdx.x * 32;
    const int tid = threadIdx.x;
    const int lane = tid & 31;
    const int wrow = tid >> 5;
    const int g = lane >> 2;
    const int tg = lane & 3;

    for (int idx = tid; idx < 2048; idx += 256)
        nodes_s[idx] = f0[(size_t)nb * 64 + idx];
    __syncthreads();

    // LN stats: warp w handles nodes 4w..4w+3
    #pragma unroll
    for (int i = 0; i < 4; i++) {
        const int n = 4 * wrow + i;
        const float x0 = nodes_s[n * 64 + lane], x1 = nodes_s[n * 64 + lane + 32];
        float s = x0 + x1, ss = x0 * x0 + x1 * x1;
        #pragma unroll
        for (int o = 16; o > 0; o >>= 1) {
            s  += __shfl_down_sync(0xffffffffu, s,  o);
            ss += __shfl_down_sync(0xffffffffu, ss, o);
        }
        if (lane == 0) {
            const float mu = s * (1.f / 64.f);
            const float var = ss * (1.f / 64.f) - mu * mu;
            stats_s[n][0] = mu;
            stats_s[n][1] = rsqrtf(var + 1e-5f);
        }
    }
    __syncthreads();

    // build NIbP: K pairs 0..31 = LN(nodes), 32..47 = MI, 48..51 = 0
    for (int idx = tid; idx < 32 * 52; idx += 256) {
        const int n = idx / 52, kp = idx - 52 * n;
        unsigned v = 0u;
        if (kp < 32) {
            const float mu = stats_s[n][0], rs = stats_s[n][1];
            const float v0 = (nodes_s[n * 64 + 2 * kp] - mu) * rs * lng[2 * kp] + lnb[2 * kp];
            const float v1 = (nodes_s[n * 64 + 2 * kp + 1] - mu) * rs * lng[2 * kp + 1] + lnb[2 * kp + 1];
            v = bf2(v0, v1);
        } else if (kp < 48) {
            const int m = kp - 32;
            const float2 mi = *(const float2*)&MI_g[(size_t)(nb + n) * 32 + 2 * m];
            v = bf2(mi.x, mi.y);
        }
        NIbP[n * 52 + kp] = v;
    }
    __syncthreads();

    // GEMM A: N1[32,128] = silu(NI @ Wn1 + bn1), K=96
    #pragma unroll
    for (int tt = 0; tt < 4; tt++) {
        const int t = wrow + 8 * tt;
        const int mt = t & 1, nt = t >> 1;
        const int e0 = 16 * mt + g;
        float d0 = 0.f, d1 = 0.f, d2 = 0.f, d3 = 0.f;
        #pragma unroll
        for (int ks = 0; ks < 6; ks++) {
            const unsigned a0 = NIbP[e0 * 52 + 8 * ks + tg];
            const unsigned a1 = NIbP[(e0 + 8) * 52 + 8 * ks + tg];
            const unsigned a2 = NIbP[e0 * 52 + 8 * ks + 4 + tg];
            const unsigned a3 = NIbP[(e0 + 8) * 52 + 8 * ks + 4 + tg];
            const ull b = __ldg(&Wfn1_g[(ks * 16 + nt) * 32 + lane]);
            mma16816(d0, d1, d2, d3, a0, a1, a2, a3, (unsigned)b, (unsigned)(b >> 32));
        }
        const int col0 = 8 * nt + 2 * tg;
        const float b0 = bn1[col0], b1 = bn1[col0 + 1];
        N1bP[e0 * 36 + 4 * nt + tg]       = bf2(siluf(d0 + b0), siluf(d1 + b1));
        N1bP[(e0 + 8) * 36 + 4 * nt + tg] = bf2(siluf(d2 + b0), siluf(d3 + b1));
    }
    __syncthreads();

    // GEMM B: node_out[32,64] = N1 @ Wn2 + bn2 + nodes, K=128
    #pragma unroll
    for (int tt = 0; tt < 2; tt++) {
        const int t = wrow + 8 * tt;
        const int mt = t & 1, nt = t >> 1;
        const int e0 = 16 * mt + g;
        float d0 = 0.f, d1 = 0.f, d2 = 0.f, d3 = 0.f;
        #pragma unroll
        for (int ks = 0; ks < 8; ks++) {
            const unsigned a0 = N1bP[e0 * 36 + 8 * ks + tg];
            const unsigned a1 = N1bP[(e0 + 8) * 36 + 8 * ks + tg];
            const unsigned a2 = N1bP[e0 * 36 + 8 * ks + 4 + tg];
            const unsigned a3 = N1bP[(e0 + 8) * 36 + 8 * ks + 4 + tg];
            const ull b = __ldg(&Wfn2_g[(ks * 8 + nt) * 32 + lane]);
            mma16816(d0, d1, d2, d3, a0, a1, a2, a3, (unsigned)b, (unsigned)(b >> 32));
        }
        const int col0 = 8 * nt + 2 * tg;
        const float b0 = bn2[col0], b1 = bn2[col0 + 1];
        const float vA0 = d0 + b0 + nodes_s[e0 * 64 + col0];
        const float vA1 = d1 + b1 + nodes_s[e0 * 64 + col0 + 1];
        const float vB0 = d2 + b0 + nodes_s[(e0 + 8) * 64 + col0];
        const float vB1 = d3 + b1 + nodes_s[(e0 + 8) * 64 + col0 + 1];
        *(float2*)&out[(size_t)(nb + e0) * 64 + col0]     = make_float2(vA0, vA1);
        *(float2*)&out[(size_t)(nb + e0 + 8) * 64 + col0] = make_float2(vB0, vB1);
        NObP[e0 * 36 + 4 * nt + tg]       = bf2(vA0, vA1);
        NObP[(e0 + 8) * 36 + 4 * nt + tg] = bf2(vB0, vB1);
    }
    __syncthreads();

    // GEMM C: gate[32,32] = sigmoid(node_out @ Wg + bg), K=64
    {
        const int mt = wrow & 1, nt = wrow >> 1;
        const int e0 = 16 * mt + g;
        float d0 = 0.f, d1 = 0.f, d2 = 0.f, d3 = 0.f;
        #pragma unroll
        for (int ks = 0; ks < 4; ks++) {
            const unsigned a0 = NObP[e0 * 36 + 8 * ks + tg];
            const unsigned a1 = NObP[(e0 + 8) * 36 + 8 * ks + tg];
            const unsigned a2 = NObP[e0 * 36 + 8 * ks + 4 + tg];
            const unsigned a3 = NObP[(e0 + 8) * 36 + 8 * ks + 4 + tg];
            const ull b = __ldg(&Wfg_g[(ks * 4 + nt) * 32 + lane]);
            mma16816(d0, d1, d2, d3, a0, a1, a2, a3, (unsigned)b, (unsigned)(b >> 32));
        }
        const int col0 = 8 * nt + 2 * tg;
        const float b0 = bg[col0], b1 = bg[col0 + 1];
        gates_s[e0 * 32 + col0]           = sigmf(d0 + b0);
        gates_s[e0 * 32 + col0 + 1]       = sigmf(d1 + b1);
        gates_s[(e0 + 8) * 32 + col0]     = sigmf(d2 + b0);
        gates_s[(e0 + 8) * 32 + col0 + 1] = sigmf(d3 + b1);
    }
    __syncthreads();

    // f1_out = (f1 + HT) * gate
    for (int idx = tid; idx < 3072; idx += 256) {
        const int n = idx / 96, t = idx - 96 * n;
        const float v = (f1[(size_t)(nb + n) * 96 + t] + HT_g[(size_t)(nb + n) * 96 + t])
                      * gates_s[n * 32 + t / 3];
        out[(size_t)Bb * Nn * D0 + (size_t)(nb + n) * 96 + t] = v;
    }
}

extern "C" void kernel_launch(void* const* d_in, const int* in_sizes, int n_in,
                              void* d_out, int out_size) {
    const float* f0   = (const float*)d_in[0];
    const float* f1   = (const float*)d_in[1];
    const int*   nbr  = (const int*)d_in[2];
    const unsigned char* msk = (const unsigned char*)d_in[3];
    const float* rdist= (const float*)d_in[4];
    const float* We1  = (const float*)d_in[5];
    const float* be1  = (const float*)d_in[6];
    const float* We2  = (const float*)d_in[7];
    const float* be2  = (const float*)d_in[8];
    const float* Wh1  = (const float*)d_in[9];
    const float* bh1  = (const float*)d_in[10];
    const float* Wh2  = (const float*)d_in[11];
    const float* bh2  = (const float*)d_in[12];
    const float* Wn1  = (const float*)d_in[13];
    const float* bn1  = (const float*)d_in[14];
    const float* Wn2  = (const float*)d_in[15];
    const float* bn2  = (const float*)d_in[16];
    const float* Wg   = (const float*)d_in[17];
    const float* bg   = (const float*)d_in[18];
    const float* lng  = (const float*)d_in[19];
    const float* lnb  = (const float*)d_in[20];
    const float* hns  = (const float*)d_in[21];
    const float* hnb  = (const float*)d_in[22];
    float* out = (float*)d_out;

    prep_frag<<<98, 256>>>(We1, We2, Wh1, Wh2, Wn1, Wn2, Wg);
    proj_tc<<<NT / 32, 256>>>(f0, be1);

    const size_t smem_bytes = 10054 * 4;

    cudaFuncSetAttribute(egnn_main, cudaFuncAttributeMaxDynamicSharedMemorySize,
                         (int)smem_bytes);

    egnn_main<<<NT, 256, smem_bytes>>>(
        f0, f1, nbr, msk, rdist,
        be2, bh1, bh2, hns, hnb);

    node_tail<<<NT / 32, 256>>>(f0, f1, bn1, bn2, bg, lng, lnb, out);
}